// round 2
// baseline (speedup 1.0000x reference)
#include <cuda_runtime.h>
#include <cuda_bf16.h>
#include <math.h>

// Problem constants
#define Bb 4
#define Ts 2048
#define Dd 1024
#define Hh 16
#define HD 64
#define M_ROWS (Bb * Ts)          // 8192
#define QKV_N (3 * Dd)            // 3072

// Scratch (device globals: allocation-free)
__device__ float g_qkv[(size_t)M_ROWS * QKV_N];   // [B*T, 3D]
__device__ float g_o[(size_t)M_ROWS * Dd];        // [B*T, D]
__device__ float g_bias[Bb * Ts];                 // per-key additive bias
__device__ int   g_maskMode;                      // 0=uint8, 1=int32, 2=float32

// ---------------------------------------------------------------------------
// Mask dtype detection: read first B*T bytes (safe under all encodings),
// OR the bytes by lane (i % 4).
//   int32 0/1   : lanes 1,2,3 all zero
//   float32 0/1 : lanes 0,1 zero; lanes 2,3 nonzero (0x80,0x3F)
//   uint8       : otherwise
// ---------------------------------------------------------------------------
__global__ void detect_mask_kernel(const unsigned char* __restrict__ mask)
{
    __shared__ unsigned int orr[4][256];
    const int tid = threadIdx.x;
    unsigned int o0 = 0, o1 = 0, o2 = 0, o3 = 0;
    for (int i = tid * 4; i < Bb * Ts; i += 256 * 4) {
        o0 |= mask[i + 0];
        o1 |= mask[i + 1];
        o2 |= mask[i + 2];
        o3 |= mask[i + 3];
    }
    orr[0][tid] = o0; orr[1][tid] = o1; orr[2][tid] = o2; orr[3][tid] = o3;
    __syncthreads();
    for (int s = 128; s; s >>= 1) {
        if (tid < s) {
            orr[0][tid] |= orr[0][tid + s];
            orr[1][tid] |= orr[1][tid + s];
            orr[2][tid] |= orr[2][tid + s];
            orr[3][tid] |= orr[3][tid + s];
        }
        __syncthreads();
    }
    if (tid == 0) {
        unsigned int l0 = orr[0][0], l1 = orr[1][0], l2 = orr[2][0], l3 = orr[3][0];
        int mode;
        if ((l1 | l2 | l3) == 0u) mode = 1;                      // int32 (or all-zero: any works)
        else if ((l0 | l1) == 0u && (l2 | l3) != 0u) mode = 2;   // float32
        else mode = 0;                                           // uint8
        g_maskMode = mode;
    }
}

// ---------------------------------------------------------------------------
// Per-key bias precompute: bias = masked ? -1e9 : log(max(eng, 1e-6))
// ---------------------------------------------------------------------------
__global__ void bias_kernel(const float* __restrict__ eng, const void* __restrict__ mask)
{
    const int kk = blockIdx.x * 256 + threadIdx.x;
    if (kk >= Bb * Ts) return;
    const int mode = g_maskMode;
    bool m;
    if (mode == 1)      m = ((const int*)mask)[kk] != 0;
    else if (mode == 2) m = ((const float*)mask)[kk] != 0.f;
    else                m = ((const unsigned char*)mask)[kk] != 0;
    g_bias[kk] = m ? -1e9f : logf(fmaxf(eng[kk], 1e-6f));
}

// ---------------------------------------------------------------------------
// SGEMM: C[M,N] = A[M,K] @ W[N,K]^T + bias[N]
// 128x128 tile, BK=8, 256 threads, 8x8 per-thread microtile.
// ---------------------------------------------------------------------------
__global__ void __launch_bounds__(256)
sgemm_bias_kernel(const float* __restrict__ A, const float* __restrict__ W,
                  const float* __restrict__ bias, float* __restrict__ C,
                  int M, int N, int K, int ldc)
{
    __shared__ float As[8][128];
    __shared__ float Bs[8][128];

    const int bm = blockIdx.y * 128;
    const int bn = blockIdx.x * 128;
    const int tid = threadIdx.x;
    const int tx = tid & 15;
    const int ty = tid >> 4;
    const int lr = tid >> 1;
    const int lc = (tid & 1) * 4;

    const float* Ap = A + (size_t)(bm + lr) * K + lc;
    const float* Wp = W + (size_t)(bn + lr) * K + lc;

    float acc[8][8];
#pragma unroll
    for (int i = 0; i < 8; ++i)
#pragma unroll
        for (int j = 0; j < 8; ++j) acc[i][j] = 0.f;

    for (int k0 = 0; k0 < K; k0 += 8) {
        float4 a4 = *(const float4*)(Ap + k0);
        float4 b4 = *(const float4*)(Wp + k0);
        As[lc + 0][lr] = a4.x; As[lc + 1][lr] = a4.y;
        As[lc + 2][lr] = a4.z; As[lc + 3][lr] = a4.w;
        Bs[lc + 0][lr] = b4.x; Bs[lc + 1][lr] = b4.y;
        Bs[lc + 2][lr] = b4.z; Bs[lc + 3][lr] = b4.w;
        __syncthreads();

#pragma unroll
        for (int kk = 0; kk < 8; ++kk) {
            float a[8], b[8];
            *(float4*)&a[0] = *(const float4*)&As[kk][ty * 8];
            *(float4*)&a[4] = *(const float4*)&As[kk][ty * 8 + 4];
            *(float4*)&b[0] = *(const float4*)&Bs[kk][tx * 8];
            *(float4*)&b[4] = *(const float4*)&Bs[kk][tx * 8 + 4];
#pragma unroll
            for (int i = 0; i < 8; ++i)
#pragma unroll
                for (int j = 0; j < 8; ++j)
                    acc[i][j] = fmaf(a[i], b[j], acc[i][j]);
        }
        __syncthreads();
    }

    float bv[8];
#pragma unroll
    for (int j = 0; j < 8; ++j) bv[j] = bias[bn + tx * 8 + j];
#pragma unroll
    for (int i = 0; i < 8; ++i) {
        float* cp = C + (size_t)(bm + ty * 8 + i) * ldc + bn + tx * 8;
        float4 o0, o1;
        o0.x = acc[i][0] + bv[0]; o0.y = acc[i][1] + bv[1];
        o0.z = acc[i][2] + bv[2]; o0.w = acc[i][3] + bv[3];
        o1.x = acc[i][4] + bv[4]; o1.y = acc[i][5] + bv[5];
        o1.z = acc[i][6] + bv[6]; o1.w = acc[i][7] + bv[7];
        *(float4*)(cp) = o0;
        *(float4*)(cp + 4) = o1;
    }
}

// ---------------------------------------------------------------------------
// Flash attention (fp32) with per-key bias from g_bias.
// Block = 256 threads = 8 warps -> one (b, h, 64-query tile).
// ---------------------------------------------------------------------------
__device__ __forceinline__ float warpMax(float v) {
#pragma unroll
    for (int o = 16; o; o >>= 1) v = fmaxf(v, __shfl_xor_sync(0xffffffffu, v, o));
    return v;
}
__device__ __forceinline__ float warpSum(float v) {
#pragma unroll
    for (int o = 16; o; o >>= 1) v += __shfl_xor_sync(0xffffffffu, v, o);
    return v;
}

__global__ void __launch_bounds__(256)
attn_kernel(const float* __restrict__ qkv, float* __restrict__ O)
{
    __shared__ float Kt[64][65];      // K tile d-major; reused for P
    __shared__ float Vs[64][64];      // V tile k-major
    __shared__ float biasS[64];

    const int qt = blockIdx.x;
    const int h  = blockIdx.y;
    const int b  = blockIdx.z;
    const int tid  = threadIdx.x;
    const int warp = tid >> 5;
    const int lane = tid & 31;

    const float scale = 0.125f;

    float qreg[8][2];
#pragma unroll
    for (int r = 0; r < 8; ++r) {
        const int q = qt * 64 + warp * 8 + r;
        const float* qp = qkv + (size_t)(b * Ts + q) * QKV_N + h * HD;
        qreg[r][0] = qp[lane];
        qreg[r][1] = qp[lane + 32];
    }

    float acc0[8], acc1[8], m[8], l[8];
#pragma unroll
    for (int r = 0; r < 8; ++r) { acc0[r] = 0.f; acc1[r] = 0.f; m[r] = -1e30f; l[r] = 0.f; }

    const int r64   = tid >> 2;
    const int dbase = (tid & 3) * 16;

    float* Pw = &Kt[0][0] + warp * 512;

    for (int j = 0; j < Ts / 64; ++j) {
        const int kg = j * 64 + r64;
        const float* kbase = qkv + (size_t)(b * Ts + kg) * QKV_N + Dd     + h * HD + dbase;
        const float* vbase = qkv + (size_t)(b * Ts + kg) * QKV_N + 2 * Dd + h * HD + dbase;
#pragma unroll
        for (int i = 0; i < 4; ++i) {
            float4 kv = *(const float4*)(kbase + i * 4);
            Kt[dbase + i * 4 + 0][r64] = kv.x;
            Kt[dbase + i * 4 + 1][r64] = kv.y;
            Kt[dbase + i * 4 + 2][r64] = kv.z;
            Kt[dbase + i * 4 + 3][r64] = kv.w;
            *(float4*)&Vs[r64][dbase + i * 4] = *(const float4*)(vbase + i * 4);
        }
        if (tid < 64) biasS[tid] = g_bias[b * Ts + j * 64 + tid];
        __syncthreads();

        // S = Q K^T
        float s0[8], s1[8];
#pragma unroll
        for (int r = 0; r < 8; ++r) { s0[r] = 0.f; s1[r] = 0.f; }
#pragma unroll
        for (int d = 0; d < 64; ++d) {
            const float k0 = Kt[d][lane];
            const float k1 = Kt[d][lane + 32];
#pragma unroll
            for (int r = 0; r < 8; ++r) {
                const float qv = __shfl_sync(0xffffffffu, qreg[r][d >> 5], d & 31);
                s0[r] = fmaf(qv, k0, s0[r]);
                s1[r] = fmaf(qv, k1, s1[r]);
            }
        }
        __syncthreads();   // Kt reads done; safe to overwrite with P

        // online softmax
        const float bs0 = biasS[lane];
        const float bs1 = biasS[lane + 32];
#pragma unroll
        for (int r = 0; r < 8; ++r) {
            const float v0 = s0[r] * scale + bs0;
            const float v1 = s1[r] * scale + bs1;
            const float mt = warpMax(fmaxf(v0, v1));
            const float mnew = fmaxf(m[r], mt);
            const float alpha = __expf(m[r] - mnew);
            const float p0 = __expf(v0 - mnew);
            const float p1 = __expf(v1 - mnew);
            l[r] = l[r] * alpha + warpSum(p0 + p1);
            m[r] = mnew;
            acc0[r] *= alpha;
            acc1[r] *= alpha;
            Pw[r * 64 + lane] = p0;
            Pw[r * 64 + lane + 32] = p1;
        }
        __syncwarp();

        // O += P V
#pragma unroll
        for (int k = 0; k < 64; ++k) {
            const float v0 = Vs[k][lane];
            const float v1 = Vs[k][lane + 32];
#pragma unroll
            for (int r = 0; r < 8; ++r) {
                const float p = Pw[r * 64 + k];
                acc0[r] = fmaf(p, v0, acc0[r]);
                acc1[r] = fmaf(p, v1, acc1[r]);
            }
        }
        __syncthreads();
    }

#pragma unroll
    for (int r = 0; r < 8; ++r) {
        const float inv = 1.0f / l[r];
        const int q = qt * 64 + warp * 8 + r;
        float* op = O + (size_t)(b * Ts + q) * Dd + h * HD;
        op[lane]      = acc0[r] * inv;
        op[lane + 32] = acc1[r] * inv;
    }
}

// ---------------------------------------------------------------------------
extern "C" void kernel_launch(void* const* d_in, const int* in_sizes, int n_in,
                              void* d_out, int out_size)
{
    const float* x     = (const float*)d_in[0];
    const float* eng   = (const float*)d_in[1];
    const void*  mask  = (const void*)d_in[2];
    const float* qkv_w = (const float*)d_in[3];
    const float* qkv_b = (const float*)d_in[4];
    const float* out_w = (const float*)d_in[5];
    const float* out_b = (const float*)d_in[6];
    float* out = (float*)d_out;

    float* qkv = nullptr;
    float* o   = nullptr;
    cudaGetSymbolAddress((void**)&qkv, g_qkv);
    cudaGetSymbolAddress((void**)&o,   g_o);

    // 0) mask dtype detection + per-key bias precompute
    detect_mask_kernel<<<1, 256>>>((const unsigned char*)mask);
    bias_kernel<<<(Bb * Ts + 255) / 256, 256>>>(eng, mask);

    // 1) QKV projection: [8192,1024] @ [3072,1024]^T + b
    dim3 g1(QKV_N / 128, M_ROWS / 128);
    sgemm_bias_kernel<<<g1, 256>>>(x, qkv_w, qkv_b, qkv, M_ROWS, QKV_N, Dd, QKV_N);

    // 2) attention
    dim3 g2(Ts / 64, Hh, Bb);
    attn_kernel<<<g2, 256>>>(qkv, o);

    // 3) output projection: [8192,1024] @ [1024,1024]^T + b
    dim3 g3(Dd / 128, M_ROWS / 128);
    sgemm_bias_kernel<<<g3, 256>>>(o, out_w, out_b, out, M_ROWS, Dd, Dd, Dd);
}

// round 4
// speedup vs baseline: 1.4035x; 1.4035x over previous
#include <cuda_runtime.h>
#include <cuda_bf16.h>
#include <math.h>
#include <stdint.h>

// Problem constants
#define Bb 4
#define Ts 2048
#define Dd 1024
#define Hh 16
#define HD 64
#define M_ROWS 8192
#define QKV_N 3072

// Scratch (device globals: allocation-free)
__device__ float g_qkv[(size_t)M_ROWS * QKV_N];   // [B*T, 3D]
__device__ float g_o[(size_t)M_ROWS * Dd];        // [B*T, D]
__device__ float g_bias[Bb * Ts];                 // per-key additive bias
__device__ int   g_maskMode;                      // 0=uint8, 1=int32, 2=float32

// ===========================================================================
// helpers
// ===========================================================================
__device__ __forceinline__ uint32_t f2tf32(float f) {
    uint32_t u;
    asm("cvt.rna.tf32.f32 %0, %1;" : "=r"(u) : "f"(f));
    return u;
}

__device__ __forceinline__ void mma_tf32(float* d, const uint32_t* a, const uint32_t* b) {
    asm volatile(
        "mma.sync.aligned.m16n8k8.row.col.f32.tf32.tf32.f32 "
        "{%0,%1,%2,%3}, {%4,%5,%6,%7}, {%8,%9}, {%0,%1,%2,%3};\n"
        : "+f"(d[0]), "+f"(d[1]), "+f"(d[2]), "+f"(d[3])
        : "r"(a[0]), "r"(a[1]), "r"(a[2]), "r"(a[3]), "r"(b[0]), "r"(b[1]));
}

// ===========================================================================
// Mask dtype detection (mask may arrive as uint8 / int32 / float32)
// ===========================================================================
__global__ void detect_mask_kernel(const unsigned char* __restrict__ mask)
{
    __shared__ unsigned int orr[4][256];
    const int tid = threadIdx.x;
    unsigned int o0 = 0, o1 = 0, o2 = 0, o3 = 0;
    for (int i = tid * 4; i < Bb * Ts; i += 256 * 4) {
        o0 |= mask[i + 0]; o1 |= mask[i + 1]; o2 |= mask[i + 2]; o3 |= mask[i + 3];
    }
    orr[0][tid] = o0; orr[1][tid] = o1; orr[2][tid] = o2; orr[3][tid] = o3;
    __syncthreads();
    for (int s = 128; s; s >>= 1) {
        if (tid < s) {
            orr[0][tid] |= orr[0][tid + s];
            orr[1][tid] |= orr[1][tid + s];
            orr[2][tid] |= orr[2][tid + s];
            orr[3][tid] |= orr[3][tid + s];
        }
        __syncthreads();
    }
    if (tid == 0) {
        unsigned int l0 = orr[0][0], l1 = orr[1][0], l2 = orr[2][0], l3 = orr[3][0];
        int mode;
        if ((l1 | l2 | l3) == 0u) mode = 1;
        else if ((l0 | l1) == 0u && (l2 | l3) != 0u) mode = 2;
        else mode = 0;
        g_maskMode = mode;
    }
}

__global__ void bias_kernel(const float* __restrict__ eng, const void* __restrict__ mask)
{
    const int kk = blockIdx.x * 256 + threadIdx.x;
    if (kk >= Bb * Ts) return;
    const int mode = g_maskMode;
    bool m;
    if (mode == 1)      m = ((const int*)mask)[kk] != 0;
    else if (mode == 2) m = ((const float*)mask)[kk] != 0.f;
    else                m = ((const unsigned char*)mask)[kk] != 0;
    g_bias[kk] = m ? -1e9f : logf(fmaxf(eng[kk], 1e-6f));
}

// ===========================================================================
// tf32 mma.sync GEMM: C[M,N] = A[M,K] @ W[N,K]^T + bias[N]
// 128x128 block, BK=32, double-buffered SMEM (stride 36 floats -> fragment
// LDS conflict-free), 8 warps, warp tile 32x64, m16n8k8 tf32 HMMA.
// ===========================================================================
#define LDS_STRIDE 36
#define BUF_FLOATS (128 * LDS_STRIDE)     // 4608 floats = 18432 B
#define GEMM_SMEM_BYTES (4 * BUF_FLOATS * 4)  // 73728 B

__global__ void __launch_bounds__(256)
tf32_mma_gemm(const float* __restrict__ A, const float* __restrict__ W,
              const float* __restrict__ bias, float* __restrict__ C,
              int K, int ldc)
{
    extern __shared__ float smem[];
    float* sA = smem;                    // [2][BUF_FLOATS]
    float* sB = smem + 2 * BUF_FLOATS;   // [2][BUF_FLOATS]

    const int tid  = threadIdx.x;
    const int wid  = tid >> 5;
    const int lane = tid & 31;
    const int g = lane >> 2;
    const int t = lane & 3;
    const int wm = wid & 3;     // 0..3 (M)
    const int wn = wid >> 2;    // 0..1 (N)
    const int bm = blockIdx.y * 128;
    const int bn = blockIdx.x * 128;

    const int r0 = tid >> 3;    // 0..31
    const int q  = tid & 7;     // float4 index within BK=32

    const float* Ag = A + (size_t)(bm + r0) * K + q * 4;
    const float* Wg = W + (size_t)(bn + r0) * K + q * 4;

    float acc[2][8][4];
#pragma unroll
    for (int mi = 0; mi < 2; ++mi)
#pragma unroll
        for (int ni = 0; ni < 8; ++ni)
#pragma unroll
            for (int r = 0; r < 4; ++r) acc[mi][ni][r] = 0.f;

    float4 va[4], vb[4];
    const int nChunks = K >> 5;

    // prologue: chunk 0
#pragma unroll
    for (int it = 0; it < 4; ++it) {
        va[it] = *(const float4*)(Ag + (size_t)(32 * it) * K);
        vb[it] = *(const float4*)(Wg + (size_t)(32 * it) * K);
    }
    {
        float* dA = sA;
        float* dB = sB;
#pragma unroll
        for (int it = 0; it < 4; ++it) {
            const int r = r0 + 32 * it;
            uint4 ua, ub;
            ua.x = f2tf32(va[it].x); ua.y = f2tf32(va[it].y);
            ua.z = f2tf32(va[it].z); ua.w = f2tf32(va[it].w);
            ub.x = f2tf32(vb[it].x); ub.y = f2tf32(vb[it].y);
            ub.z = f2tf32(vb[it].z); ub.w = f2tf32(vb[it].w);
            *(uint4*)(dA + r * LDS_STRIDE + q * 4) = ua;
            *(uint4*)(dB + r * LDS_STRIDE + q * 4) = ub;
        }
    }
    __syncthreads();

    for (int kt = 0; kt < nChunks; ++kt) {
        const int cur = kt & 1;

        if (kt + 1 < nChunks) {
#pragma unroll
            for (int it = 0; it < 4; ++it) {
                va[it] = *(const float4*)(Ag + (size_t)(32 * it) * K + (kt + 1) * 32);
                vb[it] = *(const float4*)(Wg + (size_t)(32 * it) * K + (kt + 1) * 32);
            }
        }

        // compute on buffer `cur`
        const float* bufA = sA + cur * BUF_FLOATS;
        const float* bufB = sB + cur * BUF_FLOATS;
#pragma unroll
        for (int ks = 0; ks < 4; ++ks) {
            const int k0 = ks * 8;
            uint32_t af[2][4], bf[8][2];
#pragma unroll
            for (int mi = 0; mi < 2; ++mi) {
                const float* base = bufA + (wm * 32 + mi * 16 + g) * LDS_STRIDE + k0 + t;
                af[mi][0] = __float_as_uint(base[0]);
                af[mi][1] = __float_as_uint(base[8 * LDS_STRIDE]);
                af[mi][2] = __float_as_uint(base[4]);
                af[mi][3] = __float_as_uint(base[8 * LDS_STRIDE + 4]);
            }
#pragma unroll
            for (int ni = 0; ni < 8; ++ni) {
                const float* base = bufB + (wn * 64 + ni * 8 + g) * LDS_STRIDE + k0 + t;
                bf[ni][0] = __float_as_uint(base[0]);
                bf[ni][1] = __float_as_uint(base[4]);
            }
#pragma unroll
            for (int mi = 0; mi < 2; ++mi)
#pragma unroll
                for (int ni = 0; ni < 8; ++ni)
                    mma_tf32(acc[mi][ni], af[mi], bf[ni]);
        }

        if (kt + 1 < nChunks) {
            float* dA = sA + (cur ^ 1) * BUF_FLOATS;
            float* dB = sB + (cur ^ 1) * BUF_FLOATS;
#pragma unroll
            for (int it = 0; it < 4; ++it) {
                const int r = r0 + 32 * it;
                uint4 ua, ub;
                ua.x = f2tf32(va[it].x); ua.y = f2tf32(va[it].y);
                ua.z = f2tf32(va[it].z); ua.w = f2tf32(va[it].w);
                ub.x = f2tf32(vb[it].x); ub.y = f2tf32(vb[it].y);
                ub.z = f2tf32(vb[it].z); ub.w = f2tf32(vb[it].w);
                *(uint4*)(dA + r * LDS_STRIDE + q * 4) = ua;
                *(uint4*)(dB + r * LDS_STRIDE + q * 4) = ub;
            }
        }
        __syncthreads();
    }

    // epilogue: bias + store
#pragma unroll
    for (int mi = 0; mi < 2; ++mi) {
        const int row = bm + wm * 32 + mi * 16 + g;
#pragma unroll
        for (int ni = 0; ni < 8; ++ni) {
            const int col = bn + wn * 64 + ni * 8 + 2 * t;
            const float b0 = bias[col];
            const float b1 = bias[col + 1];
            float2 lo, hi;
            lo.x = acc[mi][ni][0] + b0; lo.y = acc[mi][ni][1] + b1;
            hi.x = acc[mi][ni][2] + b0; hi.y = acc[mi][ni][3] + b1;
            *(float2*)(C + (size_t)row * ldc + col) = lo;
            *(float2*)(C + (size_t)(row + 8) * ldc + col) = hi;
        }
    }
}

// ===========================================================================
// Flash attention (fp32) with per-key bias from g_bias.
// Block = 256 threads = 8 warps -> one (b, h, 64-query tile).
// ===========================================================================
__device__ __forceinline__ float warpMax(float v) {
#pragma unroll
    for (int o = 16; o; o >>= 1) v = fmaxf(v, __shfl_xor_sync(0xffffffffu, v, o));
    return v;
}
__device__ __forceinline__ float warpSum(float v) {
#pragma unroll
    for (int o = 16; o; o >>= 1) v += __shfl_xor_sync(0xffffffffu, v, o);
    return v;
}

__global__ void __launch_bounds__(256)
attn_kernel(const float* __restrict__ qkv, float* __restrict__ O)
{
    __shared__ float Kt[64][65];      // K tile d-major; reused for P
    __shared__ float Vs[64][64];      // V tile k-major
    __shared__ float biasS[64];

    const int qt = blockIdx.x;
    const int h  = blockIdx.y;
    const int b  = blockIdx.z;
    const int tid  = threadIdx.x;
    const int warp = tid >> 5;
    const int lane = tid & 31;

    const float scale = 0.125f;

    float qreg[8][2];
#pragma unroll
    for (int r = 0; r < 8; ++r) {
        const int q = qt * 64 + warp * 8 + r;
        const float* qp = qkv + (size_t)(b * Ts + q) * QKV_N + h * HD;
        qreg[r][0] = qp[lane];
        qreg[r][1] = qp[lane + 32];
    }

    float acc0[8], acc1[8], m[8], l[8];
#pragma unroll
    for (int r = 0; r < 8; ++r) { acc0[r] = 0.f; acc1[r] = 0.f; m[r] = -1e30f; l[r] = 0.f; }

    const int r64   = tid >> 2;
    const int dbase = (tid & 3) * 16;

    float* Pw = &Kt[0][0] + warp * 512;

    for (int j = 0; j < Ts / 64; ++j) {
        const int kg = j * 64 + r64;
        const float* kbase = qkv + (size_t)(b * Ts + kg) * QKV_N + Dd     + h * HD + dbase;
        const float* vbase = qkv + (size_t)(b * Ts + kg) * QKV_N + 2 * Dd + h * HD + dbase;
#pragma unroll
        for (int i = 0; i < 4; ++i) {
            float4 kv = *(const float4*)(kbase + i * 4);
            Kt[dbase + i * 4 + 0][r64] = kv.x;
            Kt[dbase + i * 4 + 1][r64] = kv.y;
            Kt[dbase + i * 4 + 2][r64] = kv.z;
            Kt[dbase + i * 4 + 3][r64] = kv.w;
            *(float4*)&Vs[r64][dbase + i * 4] = *(const float4*)(vbase + i * 4);
        }
        if (tid < 64) biasS[tid] = g_bias[b * Ts + j * 64 + tid];
        __syncthreads();

        // S = Q K^T
        float s0[8], s1[8];
#pragma unroll
        for (int r = 0; r < 8; ++r) { s0[r] = 0.f; s1[r] = 0.f; }
#pragma unroll
        for (int d = 0; d < 64; ++d) {
            const float k0 = Kt[d][lane];
            const float k1 = Kt[d][lane + 32];
#pragma unroll
            for (int r = 0; r < 8; ++r) {
                const float qv = __shfl_sync(0xffffffffu, qreg[r][d >> 5], d & 31);
                s0[r] = fmaf(qv, k0, s0[r]);
                s1[r] = fmaf(qv, k1, s1[r]);
            }
        }
        __syncthreads();

        // online softmax
        const float bs0 = biasS[lane];
        const float bs1 = biasS[lane + 32];
#pragma unroll
        for (int r = 0; r < 8; ++r) {
            const float v0 = s0[r] * scale + bs0;
            const float v1 = s1[r] * scale + bs1;
            const float mt = warpMax(fmaxf(v0, v1));
            const float mnew = fmaxf(m[r], mt);
            const float alpha = __expf(m[r] - mnew);
            const float p0 = __expf(v0 - mnew);
            const float p1 = __expf(v1 - mnew);
            l[r] = l[r] * alpha + warpSum(p0 + p1);
            m[r] = mnew;
            acc0[r] *= alpha;
            acc1[r] *= alpha;
            Pw[r * 64 + lane] = p0;
            Pw[r * 64 + lane + 32] = p1;
        }
        __syncwarp();

        // O += P V
#pragma unroll
        for (int k = 0; k < 64; ++k) {
            const float v0 = Vs[k][lane];
            const float v1 = Vs[k][lane + 32];
#pragma unroll
            for (int r = 0; r < 8; ++r) {
                const float p = Pw[r * 64 + k];
                acc0[r] = fmaf(p, v0, acc0[r]);
                acc1[r] = fmaf(p, v1, acc1[r]);
            }
        }
        __syncthreads();
    }

#pragma unroll
    for (int r = 0; r < 8; ++r) {
        const float inv = 1.0f / l[r];
        const int q = qt * 64 + warp * 8 + r;
        float* op = O + (size_t)(b * Ts + q) * Dd + h * HD;
        op[lane]      = acc0[r] * inv;
        op[lane + 32] = acc1[r] * inv;
    }
}

// ===========================================================================
extern "C" void kernel_launch(void* const* d_in, const int* in_sizes, int n_in,
                              void* d_out, int out_size)
{
    const float* x     = (const float*)d_in[0];
    const float* eng   = (const float*)d_in[1];
    const void*  mask  = (const void*)d_in[2];
    const float* qkv_w = (const float*)d_in[3];
    const float* qkv_b = (const float*)d_in[4];
    const float* out_w = (const float*)d_in[5];
    const float* out_b = (const float*)d_in[6];
    float* out = (float*)d_out;

    float* qkv = nullptr;
    float* o   = nullptr;
    cudaGetSymbolAddress((void**)&qkv, g_qkv);
    cudaGetSymbolAddress((void**)&o,   g_o);

    cudaFuncSetAttribute(tf32_mma_gemm,
                         cudaFuncAttributeMaxDynamicSharedMemorySize, GEMM_SMEM_BYTES);

    // 0) mask dtype detection + per-key bias precompute
    detect_mask_kernel<<<1, 256>>>((const unsigned char*)mask);
    bias_kernel<<<(Bb * Ts + 255) / 256, 256>>>(eng, mask);

    // 1) QKV projection: [8192,1024] @ [3072,1024]^T + b  (tf32 mma.sync)
    dim3 g1(QKV_N / 128, M_ROWS / 128);
    tf32_mma_gemm<<<g1, 256, GEMM_SMEM_BYTES>>>(x, qkv_w, qkv_b, qkv, Dd, QKV_N);

    // 2) attention (fp32 flash)
    dim3 g2(Ts / 64, Hh, Bb);
    attn_kernel<<<g2, 256>>>(qkv, o);

    // 3) output projection: [8192,1024] @ [1024,1024]^T + b  (tf32 mma.sync)
    dim3 g3(Dd / 128, M_ROWS / 128);
    tf32_mma_gemm<<<g3, 256, GEMM_SMEM_BYTES>>>(o, out_w, out_b, out, Dd, Dd);
}

// round 5
// speedup vs baseline: 2.8473x; 2.0288x over previous
#include <cuda_runtime.h>
#include <cuda_bf16.h>
#include <math.h>
#include <stdint.h>

// Problem constants
#define Bb 4
#define Ts 2048
#define Dd 1024
#define Hh 16
#define HD 64
#define M_ROWS 8192
#define QKV_N 3072

// Scratch (device globals: allocation-free)
__device__ float g_qkv[(size_t)M_ROWS * QKV_N];   // [B*T, 3D]
__device__ float g_o[(size_t)M_ROWS * Dd];        // [B*T, D]
__device__ float g_bias[Bb * Ts];                 // per-key additive bias
__device__ int   g_maskMode;                      // 0=uint8, 1=int32, 2=float32

// ===========================================================================
// helpers
// ===========================================================================
__device__ __forceinline__ uint32_t f2tf32(float f) {
    uint32_t u;
    asm("cvt.rna.tf32.f32 %0, %1;" : "=r"(u) : "f"(f));
    return u;
}

__device__ __forceinline__ void mma_tf32(float* d, const uint32_t* a, const uint32_t* b) {
    asm volatile(
        "mma.sync.aligned.m16n8k8.row.col.f32.tf32.tf32.f32 "
        "{%0,%1,%2,%3}, {%4,%5,%6,%7}, {%8,%9}, {%0,%1,%2,%3};\n"
        : "+f"(d[0]), "+f"(d[1]), "+f"(d[2]), "+f"(d[3])
        : "r"(a[0]), "r"(a[1]), "r"(a[2]), "r"(a[3]), "r"(b[0]), "r"(b[1]));
}

__device__ __forceinline__ void mma_bf16(float* c, const uint32_t* a, uint32_t b0, uint32_t b1) {
    asm volatile(
        "mma.sync.aligned.m16n8k16.row.col.f32.bf16.bf16.f32 "
        "{%0,%1,%2,%3}, {%4,%5,%6,%7}, {%8,%9}, {%0,%1,%2,%3};\n"
        : "+f"(c[0]), "+f"(c[1]), "+f"(c[2]), "+f"(c[3])
        : "r"(a[0]), "r"(a[1]), "r"(a[2]), "r"(a[3]), "r"(b0), "r"(b1));
}

// split (x,y) into bf16 hi pair + bf16 lo pair, packed as b32
__device__ __forceinline__ void split2(float x, float y, uint32_t& hi, uint32_t& lo) {
    __nv_bfloat16 hx = __float2bfloat16_rn(x);
    __nv_bfloat16 hy = __float2bfloat16_rn(y);
    __nv_bfloat16 lx = __float2bfloat16_rn(x - __bfloat162float(hx));
    __nv_bfloat16 ly = __float2bfloat16_rn(y - __bfloat162float(hy));
    __nv_bfloat162 h2 = __halves2bfloat162(hx, hy);
    __nv_bfloat162 l2 = __halves2bfloat162(lx, ly);
    hi = *(uint32_t*)&h2;
    lo = *(uint32_t*)&l2;
}

// fast exp on FMA pipe (degree-6 2^f poly), ~1e-7 rel, clamped at -87
__device__ __forceinline__ float fast_exp(float x) {
    x = fmaxf(x, -87.0f);
    const float y  = x * 1.4426950408889634f;
    const float zf = y + 12582912.0f;                 // 1.5*2^23: round-to-int
    const float f  = y - (zf - 12582912.0f);          // f in [-0.5, 0.5]
    const int   n  = (__float_as_int(zf) & 0x7FFFFF) - 0x400000;
    float p = 1.5403530e-4f;
    p = fmaf(p, f, 1.3333558e-3f);
    p = fmaf(p, f, 9.6181291e-3f);
    p = fmaf(p, f, 5.5504109e-2f);
    p = fmaf(p, f, 2.4022651e-1f);
    p = fmaf(p, f, 6.9314718e-1f);
    p = fmaf(p, f, 1.0f);
    return __int_as_float(__float_as_int(p) + (n << 23));
}

// ===========================================================================
// Mask dtype detection (mask may arrive as uint8 / int32 / float32)
// ===========================================================================
__global__ void detect_mask_kernel(const unsigned char* __restrict__ mask)
{
    __shared__ unsigned int orr[4][256];
    const int tid = threadIdx.x;
    unsigned int o0 = 0, o1 = 0, o2 = 0, o3 = 0;
    for (int i = tid * 4; i < Bb * Ts; i += 256 * 4) {
        o0 |= mask[i + 0]; o1 |= mask[i + 1]; o2 |= mask[i + 2]; o3 |= mask[i + 3];
    }
    orr[0][tid] = o0; orr[1][tid] = o1; orr[2][tid] = o2; orr[3][tid] = o3;
    __syncthreads();
    for (int s = 128; s; s >>= 1) {
        if (tid < s) {
            orr[0][tid] |= orr[0][tid + s];
            orr[1][tid] |= orr[1][tid + s];
            orr[2][tid] |= orr[2][tid + s];
            orr[3][tid] |= orr[3][tid + s];
        }
        __syncthreads();
    }
    if (tid == 0) {
        unsigned int l0 = orr[0][0], l1 = orr[1][0], l2 = orr[2][0], l3 = orr[3][0];
        int mode;
        if ((l1 | l2 | l3) == 0u) mode = 1;
        else if ((l0 | l1) == 0u && (l2 | l3) != 0u) mode = 2;
        else mode = 0;
        g_maskMode = mode;
    }
}

__global__ void bias_kernel(const float* __restrict__ eng, const void* __restrict__ mask)
{
    const int kk = blockIdx.x * 256 + threadIdx.x;
    if (kk >= Bb * Ts) return;
    const int mode = g_maskMode;
    bool m;
    if (mode == 1)      m = ((const int*)mask)[kk] != 0;
    else if (mode == 2) m = ((const float*)mask)[kk] != 0.f;
    else                m = ((const unsigned char*)mask)[kk] != 0;
    g_bias[kk] = m ? -1e9f : logf(fmaxf(eng[kk], 1e-6f));
}

// ===========================================================================
// tf32 mma.sync GEMM (unchanged from round 4)
// ===========================================================================
#define LDS_STRIDE 36
#define BUF_FLOATS (128 * LDS_STRIDE)
#define GEMM_SMEM_BYTES (4 * BUF_FLOATS * 4)

__global__ void __launch_bounds__(256)
tf32_mma_gemm(const float* __restrict__ A, const float* __restrict__ W,
              const float* __restrict__ bias, float* __restrict__ C,
              int K, int ldc)
{
    extern __shared__ float smem[];
    float* sA = smem;
    float* sB = smem + 2 * BUF_FLOATS;

    const int tid  = threadIdx.x;
    const int wid  = tid >> 5;
    const int lane = tid & 31;
    const int g = lane >> 2;
    const int t = lane & 3;
    const int wm = wid & 3;
    const int wn = wid >> 2;
    const int bm = blockIdx.y * 128;
    const int bn = blockIdx.x * 128;

    const int r0 = tid >> 3;
    const int q  = tid & 7;

    const float* Ag = A + (size_t)(bm + r0) * K + q * 4;
    const float* Wg = W + (size_t)(bn + r0) * K + q * 4;

    float acc[2][8][4];
#pragma unroll
    for (int mi = 0; mi < 2; ++mi)
#pragma unroll
        for (int ni = 0; ni < 8; ++ni)
#pragma unroll
            for (int r = 0; r < 4; ++r) acc[mi][ni][r] = 0.f;

    float4 va[4], vb[4];
    const int nChunks = K >> 5;

#pragma unroll
    for (int it = 0; it < 4; ++it) {
        va[it] = *(const float4*)(Ag + (size_t)(32 * it) * K);
        vb[it] = *(const float4*)(Wg + (size_t)(32 * it) * K);
    }
    {
        float* dA = sA;
        float* dB = sB;
#pragma unroll
        for (int it = 0; it < 4; ++it) {
            const int r = r0 + 32 * it;
            uint4 ua, ub;
            ua.x = f2tf32(va[it].x); ua.y = f2tf32(va[it].y);
            ua.z = f2tf32(va[it].z); ua.w = f2tf32(va[it].w);
            ub.x = f2tf32(vb[it].x); ub.y = f2tf32(vb[it].y);
            ub.z = f2tf32(vb[it].z); ub.w = f2tf32(vb[it].w);
            *(uint4*)(dA + r * LDS_STRIDE + q * 4) = ua;
            *(uint4*)(dB + r * LDS_STRIDE + q * 4) = ub;
        }
    }
    __syncthreads();

    for (int kt = 0; kt < nChunks; ++kt) {
        const int cur = kt & 1;

        if (kt + 1 < nChunks) {
#pragma unroll
            for (int it = 0; it < 4; ++it) {
                va[it] = *(const float4*)(Ag + (size_t)(32 * it) * K + (kt + 1) * 32);
                vb[it] = *(const float4*)(Wg + (size_t)(32 * it) * K + (kt + 1) * 32);
            }
        }

        const float* bufA = sA + cur * BUF_FLOATS;
        const float* bufB = sB + cur * BUF_FLOATS;
#pragma unroll
        for (int ks = 0; ks < 4; ++ks) {
            const int k0 = ks * 8;
            uint32_t af[2][4], bf[8][2];
#pragma unroll
            for (int mi = 0; mi < 2; ++mi) {
                const float* base = bufA + (wm * 32 + mi * 16 + g) * LDS_STRIDE + k0 + t;
                af[mi][0] = __float_as_uint(base[0]);
                af[mi][1] = __float_as_uint(base[8 * LDS_STRIDE]);
                af[mi][2] = __float_as_uint(base[4]);
                af[mi][3] = __float_as_uint(base[8 * LDS_STRIDE + 4]);
            }
#pragma unroll
            for (int ni = 0; ni < 8; ++ni) {
                const float* base = bufB + (wn * 64 + ni * 8 + g) * LDS_STRIDE + k0 + t;
                bf[ni][0] = __float_as_uint(base[0]);
                bf[ni][1] = __float_as_uint(base[4]);
            }
#pragma unroll
            for (int mi = 0; mi < 2; ++mi)
#pragma unroll
                for (int ni = 0; ni < 8; ++ni)
                    mma_tf32(acc[mi][ni], af[mi], bf[ni]);
        }

        if (kt + 1 < nChunks) {
            float* dA = sA + (cur ^ 1) * BUF_FLOATS;
            float* dB = sB + (cur ^ 1) * BUF_FLOATS;
#pragma unroll
            for (int it = 0; it < 4; ++it) {
                const int r = r0 + 32 * it;
                uint4 ua, ub;
                ua.x = f2tf32(va[it].x); ua.y = f2tf32(va[it].y);
                ua.z = f2tf32(va[it].z); ua.w = f2tf32(va[it].w);
                ub.x = f2tf32(vb[it].x); ub.y = f2tf32(vb[it].y);
                ub.z = f2tf32(vb[it].z); ub.w = f2tf32(vb[it].w);
                *(uint4*)(dA + r * LDS_STRIDE + q * 4) = ua;
                *(uint4*)(dB + r * LDS_STRIDE + q * 4) = ub;
            }
        }
        __syncthreads();
    }

#pragma unroll
    for (int mi = 0; mi < 2; ++mi) {
        const int row = bm + wm * 32 + mi * 16 + g;
#pragma unroll
        for (int ni = 0; ni < 8; ++ni) {
            const int col = bn + wn * 64 + ni * 8 + 2 * t;
            const float b0 = bias[col];
            const float b1 = bias[col + 1];
            float2 lo, hi;
            lo.x = acc[mi][ni][0] + b0; lo.y = acc[mi][ni][1] + b1;
            hi.x = acc[mi][ni][2] + b0; hi.y = acc[mi][ni][3] + b1;
            *(float2*)(C + (size_t)row * ldc + col) = lo;
            *(float2*)(C + (size_t)(row + 8) * ldc + col) = hi;
        }
    }
}

// ===========================================================================
// Tensor-core flash attention, bf16x2-split (3-MMA) for S and PV.
// Block = 128 threads (4 warps) -> one (b, h, 64-query tile); warp = 16 q rows.
// K tile: planes [key][hd-pair-words], V tile transposed: [d][key-pair-words].
// ===========================================================================
#define AT_W 36   // u32 words per plane row (32 data + 4 pad; 4g+t bank pattern)

__global__ void __launch_bounds__(128)
attn_bf16_kernel(const float* __restrict__ qkv, float* __restrict__ O)
{
    __shared__ uint32_t sKh[64 * AT_W], sKl[64 * AT_W];
    __shared__ uint32_t sVh[64 * AT_W], sVl[64 * AT_W];
    __shared__ float biasS[64];

    const int qt = blockIdx.x;    // 64-query tile
    const int h  = blockIdx.y;
    const int b  = blockIdx.z;
    const int tid  = threadIdx.x;
    const int warp = tid >> 5;
    const int lane = tid & 31;
    const int g = lane >> 2, t = lane & 3;

    // ---- Q fragments (split bf16): rows qt*64 + warp*16 + {g, g+8} ----
    uint32_t qh[4][4], ql[4][4];
    {
        const float* q0 = qkv + (size_t)(b * Ts + qt * 64 + warp * 16 + g) * QKV_N + h * HD;
        const float* q1 = q0 + (size_t)8 * QKV_N;
#pragma unroll
        for (int ks = 0; ks < 4; ++ks) {
#pragma unroll
            for (int hf = 0; hf < 2; ++hf) {
                const int col = 16 * ks + 2 * t + 8 * hf;
                const float2 v0 = *(const float2*)(q0 + col);
                const float2 v1 = *(const float2*)(q1 + col);
                split2(v0.x, v0.y, qh[ks][2 * hf + 0], ql[ks][2 * hf + 0]);
                split2(v1.x, v1.y, qh[ks][2 * hf + 1], ql[ks][2 * hf + 1]);
            }
        }
    }

    float o[8][4];
#pragma unroll
    for (int i = 0; i < 8; ++i)
#pragma unroll
        for (int j = 0; j < 4; ++j) o[i][j] = 0.f;
    float m0 = -1e30f, m1 = -1e30f, l0 = 0.f, l1 = 0.f;

    const int a  = tid >> 2;   // key pair 0..31 (keys 2a, 2a+1)
    const int cb = tid & 3;    // col block of 16

    for (int kt = 0; kt < Ts / 64; ++kt) {
        // ---- load + split K (row-major pairs) and V (transposed pairs) ----
        const float* kb = qkv + (size_t)(b * Ts + kt * 64 + 2 * a) * QKV_N + Dd + h * HD + 16 * cb;
        const float* vb = kb + Dd;
#pragma unroll
        for (int i = 0; i < 4; ++i) {
            const float4 k0 = *(const float4*)(kb + 4 * i);
            const float4 k1 = *(const float4*)(kb + QKV_N + 4 * i);
            uint32_t hi0, lo0, hi1, lo1;
            split2(k0.x, k0.y, hi0, lo0);
            split2(k0.z, k0.w, hi1, lo1);
            sKh[2 * a * AT_W + 8 * cb + 2 * i]     = hi0;
            sKh[2 * a * AT_W + 8 * cb + 2 * i + 1] = hi1;
            sKl[2 * a * AT_W + 8 * cb + 2 * i]     = lo0;
            sKl[2 * a * AT_W + 8 * cb + 2 * i + 1] = lo1;
            split2(k1.x, k1.y, hi0, lo0);
            split2(k1.z, k1.w, hi1, lo1);
            sKh[(2 * a + 1) * AT_W + 8 * cb + 2 * i]     = hi0;
            sKh[(2 * a + 1) * AT_W + 8 * cb + 2 * i + 1] = hi1;
            sKl[(2 * a + 1) * AT_W + 8 * cb + 2 * i]     = lo0;
            sKl[(2 * a + 1) * AT_W + 8 * cb + 2 * i + 1] = lo1;

            const float4 v0 = *(const float4*)(vb + 4 * i);
            const float4 v1 = *(const float4*)(vb + QKV_N + 4 * i);
            const float v0a[4] = {v0.x, v0.y, v0.z, v0.w};
            const float v1a[4] = {v1.x, v1.y, v1.z, v1.w};
#pragma unroll
            for (int j = 0; j < 4; ++j) {
                const int d = 16 * cb + 4 * i + j;
                uint32_t hv, lv;
                split2(v0a[j], v1a[j], hv, lv);   // pack(V[key2a][d], V[key2a+1][d])
                sVh[d * AT_W + a] = hv;
                sVl[d * AT_W + a] = lv;
            }
        }
        if (tid < 64) biasS[tid] = g_bias[b * Ts + kt * 64 + tid];
        __syncthreads();

        // ---- S = Q K^T (bf16x3) ----
        float sacc[8][4];
#pragma unroll
        for (int nt = 0; nt < 8; ++nt)
#pragma unroll
            for (int j = 0; j < 4; ++j) sacc[nt][j] = 0.f;
#pragma unroll
        for (int ks = 0; ks < 4; ++ks) {
#pragma unroll
            for (int nt = 0; nt < 8; ++nt) {
                const int base = (8 * nt + g) * AT_W + 8 * ks + t;
                const uint32_t bh0 = sKh[base], bh1 = sKh[base + 4];
                const uint32_t bl0 = sKl[base], bl1 = sKl[base + 4];
                mma_bf16(sacc[nt], qh[ks], bh0, bh1);
                mma_bf16(sacc[nt], qh[ks], bl0, bl1);
                mma_bf16(sacc[nt], ql[ks], bh0, bh1);
            }
        }

        // ---- online softmax (C-frag layout: rows g, g+8; cols 2t,2t+1 per nt) ----
        float mt0 = -1e30f, mt1 = -1e30f;
#pragma unroll
        for (int nt = 0; nt < 8; ++nt) {
            const float b0 = biasS[8 * nt + 2 * t];
            const float b1 = biasS[8 * nt + 2 * t + 1];
            sacc[nt][0] = fmaf(sacc[nt][0], 0.125f, b0);
            sacc[nt][1] = fmaf(sacc[nt][1], 0.125f, b1);
            sacc[nt][2] = fmaf(sacc[nt][2], 0.125f, b0);
            sacc[nt][3] = fmaf(sacc[nt][3], 0.125f, b1);
            mt0 = fmaxf(mt0, fmaxf(sacc[nt][0], sacc[nt][1]));
            mt1 = fmaxf(mt1, fmaxf(sacc[nt][2], sacc[nt][3]));
        }
        mt0 = fmaxf(mt0, __shfl_xor_sync(0xffffffffu, mt0, 1));
        mt0 = fmaxf(mt0, __shfl_xor_sync(0xffffffffu, mt0, 2));
        mt1 = fmaxf(mt1, __shfl_xor_sync(0xffffffffu, mt1, 1));
        mt1 = fmaxf(mt1, __shfl_xor_sync(0xffffffffu, mt1, 2));

        const float mn0 = fmaxf(m0, mt0);
        const float mn1 = fmaxf(m1, mt1);
        const float al0 = fast_exp(m0 - mn0);
        const float al1 = fast_exp(m1 - mn1);
        m0 = mn0; m1 = mn1;

        float rs0 = 0.f, rs1 = 0.f;
        uint32_t ph[8][2], pl[8][2];
#pragma unroll
        for (int nt = 0; nt < 8; ++nt) {
            const float p0 = fast_exp(sacc[nt][0] - mn0);
            const float p1 = fast_exp(sacc[nt][1] - mn0);
            const float p2 = fast_exp(sacc[nt][2] - mn1);
            const float p3 = fast_exp(sacc[nt][3] - mn1);
            rs0 += p0 + p1;
            rs1 += p2 + p3;
            split2(p0, p1, ph[nt][0], pl[nt][0]);
            split2(p2, p3, ph[nt][1], pl[nt][1]);
        }
        rs0 += __shfl_xor_sync(0xffffffffu, rs0, 1);
        rs0 += __shfl_xor_sync(0xffffffffu, rs0, 2);
        rs1 += __shfl_xor_sync(0xffffffffu, rs1, 1);
        rs1 += __shfl_xor_sync(0xffffffffu, rs1, 2);
        l0 = l0 * al0 + rs0;
        l1 = l1 * al1 + rs1;
#pragma unroll
        for (int ndt = 0; ndt < 8; ++ndt) {
            o[ndt][0] *= al0; o[ndt][1] *= al0;
            o[ndt][2] *= al1; o[ndt][3] *= al1;
        }

        // ---- O += P V (bf16x3); S C-frags feed A-frags directly ----
#pragma unroll
        for (int kp = 0; kp < 4; ++kp) {
            const uint32_t ah[4] = { ph[2 * kp][0], ph[2 * kp][1], ph[2 * kp + 1][0], ph[2 * kp + 1][1] };
            const uint32_t apl[4] = { pl[2 * kp][0], pl[2 * kp][1], pl[2 * kp + 1][0], pl[2 * kp + 1][1] };
#pragma unroll
            for (int ndt = 0; ndt < 8; ++ndt) {
                const int base = (8 * ndt + g) * AT_W + 8 * kp + t;
                const uint32_t bh0 = sVh[base], bh1 = sVh[base + 4];
                const uint32_t bl0 = sVl[base], bl1 = sVl[base + 4];
                mma_bf16(o[ndt], ah, bh0, bh1);
                mma_bf16(o[ndt], ah, bl0, bl1);
                mma_bf16(o[ndt], apl, bh0, bh1);
            }
        }
        __syncthreads();
    }

    // ---- epilogue ----
    const float inv0 = 1.0f / l0;
    const float inv1 = 1.0f / l1;
    const int row0 = b * Ts + qt * 64 + warp * 16 + g;
    float* op = O + (size_t)row0 * Dd + h * HD;
#pragma unroll
    for (int ndt = 0; ndt < 8; ++ndt) {
        float2 lo, hi;
        lo.x = o[ndt][0] * inv0; lo.y = o[ndt][1] * inv0;
        hi.x = o[ndt][2] * inv1; hi.y = o[ndt][3] * inv1;
        *(float2*)(op + ndt * 8 + 2 * t) = lo;
        *(float2*)(op + (size_t)8 * Dd + ndt * 8 + 2 * t) = hi;
    }
}

// ===========================================================================
extern "C" void kernel_launch(void* const* d_in, const int* in_sizes, int n_in,
                              void* d_out, int out_size)
{
    const float* x     = (const float*)d_in[0];
    const float* eng   = (const float*)d_in[1];
    const void*  mask  = (const void*)d_in[2];
    const float* qkv_w = (const float*)d_in[3];
    const float* qkv_b = (const float*)d_in[4];
    const float* out_w = (const float*)d_in[5];
    const float* out_b = (const float*)d_in[6];
    float* out = (float*)d_out;

    float* qkv = nullptr;
    float* o   = nullptr;
    cudaGetSymbolAddress((void**)&qkv, g_qkv);
    cudaGetSymbolAddress((void**)&o,   g_o);

    cudaFuncSetAttribute(tf32_mma_gemm,
                         cudaFuncAttributeMaxDynamicSharedMemorySize, GEMM_SMEM_BYTES);

    // 0) mask dtype detection + per-key bias precompute
    detect_mask_kernel<<<1, 256>>>((const unsigned char*)mask);
    bias_kernel<<<(Bb * Ts + 255) / 256, 256>>>(eng, mask);

    // 1) QKV projection (tf32 mma.sync)
    dim3 g1(QKV_N / 128, M_ROWS / 128);
    tf32_mma_gemm<<<g1, 256, GEMM_SMEM_BYTES>>>(x, qkv_w, qkv_b, qkv, Dd, QKV_N);

    // 2) attention (bf16x3 tensor-core flash)
    dim3 g2(Ts / 64, Hh, Bb);
    attn_bf16_kernel<<<g2, 128>>>(qkv, o);

    // 3) output projection (tf32 mma.sync)
    dim3 g3(Dd / 128, M_ROWS / 128);
    tf32_mma_gemm<<<g3, 256, GEMM_SMEM_BYTES>>>(o, out_w, out_b, out, Dd, Dd);
}

// round 6
// speedup vs baseline: 3.9305x; 1.3805x over previous
#include <cuda_runtime.h>
#include <cuda_bf16.h>
#include <math.h>
#include <stdint.h>

// Problem constants
#define Bb 4
#define Ts 2048
#define Dd 1024
#define Hh 16
#define HD 64
#define M_ROWS 8192
#define QKV_N 3072

// Scratch (device globals: allocation-free)
__device__ float g_qkv[(size_t)M_ROWS * QKV_N];   // [B*T, 3D]
__device__ float g_o[(size_t)M_ROWS * Dd];        // [B*T, D]
__device__ float g_bias[Bb * Ts];                 // per-key additive bias
__device__ int   g_maskMode;                      // 0=uint8, 1=int32, 2=float32
// Fragment-ready split-bf16 K and V: per (b,h,kt): 4096 u32 (16KB)
// K quad (ks,key,t): {hi(d=16ks+2t,+1), hi(d+8,+9), lo, lo} for that key
// V quad (kp,d,t):   {hi(keys 16kp+2t,+1), hi(keys +8,+9), lo, lo} at dim d
__device__ uint32_t g_K[(size_t)Bb * Hh * 32 * 4096];
__device__ uint32_t g_V[(size_t)Bb * Hh * 32 * 4096];

// ===========================================================================
// helpers
// ===========================================================================
__device__ __forceinline__ uint32_t f2tf32(float f) {
    uint32_t u;
    asm("cvt.rna.tf32.f32 %0, %1;" : "=r"(u) : "f"(f));
    return u;
}

__device__ __forceinline__ void mma_tf32(float* d, const uint32_t* a, const uint32_t* b) {
    asm volatile(
        "mma.sync.aligned.m16n8k8.row.col.f32.tf32.tf32.f32 "
        "{%0,%1,%2,%3}, {%4,%5,%6,%7}, {%8,%9}, {%0,%1,%2,%3};\n"
        : "+f"(d[0]), "+f"(d[1]), "+f"(d[2]), "+f"(d[3])
        : "r"(a[0]), "r"(a[1]), "r"(a[2]), "r"(a[3]), "r"(b[0]), "r"(b[1]));
}

__device__ __forceinline__ void mma_bf16(float* c, const uint32_t* a, uint32_t b0, uint32_t b1) {
    asm volatile(
        "mma.sync.aligned.m16n8k16.row.col.f32.bf16.bf16.f32 "
        "{%0,%1,%2,%3}, {%4,%5,%6,%7}, {%8,%9}, {%0,%1,%2,%3};\n"
        : "+f"(c[0]), "+f"(c[1]), "+f"(c[2]), "+f"(c[3])
        : "r"(a[0]), "r"(a[1]), "r"(a[2]), "r"(a[3]), "r"(b0), "r"(b1));
}

__device__ __forceinline__ void split2(float x, float y, uint32_t& hi, uint32_t& lo) {
    __nv_bfloat16 hx = __float2bfloat16_rn(x);
    __nv_bfloat16 hy = __float2bfloat16_rn(y);
    __nv_bfloat16 lx = __float2bfloat16_rn(x - __bfloat162float(hx));
    __nv_bfloat16 ly = __float2bfloat16_rn(y - __bfloat162float(hy));
    __nv_bfloat162 h2 = __halves2bfloat162(hx, hy);
    __nv_bfloat162 l2 = __halves2bfloat162(lx, ly);
    hi = *(uint32_t*)&h2;
    lo = *(uint32_t*)&l2;
}

__device__ __forceinline__ float fast_exp(float x) {
    x = fmaxf(x, -87.0f);
    const float y  = x * 1.4426950408889634f;
    const float zf = y + 12582912.0f;
    const float f  = y - (zf - 12582912.0f);
    const int   n  = (__float_as_int(zf) & 0x7FFFFF) - 0x400000;
    float p = 1.5403530e-4f;
    p = fmaf(p, f, 1.3333558e-3f);
    p = fmaf(p, f, 9.6181291e-3f);
    p = fmaf(p, f, 5.5504109e-2f);
    p = fmaf(p, f, 2.4022651e-1f);
    p = fmaf(p, f, 6.9314718e-1f);
    p = fmaf(p, f, 1.0f);
    return __int_as_float(__float_as_int(p) + (n << 23));
}

__device__ __forceinline__ uint32_t smem_u32(const void* p) {
    uint32_t a;
    asm("{ .reg .u64 t; cvta.to.shared.u64 t, %1; cvt.u32.u64 %0, t; }" : "=r"(a) : "l"(p));
    return a;
}
__device__ __forceinline__ void cp_async16(uint32_t dst, const void* src) {
    asm volatile("cp.async.cg.shared.global [%0], [%1], 16;" :: "r"(dst), "l"(src));
}
#define CP_COMMIT() asm volatile("cp.async.commit_group;" ::: "memory")
#define CP_WAIT(n)  asm volatile("cp.async.wait_group %0;" :: "n"(n) : "memory")

// ===========================================================================
// Mask dtype detection + bias precompute
// ===========================================================================
__global__ void detect_mask_kernel(const unsigned char* __restrict__ mask)
{
    __shared__ unsigned int orr[4][256];
    const int tid = threadIdx.x;
    unsigned int o0 = 0, o1 = 0, o2 = 0, o3 = 0;
    for (int i = tid * 4; i < Bb * Ts; i += 256 * 4) {
        o0 |= mask[i + 0]; o1 |= mask[i + 1]; o2 |= mask[i + 2]; o3 |= mask[i + 3];
    }
    orr[0][tid] = o0; orr[1][tid] = o1; orr[2][tid] = o2; orr[3][tid] = o3;
    __syncthreads();
    for (int s = 128; s; s >>= 1) {
        if (tid < s) {
            orr[0][tid] |= orr[0][tid + s];
            orr[1][tid] |= orr[1][tid + s];
            orr[2][tid] |= orr[2][tid + s];
            orr[3][tid] |= orr[3][tid + s];
        }
        __syncthreads();
    }
    if (tid == 0) {
        unsigned int l0 = orr[0][0], l1 = orr[1][0], l2 = orr[2][0], l3 = orr[3][0];
        int mode;
        if ((l1 | l2 | l3) == 0u) mode = 1;
        else if ((l0 | l1) == 0u && (l2 | l3) != 0u) mode = 2;
        else mode = 0;
        g_maskMode = mode;
    }
}

__global__ void bias_kernel(const float* __restrict__ eng, const void* __restrict__ mask)
{
    const int kk = blockIdx.x * 256 + threadIdx.x;
    if (kk >= Bb * Ts) return;
    const int mode = g_maskMode;
    bool m;
    if (mode == 1)      m = ((const int*)mask)[kk] != 0;
    else if (mode == 2) m = ((const float*)mask)[kk] != 0.f;
    else                m = ((const unsigned char*)mask)[kk] != 0;
    g_bias[kk] = m ? -1e9f : logf(fmaxf(eng[kk], 1e-6f));
}

// ===========================================================================
// K/V split + fragment-ready repack (once per (b,h,kt))
// ===========================================================================
__global__ void __launch_bounds__(256)
convert_kv_kernel(const float* __restrict__ qkv)
{
    const int kt = blockIdx.x, h = blockIdx.y, b = blockIdx.z;
    const size_t tileBase = (((size_t)(b * Hh + h)) * 32 + kt) * 4096;
    const int tid = threadIdx.x;

    // K
#pragma unroll
    for (int i = 0; i < 4; ++i) {
        const int qi  = tid + 256 * i;            // 0..1023
        const int t   = qi & 3;
        const int key = (qi >> 2) & 63;
        const int ks  = qi >> 8;
        const float* kp = qkv + (size_t)(b * Ts + kt * 64 + key) * QKV_N + Dd + h * HD + 16 * ks + 2 * t;
        const float2 v0 = *(const float2*)(kp);
        const float2 v1 = *(const float2*)(kp + 8);
        uint32_t h0, l0, h1, l1;
        split2(v0.x, v0.y, h0, l0);
        split2(v1.x, v1.y, h1, l1);
        uint4 w; w.x = h0; w.y = h1; w.z = l0; w.w = l1;
        *(uint4*)&g_K[tileBase + (size_t)qi * 4] = w;
    }
    // V (transposed fragment layout)
#pragma unroll
    for (int i = 0; i < 4; ++i) {
        const int qi  = tid + 256 * i;
        const int t   = qi & 3;
        const int d   = (qi >> 2) & 63;
        const int kp_ = qi >> 8;
        const float* vp = qkv + (size_t)(b * Ts + kt * 64 + 16 * kp_ + 2 * t) * QKV_N + 2 * Dd + h * HD + d;
        const float a0 = vp[0];
        const float a1 = vp[QKV_N];
        const float a2 = vp[8 * QKV_N];
        const float a3 = vp[9 * QKV_N];
        uint32_t h0, l0, h1, l1;
        split2(a0, a1, h0, l0);
        split2(a2, a3, h1, l1);
        uint4 w; w.x = h0; w.y = h1; w.z = l0; w.w = l1;
        *(uint4*)&g_V[tileBase + (size_t)qi * 4] = w;
    }
}

// ===========================================================================
// tf32 mma.sync GEMM (unchanged)
// ===========================================================================
#define LDS_STRIDE 36
#define BUF_FLOATS (128 * LDS_STRIDE)
#define GEMM_SMEM_BYTES (4 * BUF_FLOATS * 4)

__global__ void __launch_bounds__(256)
tf32_mma_gemm(const float* __restrict__ A, const float* __restrict__ W,
              const float* __restrict__ bias, float* __restrict__ C,
              int K, int ldc)
{
    extern __shared__ float smem[];
    float* sA = smem;
    float* sB = smem + 2 * BUF_FLOATS;

    const int tid  = threadIdx.x;
    const int wid  = tid >> 5;
    const int lane = tid & 31;
    const int g = lane >> 2;
    const int t = lane & 3;
    const int wm = wid & 3;
    const int wn = wid >> 2;
    const int bm = blockIdx.y * 128;
    const int bn = blockIdx.x * 128;

    const int r0 = tid >> 3;
    const int q  = tid & 7;

    const float* Ag = A + (size_t)(bm + r0) * K + q * 4;
    const float* Wg = W + (size_t)(bn + r0) * K + q * 4;

    float acc[2][8][4];
#pragma unroll
    for (int mi = 0; mi < 2; ++mi)
#pragma unroll
        for (int ni = 0; ni < 8; ++ni)
#pragma unroll
            for (int r = 0; r < 4; ++r) acc[mi][ni][r] = 0.f;

    float4 va[4], vb[4];
    const int nChunks = K >> 5;

#pragma unroll
    for (int it = 0; it < 4; ++it) {
        va[it] = *(const float4*)(Ag + (size_t)(32 * it) * K);
        vb[it] = *(const float4*)(Wg + (size_t)(32 * it) * K);
    }
    {
        float* dA = sA;
        float* dB = sB;
#pragma unroll
        for (int it = 0; it < 4; ++it) {
            const int r = r0 + 32 * it;
            uint4 ua, ub;
            ua.x = f2tf32(va[it].x); ua.y = f2tf32(va[it].y);
            ua.z = f2tf32(va[it].z); ua.w = f2tf32(va[it].w);
            ub.x = f2tf32(vb[it].x); ub.y = f2tf32(vb[it].y);
            ub.z = f2tf32(vb[it].z); ub.w = f2tf32(vb[it].w);
            *(uint4*)(dA + r * LDS_STRIDE + q * 4) = ua;
            *(uint4*)(dB + r * LDS_STRIDE + q * 4) = ub;
        }
    }
    __syncthreads();

    for (int kt = 0; kt < nChunks; ++kt) {
        const int cur = kt & 1;

        if (kt + 1 < nChunks) {
#pragma unroll
            for (int it = 0; it < 4; ++it) {
                va[it] = *(const float4*)(Ag + (size_t)(32 * it) * K + (kt + 1) * 32);
                vb[it] = *(const float4*)(Wg + (size_t)(32 * it) * K + (kt + 1) * 32);
            }
        }

        const float* bufA = sA + cur * BUF_FLOATS;
        const float* bufB = sB + cur * BUF_FLOATS;
#pragma unroll
        for (int ks = 0; ks < 4; ++ks) {
            const int k0 = ks * 8;
            uint32_t af[2][4], bf[8][2];
#pragma unroll
            for (int mi = 0; mi < 2; ++mi) {
                const float* base = bufA + (wm * 32 + mi * 16 + g) * LDS_STRIDE + k0 + t;
                af[mi][0] = __float_as_uint(base[0]);
                af[mi][1] = __float_as_uint(base[8 * LDS_STRIDE]);
                af[mi][2] = __float_as_uint(base[4]);
                af[mi][3] = __float_as_uint(base[8 * LDS_STRIDE + 4]);
            }
#pragma unroll
            for (int ni = 0; ni < 8; ++ni) {
                const float* base = bufB + (wn * 64 + ni * 8 + g) * LDS_STRIDE + k0 + t;
                bf[ni][0] = __float_as_uint(base[0]);
                bf[ni][1] = __float_as_uint(base[4]);
            }
#pragma unroll
            for (int mi = 0; mi < 2; ++mi)
#pragma unroll
                for (int ni = 0; ni < 8; ++ni)
                    mma_tf32(acc[mi][ni], af[mi], bf[ni]);
        }

        if (kt + 1 < nChunks) {
            float* dA = sA + (cur ^ 1) * BUF_FLOATS;
            float* dB = sB + (cur ^ 1) * BUF_FLOATS;
#pragma unroll
            for (int it = 0; it < 4; ++it) {
                const int r = r0 + 32 * it;
                uint4 ua, ub;
                ua.x = f2tf32(va[it].x); ua.y = f2tf32(va[it].y);
                ua.z = f2tf32(va[it].z); ua.w = f2tf32(va[it].w);
                ub.x = f2tf32(vb[it].x); ub.y = f2tf32(vb[it].y);
                ub.z = f2tf32(vb[it].z); ub.w = f2tf32(vb[it].w);
                *(uint4*)(dA + r * LDS_STRIDE + q * 4) = ua;
                *(uint4*)(dB + r * LDS_STRIDE + q * 4) = ub;
            }
        }
        __syncthreads();
    }

#pragma unroll
    for (int mi = 0; mi < 2; ++mi) {
        const int row = bm + wm * 32 + mi * 16 + g;
#pragma unroll
        for (int ni = 0; ni < 8; ++ni) {
            const int col = bn + wn * 64 + ni * 8 + 2 * t;
            const float b0 = bias[col];
            const float b1 = bias[col + 1];
            float2 lo, hi;
            lo.x = acc[mi][ni][0] + b0; lo.y = acc[mi][ni][1] + b1;
            hi.x = acc[mi][ni][2] + b0; hi.y = acc[mi][ni][3] + b1;
            *(float2*)(C + (size_t)row * ldc + col) = lo;
            *(float2*)(C + (size_t)(row + 8) * ldc + col) = hi;
        }
    }
}

// ===========================================================================
// Tensor-core flash attention on precomputed fragment-ready split-bf16 K/V.
// 128 threads (4 warps) per (b, h, 64-query tile); warp = 16 q rows.
// cp.async double-buffered 16KB K + 16KB V tiles; LDS.128 fragment loads.
// ===========================================================================
#define ATTN_SMEM_BYTES (2 * 16384 + 2 * 16384 + 2 * 256)

__global__ void __launch_bounds__(128, 3)
attn_bf16_kernel(const float* __restrict__ qkv, float* __restrict__ O)
{
    extern __shared__ uint32_t asmem[];
    uint32_t* sK = asmem;                 // [2][4096]
    uint32_t* sV = asmem + 8192;          // [2][4096]
    float*    sBias = (float*)(asmem + 16384);  // [2][64]

    const uint32_t sKaddr = smem_u32(sK);
    const uint32_t sVaddr = smem_u32(sV);
    const uint32_t sBaddr = smem_u32(sBias);

    const int qt = blockIdx.x;
    const int h  = blockIdx.y;
    const int b  = blockIdx.z;
    const int tid  = threadIdx.x;
    const int warp = tid >> 5;
    const int lane = tid & 31;
    const int g = lane >> 2, t = lane & 3;

    const size_t kvBase = ((size_t)(b * Hh + h)) * 32 * 4096;

    // ---- Q fragments (split bf16): rows qt*64 + warp*16 + {g, g+8} ----
    uint32_t qh[4][4], ql[4][4];
    {
        const float* q0 = qkv + (size_t)(b * Ts + qt * 64 + warp * 16 + g) * QKV_N + h * HD;
        const float* q1 = q0 + (size_t)8 * QKV_N;
#pragma unroll
        for (int ks = 0; ks < 4; ++ks) {
#pragma unroll
            for (int hf = 0; hf < 2; ++hf) {
                const int col = 16 * ks + 2 * t + 8 * hf;
                const float2 v0 = *(const float2*)(q0 + col);
                const float2 v1 = *(const float2*)(q1 + col);
                split2(v0.x, v0.y, qh[ks][2 * hf + 0], ql[ks][2 * hf + 0]);
                split2(v1.x, v1.y, qh[ks][2 * hf + 1], ql[ks][2 * hf + 1]);
            }
        }
    }

    float o[8][4];
#pragma unroll
    for (int i = 0; i < 8; ++i)
#pragma unroll
        for (int j = 0; j < 4; ++j) o[i][j] = 0.f;
    float m0 = -1e30f, m1 = -1e30f, l0 = 0.f, l1 = 0.f;

    // ---- tile fill (cp.async): 8 chunks K + 8 chunks V per thread ----
    auto issue = [&](int buf, int kt) {
        const uint32_t* srcK = g_K + kvBase + (size_t)kt * 4096 + tid * 4;
        const uint32_t* srcV = g_V + kvBase + (size_t)kt * 4096 + tid * 4;
        const uint32_t dK = sKaddr + buf * 16384 + tid * 16;
        const uint32_t dV = sVaddr + buf * 16384 + tid * 16;
#pragma unroll
        for (int i = 0; i < 8; ++i) {
            cp_async16(dK + i * 2048, srcK + i * 512);
            cp_async16(dV + i * 2048, srcV + i * 512);
        }
        if (tid < 16) cp_async16(sBaddr + buf * 256 + tid * 16, g_bias + b * Ts + kt * 64 + tid * 4);
    };

    issue(0, 0);
    CP_COMMIT();

    for (int kt = 0; kt < Ts / 64; ++kt) {
        const int buf = kt & 1;
        if (kt + 1 < Ts / 64) {
            issue(buf ^ 1, kt + 1);
            CP_COMMIT();
            CP_WAIT(1);
        } else {
            CP_WAIT(0);
        }
        __syncthreads();

        const uint32_t* bK = sK + buf * 4096;
        const uint32_t* bV = sV + buf * 4096;
        const float* bB = sBias + buf * 64;

        // ---- S = Q K^T (bf16x3) ----
        float sacc[8][4];
#pragma unroll
        for (int nt = 0; nt < 8; ++nt)
#pragma unroll
            for (int j = 0; j < 4; ++j) sacc[nt][j] = 0.f;
#pragma unroll
        for (int ks = 0; ks < 4; ++ks) {
#pragma unroll
            for (int nt = 0; nt < 8; ++nt) {
                const uint4 f = *(const uint4*)(bK + ks * 1024 + (8 * nt + g) * 16 + t * 4);
                mma_bf16(sacc[nt], qh[ks], f.x, f.y);
                mma_bf16(sacc[nt], qh[ks], f.z, f.w);
                mma_bf16(sacc[nt], ql[ks], f.x, f.y);
            }
        }

        // ---- online softmax ----
        float mt0 = -1e30f, mt1 = -1e30f;
#pragma unroll
        for (int nt = 0; nt < 8; ++nt) {
            const float b0 = bB[8 * nt + 2 * t];
            const float b1 = bB[8 * nt + 2 * t + 1];
            sacc[nt][0] = fmaf(sacc[nt][0], 0.125f, b0);
            sacc[nt][1] = fmaf(sacc[nt][1], 0.125f, b1);
            sacc[nt][2] = fmaf(sacc[nt][2], 0.125f, b0);
            sacc[nt][3] = fmaf(sacc[nt][3], 0.125f, b1);
            mt0 = fmaxf(mt0, fmaxf(sacc[nt][0], sacc[nt][1]));
            mt1 = fmaxf(mt1, fmaxf(sacc[nt][2], sacc[nt][3]));
        }
        mt0 = fmaxf(mt0, __shfl_xor_sync(0xffffffffu, mt0, 1));
        mt0 = fmaxf(mt0, __shfl_xor_sync(0xffffffffu, mt0, 2));
        mt1 = fmaxf(mt1, __shfl_xor_sync(0xffffffffu, mt1, 1));
        mt1 = fmaxf(mt1, __shfl_xor_sync(0xffffffffu, mt1, 2));

        const float mn0 = fmaxf(m0, mt0);
        const float mn1 = fmaxf(m1, mt1);
        const float al0 = fast_exp(m0 - mn0);
        const float al1 = fast_exp(m1 - mn1);
        m0 = mn0; m1 = mn1;

        float rs0 = 0.f, rs1 = 0.f;
        uint32_t ph[8][2], pl[8][2];
#pragma unroll
        for (int nt = 0; nt < 8; ++nt) {
            const float p0 = fast_exp(sacc[nt][0] - mn0);
            const float p1 = fast_exp(sacc[nt][1] - mn0);
            const float p2 = fast_exp(sacc[nt][2] - mn1);
            const float p3 = fast_exp(sacc[nt][3] - mn1);
            rs0 += p0 + p1;
            rs1 += p2 + p3;
            split2(p0, p1, ph[nt][0], pl[nt][0]);
            split2(p2, p3, ph[nt][1], pl[nt][1]);
        }
        rs0 += __shfl_xor_sync(0xffffffffu, rs0, 1);
        rs0 += __shfl_xor_sync(0xffffffffu, rs0, 2);
        rs1 += __shfl_xor_sync(0xffffffffu, rs1, 1);
        rs1 += __shfl_xor_sync(0xffffffffu, rs1, 2);
        l0 = l0 * al0 + rs0;
        l1 = l1 * al1 + rs1;
#pragma unroll
        for (int ndt = 0; ndt < 8; ++ndt) {
            o[ndt][0] *= al0; o[ndt][1] *= al0;
            o[ndt][2] *= al1; o[ndt][3] *= al1;
        }

        // ---- O += P V (bf16x3) ----
#pragma unroll
        for (int kp = 0; kp < 4; ++kp) {
            const uint32_t ah[4]  = { ph[2 * kp][0], ph[2 * kp][1], ph[2 * kp + 1][0], ph[2 * kp + 1][1] };
            const uint32_t apl[4] = { pl[2 * kp][0], pl[2 * kp][1], pl[2 * kp + 1][0], pl[2 * kp + 1][1] };
#pragma unroll
            for (int ndt = 0; ndt < 8; ++ndt) {
                const uint4 f = *(const uint4*)(bV + kp * 1024 + (8 * ndt + g) * 16 + t * 4);
                mma_bf16(o[ndt], ah, f.x, f.y);
                mma_bf16(o[ndt], ah, f.z, f.w);
                mma_bf16(o[ndt], apl, f.x, f.y);
            }
        }
        __syncthreads();
    }

    // ---- epilogue ----
    const float inv0 = 1.0f / l0;
    const float inv1 = 1.0f / l1;
    const int row0 = b * Ts + qt * 64 + warp * 16 + g;
    float* op = O + (size_t)row0 * Dd + h * HD;
#pragma unroll
    for (int ndt = 0; ndt < 8; ++ndt) {
        float2 lo, hi;
        lo.x = o[ndt][0] * inv0; lo.y = o[ndt][1] * inv0;
        hi.x = o[ndt][2] * inv1; hi.y = o[ndt][3] * inv1;
        *(float2*)(op + ndt * 8 + 2 * t) = lo;
        *(float2*)(op + (size_t)8 * Dd + ndt * 8 + 2 * t) = hi;
    }
}

// ===========================================================================
extern "C" void kernel_launch(void* const* d_in, const int* in_sizes, int n_in,
                              void* d_out, int out_size)
{
    const float* x     = (const float*)d_in[0];
    const float* eng   = (const float*)d_in[1];
    const void*  mask  = (const void*)d_in[2];
    const float* qkv_w = (const float*)d_in[3];
    const float* qkv_b = (const float*)d_in[4];
    const float* out_w = (const float*)d_in[5];
    const float* out_b = (const float*)d_in[6];
    float* out = (float*)d_out;

    float* qkv = nullptr;
    float* o   = nullptr;
    cudaGetSymbolAddress((void**)&qkv, g_qkv);
    cudaGetSymbolAddress((void**)&o,   g_o);

    cudaFuncSetAttribute(tf32_mma_gemm,
                         cudaFuncAttributeMaxDynamicSharedMemorySize, GEMM_SMEM_BYTES);
    cudaFuncSetAttribute(attn_bf16_kernel,
                         cudaFuncAttributeMaxDynamicSharedMemorySize, ATTN_SMEM_BYTES);

    // 0) mask dtype detection + per-key bias precompute
    detect_mask_kernel<<<1, 256>>>((const unsigned char*)mask);
    bias_kernel<<<(Bb * Ts + 255) / 256, 256>>>(eng, mask);

    // 1) QKV projection (tf32 mma.sync)
    dim3 g1(QKV_N / 128, M_ROWS / 128);
    tf32_mma_gemm<<<g1, 256, GEMM_SMEM_BYTES>>>(x, qkv_w, qkv_b, qkv, Dd, QKV_N);

    // 1b) split + repack K/V into fragment-ready bf16 layout
    dim3 gc(32, Hh, Bb);
    convert_kv_kernel<<<gc, 256>>>(qkv);

    // 2) attention (bf16x3 tensor-core flash on precomputed fragments)
    dim3 g2(Ts / 64, Hh, Bb);
    attn_bf16_kernel<<<g2, 128, ATTN_SMEM_BYTES>>>(qkv, o);

    // 3) output projection (tf32 mma.sync)
    dim3 g3(Dd / 128, M_ROWS / 128);
    tf32_mma_gemm<<<g3, 256, GEMM_SMEM_BYTES>>>(o, out_w, out_b, out, Dd, Dd);
}

// round 7
// speedup vs baseline: 4.5274x; 1.1519x over previous
#include <cuda_runtime.h>
#include <cuda_bf16.h>
#include <math.h>
#include <stdint.h>

// Problem constants
#define Bb 4
#define Ts 2048
#define Dd 1024
#define Hh 16
#define HD 64
#define M_ROWS 8192
#define QKV_N 3072

// Scratch (device globals: allocation-free)
__device__ float g_qkv[(size_t)M_ROWS * QKV_N];   // [B*T, 3D]
__device__ float g_o[(size_t)M_ROWS * Dd];        // [B*T, D]
__device__ float g_bias[Bb * Ts];                 // per-key additive bias
__device__ int   g_maskMode;                      // 0=uint8, 1=int32, 2=float32
// Fragment-ready split-bf16 K and V (see round 6)
__device__ uint32_t g_K[(size_t)Bb * Hh * 32 * 4096];
__device__ uint32_t g_V[(size_t)Bb * Hh * 32 * 4096];
// Fragment-ready tf32 packs for GEMM operands
__device__ uint32_t g_xp[(size_t)M_ROWS * Dd];    // x packed (A-layout)
__device__ uint32_t g_op[(size_t)M_ROWS * Dd];    // attention-out packed (A-layout)
__device__ uint32_t g_wq[(size_t)QKV_N * Dd];     // qkv_w packed (B-layout)
__device__ uint32_t g_wo[(size_t)Dd * Dd];        // out_w packed (B-layout)

// ===========================================================================
// helpers
// ===========================================================================
__device__ __forceinline__ uint32_t f2tf32(float f) {
    uint32_t u;
    asm("cvt.rna.tf32.f32 %0, %1;" : "=r"(u) : "f"(f));
    return u;
}

__device__ __forceinline__ void mma_tf32(float* d, const uint32_t* a, uint32_t b0, uint32_t b1) {
    asm volatile(
        "mma.sync.aligned.m16n8k8.row.col.f32.tf32.tf32.f32 "
        "{%0,%1,%2,%3}, {%4,%5,%6,%7}, {%8,%9}, {%0,%1,%2,%3};\n"
        : "+f"(d[0]), "+f"(d[1]), "+f"(d[2]), "+f"(d[3])
        : "r"(a[0]), "r"(a[1]), "r"(a[2]), "r"(a[3]), "r"(b0), "r"(b1));
}

__device__ __forceinline__ void mma_bf16(float* c, const uint32_t* a, uint32_t b0, uint32_t b1) {
    asm volatile(
        "mma.sync.aligned.m16n8k16.row.col.f32.bf16.bf16.f32 "
        "{%0,%1,%2,%3}, {%4,%5,%6,%7}, {%8,%9}, {%0,%1,%2,%3};\n"
        : "+f"(c[0]), "+f"(c[1]), "+f"(c[2]), "+f"(c[3])
        : "r"(a[0]), "r"(a[1]), "r"(a[2]), "r"(a[3]), "r"(b0), "r"(b1));
}

__device__ __forceinline__ void split2(float x, float y, uint32_t& hi, uint32_t& lo) {
    __nv_bfloat16 hx = __float2bfloat16_rn(x);
    __nv_bfloat16 hy = __float2bfloat16_rn(y);
    __nv_bfloat16 lx = __float2bfloat16_rn(x - __bfloat162float(hx));
    __nv_bfloat16 ly = __float2bfloat16_rn(y - __bfloat162float(hy));
    __nv_bfloat162 h2 = __halves2bfloat162(hx, hy);
    __nv_bfloat162 l2 = __halves2bfloat162(lx, ly);
    hi = *(uint32_t*)&h2;
    lo = *(uint32_t*)&l2;
}

__device__ __forceinline__ float fast_exp(float x) {
    x = fmaxf(x, -87.0f);
    const float y  = x * 1.4426950408889634f;
    const float zf = y + 12582912.0f;
    const float f  = y - (zf - 12582912.0f);
    const int   n  = (__float_as_int(zf) & 0x7FFFFF) - 0x400000;
    float p = 1.5403530e-4f;
    p = fmaf(p, f, 1.3333558e-3f);
    p = fmaf(p, f, 9.6181291e-3f);
    p = fmaf(p, f, 5.5504109e-2f);
    p = fmaf(p, f, 2.4022651e-1f);
    p = fmaf(p, f, 6.9314718e-1f);
    p = fmaf(p, f, 1.0f);
    return __int_as_float(__float_as_int(p) + (n << 23));
}

__device__ __forceinline__ uint32_t smem_u32(const void* p) {
    uint32_t a;
    asm("{ .reg .u64 t; cvta.to.shared.u64 t, %1; cvt.u32.u64 %0, t; }" : "=r"(a) : "l"(p));
    return a;
}
__device__ __forceinline__ void cp_async16(uint32_t dst, const void* src) {
    asm volatile("cp.async.cg.shared.global [%0], [%1], 16;" :: "r"(dst), "l"(src));
}
#define CP_COMMIT() asm volatile("cp.async.commit_group;" ::: "memory")
#define CP_WAIT(n)  asm volatile("cp.async.wait_group %0;" :: "n"(n) : "memory")

// ===========================================================================
// Mask dtype detection + bias precompute
// ===========================================================================
__global__ void detect_mask_kernel(const unsigned char* __restrict__ mask)
{
    __shared__ unsigned int orr[4][256];
    const int tid = threadIdx.x;
    unsigned int o0 = 0, o1 = 0, o2 = 0, o3 = 0;
    for (int i = tid * 4; i < Bb * Ts; i += 256 * 4) {
        o0 |= mask[i + 0]; o1 |= mask[i + 1]; o2 |= mask[i + 2]; o3 |= mask[i + 3];
    }
    orr[0][tid] = o0; orr[1][tid] = o1; orr[2][tid] = o2; orr[3][tid] = o3;
    __syncthreads();
    for (int s = 128; s; s >>= 1) {
        if (tid < s) {
            orr[0][tid] |= orr[0][tid + s];
            orr[1][tid] |= orr[1][tid + s];
            orr[2][tid] |= orr[2][tid + s];
            orr[3][tid] |= orr[3][tid + s];
        }
        __syncthreads();
    }
    if (tid == 0) {
        unsigned int l0 = orr[0][0], l1 = orr[1][0], l2 = orr[2][0], l3 = orr[3][0];
        int mode;
        if ((l1 | l2 | l3) == 0u) mode = 1;
        else if ((l0 | l1) == 0u && (l2 | l3) != 0u) mode = 2;
        else mode = 0;
        g_maskMode = mode;
    }
}

__global__ void bias_kernel(const float* __restrict__ eng, const void* __restrict__ mask)
{
    const int kk = blockIdx.x * 256 + threadIdx.x;
    if (kk >= Bb * Ts) return;
    const int mode = g_maskMode;
    bool m;
    if (mode == 1)      m = ((const int*)mask)[kk] != 0;
    else if (mode == 2) m = ((const float*)mask)[kk] != 0.f;
    else                m = ((const unsigned char*)mask)[kk] != 0;
    g_bias[kk] = m ? -1e9f : logf(fmaxf(eng[kk], 1e-6f));
}

// ===========================================================================
// Fragment-ready tf32 packing.
// A-layout quad (lane = 4g+t): {A[16R+g][8S+t], A[16R+8+g][8S+t],
//                               A[16R+g][8S+t+4], A[16R+8+g][8S+t+4]}
// B-layout quad: {W[16C+g][8S+t], W[16C+g][8S+t+4],
//                 W[16C+8+g][8S+t], W[16C+8+g][8S+t+4]}
// ===========================================================================
__global__ void __launch_bounds__(256)
pack_a_kernel(const float* __restrict__ src, uint32_t* __restrict__ dst, int M, int K)
{
    const int K8 = K >> 3;
    const int total = (M >> 4) * K8 * 32;
    for (int q = blockIdx.x * 256 + threadIdx.x; q < total; q += gridDim.x * 256) {
        const int lane = q & 31;
        const int rs = q >> 5;
        const int S = rs % K8;
        const int R = rs / K8;
        const int g = lane >> 2, t = lane & 3;
        const float* p = src + (size_t)(R * 16 + g) * K + S * 8 + t;
        uint4 w;
        w.x = f2tf32(p[0]);
        w.y = f2tf32(p[(size_t)8 * K]);
        w.z = f2tf32(p[4]);
        w.w = f2tf32(p[(size_t)8 * K + 4]);
        ((uint4*)dst)[q] = w;
    }
}

__global__ void __launch_bounds__(256)
pack_b_kernel(const float* __restrict__ src, uint32_t* __restrict__ dst, int N, int K)
{
    const int K8 = K >> 3;
    const int total = (N >> 4) * K8 * 32;
    for (int q = blockIdx.x * 256 + threadIdx.x; q < total; q += gridDim.x * 256) {
        const int lane = q & 31;
        const int cs = q >> 5;
        const int S = cs % K8;
        const int C = cs / K8;
        const int g = lane >> 2, t = lane & 3;
        const float* p = src + (size_t)(C * 16 + g) * K + S * 8 + t;
        uint4 w;
        w.x = f2tf32(p[0]);
        w.y = f2tf32(p[4]);
        w.z = f2tf32(p[(size_t)8 * K]);
        w.w = f2tf32(p[(size_t)8 * K + 4]);
        ((uint4*)dst)[q] = w;
    }
}

// ===========================================================================
// tf32 GEMM on packed operands. C[M,N] = A@W^T + bias.
// 128x128 tile, BK=32, cp.async double-buffered, LDS.128 fragment loads.
// ===========================================================================
#define GP_SMEM_BYTES (4 * 16384)

__global__ void __launch_bounds__(256)
tf32_gemm_packed(const uint32_t* __restrict__ Ap, const uint32_t* __restrict__ Bp,
                 const float* __restrict__ bias, float* __restrict__ C,
                 int K, int ldc)
{
    extern __shared__ uint32_t ps[];
    uint32_t* sA = ps;            // [2][4096]
    uint32_t* sB = ps + 8192;     // [2][4096]
    const uint32_t sAaddr = smem_u32(sA);
    const uint32_t sBaddr = smem_u32(sB);

    const int tid  = threadIdx.x;
    const int wid  = tid >> 5;
    const int lane = tid & 31;
    const int g = lane >> 2, t = lane & 3;
    const int wm = wid & 3;
    const int wn = wid >> 2;
    const int bm = blockIdx.y * 128;
    const int bn = blockIdx.x * 128;
    const int K8 = K >> 3;
    const int Rb = bm >> 4;
    const int Cb = bn >> 4;

    float acc[2][8][4];
#pragma unroll
    for (int mi = 0; mi < 2; ++mi)
#pragma unroll
        for (int ni = 0; ni < 8; ++ni)
#pragma unroll
            for (int r = 0; r < 4; ++r) acc[mi][ni][r] = 0.f;

    auto issue = [&](int buf, int kt) {
        const int Sb = kt * 4;
#pragma unroll
        for (int i = 0; i < 4; ++i) {
            const int l  = tid + 256 * i;        // 0..1023
            const int lR = l >> 7;
            const int lS = (l >> 5) & 3;
            const int ln = l & 31;
            cp_async16(sAaddr + buf * 16384 + l * 16,
                       Ap + (((size_t)(Rb + lR) * K8 + Sb + lS) * 32 + ln) * 4);
            cp_async16(sBaddr + buf * 16384 + l * 16,
                       Bp + (((size_t)(Cb + lR) * K8 + Sb + lS) * 32 + ln) * 4);
        }
    };

    const int nChunks = K >> 5;
    issue(0, 0);
    CP_COMMIT();

    for (int kt = 0; kt < nChunks; ++kt) {
        const int buf = kt & 1;
        if (kt + 1 < nChunks) {
            issue(buf ^ 1, kt + 1);
            CP_COMMIT();
            CP_WAIT(1);
        } else {
            CP_WAIT(0);
        }
        __syncthreads();

        const uint32_t* bufA = sA + buf * 4096;
        const uint32_t* bufB = sB + buf * 4096;
#pragma unroll
        for (int ks = 0; ks < 4; ++ks) {
            const uint4 fa0 = *(const uint4*)(bufA + ((((wm * 2 + 0) << 7) | (ks << 5) | lane) << 2));
            const uint4 fa1 = *(const uint4*)(bufA + ((((wm * 2 + 1) << 7) | (ks << 5) | lane) << 2));
            const uint32_t af0[4] = { fa0.x, fa0.y, fa0.z, fa0.w };
            const uint32_t af1[4] = { fa1.x, fa1.y, fa1.z, fa1.w };
#pragma unroll
            for (int c2 = 0; c2 < 4; ++c2) {
                const uint4 fb = *(const uint4*)(bufB + ((((wn * 4 + c2) << 7) | (ks << 5) | lane) << 2));
                mma_tf32(acc[0][2 * c2 + 0], af0, fb.x, fb.y);
                mma_tf32(acc[0][2 * c2 + 1], af0, fb.z, fb.w);
                mma_tf32(acc[1][2 * c2 + 0], af1, fb.x, fb.y);
                mma_tf32(acc[1][2 * c2 + 1], af1, fb.z, fb.w);
            }
        }
        __syncthreads();
    }

    // epilogue: bias + store
#pragma unroll
    for (int mi = 0; mi < 2; ++mi) {
        const int row = bm + wm * 32 + mi * 16 + g;
#pragma unroll
        for (int ni = 0; ni < 8; ++ni) {
            const int col = bn + wn * 64 + ni * 8 + 2 * t;
            const float b0 = bias[col];
            const float b1 = bias[col + 1];
            float2 lo, hi;
            lo.x = acc[mi][ni][0] + b0; lo.y = acc[mi][ni][1] + b1;
            hi.x = acc[mi][ni][2] + b0; hi.y = acc[mi][ni][3] + b1;
            *(float2*)(C + (size_t)row * ldc + col) = lo;
            *(float2*)(C + (size_t)(row + 8) * ldc + col) = hi;
        }
    }
}

// ===========================================================================
// K/V split + fragment-ready repack (once per (b,h,kt))
// ===========================================================================
__global__ void __launch_bounds__(256)
convert_kv_kernel(const float* __restrict__ qkv)
{
    const int kt = blockIdx.x, h = blockIdx.y, b = blockIdx.z;
    const size_t tileBase = (((size_t)(b * Hh + h)) * 32 + kt) * 4096;
    const int tid = threadIdx.x;

#pragma unroll
    for (int i = 0; i < 4; ++i) {
        const int qi  = tid + 256 * i;
        const int t   = qi & 3;
        const int key = (qi >> 2) & 63;
        const int ks  = qi >> 8;
        const float* kp = qkv + (size_t)(b * Ts + kt * 64 + key) * QKV_N + Dd + h * HD + 16 * ks + 2 * t;
        const float2 v0 = *(const float2*)(kp);
        const float2 v1 = *(const float2*)(kp + 8);
        uint32_t h0, l0, h1, l1;
        split2(v0.x, v0.y, h0, l0);
        split2(v1.x, v1.y, h1, l1);
        uint4 w; w.x = h0; w.y = h1; w.z = l0; w.w = l1;
        *(uint4*)&g_K[tileBase + (size_t)qi * 4] = w;
    }
#pragma unroll
    for (int i = 0; i < 4; ++i) {
        const int qi  = tid + 256 * i;
        const int t   = qi & 3;
        const int d   = (qi >> 2) & 63;
        const int kp_ = qi >> 8;
        const float* vp = qkv + (size_t)(b * Ts + kt * 64 + 16 * kp_ + 2 * t) * QKV_N + 2 * Dd + h * HD + d;
        const float a0 = vp[0];
        const float a1 = vp[QKV_N];
        const float a2 = vp[8 * QKV_N];
        const float a3 = vp[9 * QKV_N];
        uint32_t h0, l0, h1, l1;
        split2(a0, a1, h0, l0);
        split2(a2, a3, h1, l1);
        uint4 w; w.x = h0; w.y = h1; w.z = l0; w.w = l1;
        *(uint4*)&g_V[tileBase + (size_t)qi * 4] = w;
    }
}

// ===========================================================================
// Tensor-core flash attention (unchanged from round 6)
// ===========================================================================
#define ATTN_SMEM_BYTES (2 * 16384 + 2 * 16384 + 2 * 256)

__global__ void __launch_bounds__(128, 3)
attn_bf16_kernel(const float* __restrict__ qkv, float* __restrict__ O)
{
    extern __shared__ uint32_t asmem[];
    uint32_t* sK = asmem;
    uint32_t* sV = asmem + 8192;
    float*    sBias = (float*)(asmem + 16384);

    const uint32_t sKaddr = smem_u32(sK);
    const uint32_t sVaddr = smem_u32(sV);
    const uint32_t sBaddr = smem_u32(sBias);

    const int qt = blockIdx.x;
    const int h  = blockIdx.y;
    const int b  = blockIdx.z;
    const int tid  = threadIdx.x;
    const int warp = tid >> 5;
    const int lane = tid & 31;
    const int g = lane >> 2, t = lane & 3;

    const size_t kvBase = ((size_t)(b * Hh + h)) * 32 * 4096;

    uint32_t qh[4][4], ql[4][4];
    {
        const float* q0 = qkv + (size_t)(b * Ts + qt * 64 + warp * 16 + g) * QKV_N + h * HD;
        const float* q1 = q0 + (size_t)8 * QKV_N;
#pragma unroll
        for (int ks = 0; ks < 4; ++ks) {
#pragma unroll
            for (int hf = 0; hf < 2; ++hf) {
                const int col = 16 * ks + 2 * t + 8 * hf;
                const float2 v0 = *(const float2*)(q0 + col);
                const float2 v1 = *(const float2*)(q1 + col);
                split2(v0.x, v0.y, qh[ks][2 * hf + 0], ql[ks][2 * hf + 0]);
                split2(v1.x, v1.y, qh[ks][2 * hf + 1], ql[ks][2 * hf + 1]);
            }
        }
    }

    float o[8][4];
#pragma unroll
    for (int i = 0; i < 8; ++i)
#pragma unroll
        for (int j = 0; j < 4; ++j) o[i][j] = 0.f;
    float m0 = -1e30f, m1 = -1e30f, l0 = 0.f, l1 = 0.f;

    auto issue = [&](int buf, int kt) {
        const uint32_t* srcK = g_K + kvBase + (size_t)kt * 4096 + tid * 4;
        const uint32_t* srcV = g_V + kvBase + (size_t)kt * 4096 + tid * 4;
        const uint32_t dK = sKaddr + buf * 16384 + tid * 16;
        const uint32_t dV = sVaddr + buf * 16384 + tid * 16;
#pragma unroll
        for (int i = 0; i < 8; ++i) {
            cp_async16(dK + i * 2048, srcK + i * 512);
            cp_async16(dV + i * 2048, srcV + i * 512);
        }
        if (tid < 16) cp_async16(sBaddr + buf * 256 + tid * 16, g_bias + b * Ts + kt * 64 + tid * 4);
    };

    issue(0, 0);
    CP_COMMIT();

    for (int kt = 0; kt < Ts / 64; ++kt) {
        const int buf = kt & 1;
        if (kt + 1 < Ts / 64) {
            issue(buf ^ 1, kt + 1);
            CP_COMMIT();
            CP_WAIT(1);
        } else {
            CP_WAIT(0);
        }
        __syncthreads();

        const uint32_t* bK = sK + buf * 4096;
        const uint32_t* bV = sV + buf * 4096;
        const float* bB = sBias + buf * 64;

        float sacc[8][4];
#pragma unroll
        for (int nt = 0; nt < 8; ++nt)
#pragma unroll
            for (int j = 0; j < 4; ++j) sacc[nt][j] = 0.f;
#pragma unroll
        for (int ks = 0; ks < 4; ++ks) {
#pragma unroll
            for (int nt = 0; nt < 8; ++nt) {
                const uint4 f = *(const uint4*)(bK + ks * 1024 + (8 * nt + g) * 16 + t * 4);
                mma_bf16(sacc[nt], qh[ks], f.x, f.y);
                mma_bf16(sacc[nt], qh[ks], f.z, f.w);
                mma_bf16(sacc[nt], ql[ks], f.x, f.y);
            }
        }

        float mt0 = -1e30f, mt1 = -1e30f;
#pragma unroll
        for (int nt = 0; nt < 8; ++nt) {
            const float b0 = bB[8 * nt + 2 * t];
            const float b1 = bB[8 * nt + 2 * t + 1];
            sacc[nt][0] = fmaf(sacc[nt][0], 0.125f, b0);
            sacc[nt][1] = fmaf(sacc[nt][1], 0.125f, b1);
            sacc[nt][2] = fmaf(sacc[nt][2], 0.125f, b0);
            sacc[nt][3] = fmaf(sacc[nt][3], 0.125f, b1);
            mt0 = fmaxf(mt0, fmaxf(sacc[nt][0], sacc[nt][1]));
            mt1 = fmaxf(mt1, fmaxf(sacc[nt][2], sacc[nt][3]));
        }
        mt0 = fmaxf(mt0, __shfl_xor_sync(0xffffffffu, mt0, 1));
        mt0 = fmaxf(mt0, __shfl_xor_sync(0xffffffffu, mt0, 2));
        mt1 = fmaxf(mt1, __shfl_xor_sync(0xffffffffu, mt1, 1));
        mt1 = fmaxf(mt1, __shfl_xor_sync(0xffffffffu, mt1, 2));

        const float mn0 = fmaxf(m0, mt0);
        const float mn1 = fmaxf(m1, mt1);
        const float al0 = fast_exp(m0 - mn0);
        const float al1 = fast_exp(m1 - mn1);
        m0 = mn0; m1 = mn1;

        float rs0 = 0.f, rs1 = 0.f;
        uint32_t ph[8][2], pl[8][2];
#pragma unroll
        for (int nt = 0; nt < 8; ++nt) {
            const float p0 = fast_exp(sacc[nt][0] - mn0);
            const float p1 = fast_exp(sacc[nt][1] - mn0);
            const float p2 = fast_exp(sacc[nt][2] - mn1);
            const float p3 = fast_exp(sacc[nt][3] - mn1);
            rs0 += p0 + p1;
            rs1 += p2 + p3;
            split2(p0, p1, ph[nt][0], pl[nt][0]);
            split2(p2, p3, ph[nt][1], pl[nt][1]);
        }
        rs0 += __shfl_xor_sync(0xffffffffu, rs0, 1);
        rs0 += __shfl_xor_sync(0xffffffffu, rs0, 2);
        rs1 += __shfl_xor_sync(0xffffffffu, rs1, 1);
        rs1 += __shfl_xor_sync(0xffffffffu, rs1, 2);
        l0 = l0 * al0 + rs0;
        l1 = l1 * al1 + rs1;
#pragma unroll
        for (int ndt = 0; ndt < 8; ++ndt) {
            o[ndt][0] *= al0; o[ndt][1] *= al0;
            o[ndt][2] *= al1; o[ndt][3] *= al1;
        }

#pragma unroll
        for (int kp = 0; kp < 4; ++kp) {
            const uint32_t ah[4]  = { ph[2 * kp][0], ph[2 * kp][1], ph[2 * kp + 1][0], ph[2 * kp + 1][1] };
            const uint32_t apl[4] = { pl[2 * kp][0], pl[2 * kp][1], pl[2 * kp + 1][0], pl[2 * kp + 1][1] };
#pragma unroll
            for (int ndt = 0; ndt < 8; ++ndt) {
                const uint4 f = *(const uint4*)(bV + kp * 1024 + (8 * ndt + g) * 16 + t * 4);
                mma_bf16(o[ndt], ah, f.x, f.y);
                mma_bf16(o[ndt], ah, f.z, f.w);
                mma_bf16(o[ndt], apl, f.x, f.y);
            }
        }
        __syncthreads();
    }

    const float inv0 = 1.0f / l0;
    const float inv1 = 1.0f / l1;
    const int row0 = b * Ts + qt * 64 + warp * 16 + g;
    float* op = O + (size_t)row0 * Dd + h * HD;
#pragma unroll
    for (int ndt = 0; ndt < 8; ++ndt) {
        float2 lo, hi;
        lo.x = o[ndt][0] * inv0; lo.y = o[ndt][1] * inv0;
        hi.x = o[ndt][2] * inv1; hi.y = o[ndt][3] * inv1;
        *(float2*)(op + ndt * 8 + 2 * t) = lo;
        *(float2*)(op + (size_t)8 * Dd + ndt * 8 + 2 * t) = hi;
    }
}

// ===========================================================================
extern "C" void kernel_launch(void* const* d_in, const int* in_sizes, int n_in,
                              void* d_out, int out_size)
{
    const float* x     = (const float*)d_in[0];
    const float* eng   = (const float*)d_in[1];
    const void*  mask  = (const void*)d_in[2];
    const float* qkv_w = (const float*)d_in[3];
    const float* qkv_b = (const float*)d_in[4];
    const float* out_w = (const float*)d_in[5];
    const float* out_b = (const float*)d_in[6];
    float* out = (float*)d_out;

    float *qkv = nullptr, *o = nullptr;
    uint32_t *xp = nullptr, *op = nullptr, *wq = nullptr, *wo = nullptr;
    cudaGetSymbolAddress((void**)&qkv, g_qkv);
    cudaGetSymbolAddress((void**)&o,   g_o);
    cudaGetSymbolAddress((void**)&xp,  g_xp);
    cudaGetSymbolAddress((void**)&op,  g_op);
    cudaGetSymbolAddress((void**)&wq,  g_wq);
    cudaGetSymbolAddress((void**)&wo,  g_wo);

    cudaFuncSetAttribute(tf32_gemm_packed,
                         cudaFuncAttributeMaxDynamicSharedMemorySize, GP_SMEM_BYTES);
    cudaFuncSetAttribute(attn_bf16_kernel,
                         cudaFuncAttributeMaxDynamicSharedMemorySize, ATTN_SMEM_BYTES);

    // 0) mask dtype detection + per-key bias precompute
    detect_mask_kernel<<<1, 256>>>((const unsigned char*)mask);
    bias_kernel<<<(Bb * Ts + 255) / 256, 256>>>(eng, mask);

    // 0b) pack x and weights into fragment-ready tf32 layouts
    pack_a_kernel<<<2048, 256>>>(x, xp, M_ROWS, Dd);
    pack_b_kernel<<<1024, 256>>>(qkv_w, wq, QKV_N, Dd);
    pack_b_kernel<<<512, 256>>>(out_w, wo, Dd, Dd);

    // 1) QKV projection (packed tf32 mma.sync)
    dim3 g1(QKV_N / 128, M_ROWS / 128);
    tf32_gemm_packed<<<g1, 256, GP_SMEM_BYTES>>>(xp, wq, qkv_b, qkv, Dd, QKV_N);

    // 1b) split + repack K/V into fragment-ready bf16 layout
    dim3 gc(32, Hh, Bb);
    convert_kv_kernel<<<gc, 256>>>(qkv);

    // 2) attention (bf16x3 tensor-core flash on precomputed fragments)
    dim3 g2(Ts / 64, Hh, Bb);
    attn_bf16_kernel<<<g2, 128, ATTN_SMEM_BYTES>>>(qkv, o);

    // 2b) pack attention output for the out-projection
    pack_a_kernel<<<2048, 256>>>(o, op, M_ROWS, Dd);

    // 3) output projection (packed tf32 mma.sync)
    dim3 g3(Dd / 128, M_ROWS / 128);
    tf32_gemm_packed<<<g3, 256, GP_SMEM_BYTES>>>(op, wo, out_b, out, Dd, Dd);
}

// round 8
// speedup vs baseline: 5.1066x; 1.1279x over previous
#include <cuda_runtime.h>
#include <cuda_bf16.h>
#include <math.h>
#include <stdint.h>

// Problem constants
#define Bb 4
#define Ts 2048
#define Dd 1024
#define Hh 16
#define HD 64
#define M_ROWS 8192
#define QKV_N 3072

// Scratch (device globals: allocation-free)
__device__ float g_qkv[(size_t)M_ROWS * QKV_N];   // [B*T, 3D]
__device__ float g_bias[Bb * Ts];                 // per-key log2-domain bias
__device__ int   g_maskMode;                      // 0=uint8, 1=int32, 2=float32
// Fragment-ready split-bf16 K and V
__device__ uint32_t g_K[(size_t)Bb * Hh * 32 * 4096];
__device__ uint32_t g_V[(size_t)Bb * Hh * 32 * 4096];
// Fragment-ready tf32 packs for GEMM operands
__device__ uint32_t g_xp[(size_t)M_ROWS * Dd];    // x packed (A-layout)
__device__ uint32_t g_op[(size_t)M_ROWS * Dd];    // attention-out packed (A-layout)
__device__ uint32_t g_wq[(size_t)QKV_N * Dd];     // qkv_w packed (B-layout)
__device__ uint32_t g_wo[(size_t)Dd * Dd];        // out_w packed (B-layout)

// ===========================================================================
// helpers
// ===========================================================================
__device__ __forceinline__ uint32_t f2tf32(float f) {
    uint32_t u;
    asm("cvt.rna.tf32.f32 %0, %1;" : "=r"(u) : "f"(f));
    return u;
}
__device__ __forceinline__ float ex2f(float x) {
    float r;
    asm("ex2.approx.ftz.f32 %0, %1;" : "=f"(r) : "f"(x));
    return r;
}

__device__ __forceinline__ void mma_tf32(float* d, const uint32_t* a, uint32_t b0, uint32_t b1) {
    asm volatile(
        "mma.sync.aligned.m16n8k8.row.col.f32.tf32.tf32.f32 "
        "{%0,%1,%2,%3}, {%4,%5,%6,%7}, {%8,%9}, {%0,%1,%2,%3};\n"
        : "+f"(d[0]), "+f"(d[1]), "+f"(d[2]), "+f"(d[3])
        : "r"(a[0]), "r"(a[1]), "r"(a[2]), "r"(a[3]), "r"(b0), "r"(b1));
}

__device__ __forceinline__ void mma_bf16(float* c, const uint32_t* a, uint32_t b0, uint32_t b1) {
    asm volatile(
        "mma.sync.aligned.m16n8k16.row.col.f32.bf16.bf16.f32 "
        "{%0,%1,%2,%3}, {%4,%5,%6,%7}, {%8,%9}, {%0,%1,%2,%3};\n"
        : "+f"(c[0]), "+f"(c[1]), "+f"(c[2]), "+f"(c[3])
        : "r"(a[0]), "r"(a[1]), "r"(a[2]), "r"(a[3]), "r"(b0), "r"(b1));
}

__device__ __forceinline__ void split2(float x, float y, uint32_t& hi, uint32_t& lo) {
    __nv_bfloat16 hx = __float2bfloat16_rn(x);
    __nv_bfloat16 hy = __float2bfloat16_rn(y);
    __nv_bfloat16 lx = __float2bfloat16_rn(x - __bfloat162float(hx));
    __nv_bfloat16 ly = __float2bfloat16_rn(y - __bfloat162float(hy));
    __nv_bfloat162 h2 = __halves2bfloat162(hx, hy);
    __nv_bfloat162 l2 = __halves2bfloat162(lx, ly);
    hi = *(uint32_t*)&h2;
    lo = *(uint32_t*)&l2;
}

__device__ __forceinline__ uint32_t smem_u32(const void* p) {
    uint32_t a;
    asm("{ .reg .u64 t; cvta.to.shared.u64 t, %1; cvt.u32.u64 %0, t; }" : "=r"(a) : "l"(p));
    return a;
}
__device__ __forceinline__ void cp_async16(uint32_t dst, const void* src) {
    asm volatile("cp.async.cg.shared.global [%0], [%1], 16;" :: "r"(dst), "l"(src));
}
#define CP_COMMIT() asm volatile("cp.async.commit_group;" ::: "memory")
#define CP_WAIT(n)  asm volatile("cp.async.wait_group %0;" :: "n"(n) : "memory")

// ===========================================================================
// Mask dtype detection + bias precompute (log2 domain)
// ===========================================================================
__global__ void detect_mask_kernel(const unsigned char* __restrict__ mask)
{
    __shared__ unsigned int orr[4][256];
    const int tid = threadIdx.x;
    unsigned int o0 = 0, o1 = 0, o2 = 0, o3 = 0;
    for (int i = tid * 4; i < Bb * Ts; i += 256 * 4) {
        o0 |= mask[i + 0]; o1 |= mask[i + 1]; o2 |= mask[i + 2]; o3 |= mask[i + 3];
    }
    orr[0][tid] = o0; orr[1][tid] = o1; orr[2][tid] = o2; orr[3][tid] = o3;
    __syncthreads();
    for (int s = 128; s; s >>= 1) {
        if (tid < s) {
            orr[0][tid] |= orr[0][tid + s];
            orr[1][tid] |= orr[1][tid + s];
            orr[2][tid] |= orr[2][tid + s];
            orr[3][tid] |= orr[3][tid + s];
        }
        __syncthreads();
    }
    if (tid == 0) {
        unsigned int l0 = orr[0][0], l1 = orr[1][0], l2 = orr[2][0], l3 = orr[3][0];
        int mode;
        if ((l1 | l2 | l3) == 0u) mode = 1;
        else if ((l0 | l1) == 0u && (l2 | l3) != 0u) mode = 2;
        else mode = 0;
        g_maskMode = mode;
    }
}

__global__ void bias_kernel(const float* __restrict__ eng, const void* __restrict__ mask)
{
    const int kk = blockIdx.x * 256 + threadIdx.x;
    if (kk >= Bb * Ts) return;
    const int mode = g_maskMode;
    bool m;
    if (mode == 1)      m = ((const int*)mask)[kk] != 0;
    else if (mode == 2) m = ((const float*)mask)[kk] != 0.f;
    else                m = ((const unsigned char*)mask)[kk] != 0;
    // log2 domain: softmax weight = exp2(S*scale*log2e + log2(eng))
    g_bias[kk] = m ? -1e9f : log2f(fmaxf(eng[kk], 1e-6f));
}

// ===========================================================================
// Fragment-ready tf32 packing (A- and B-layouts)
// ===========================================================================
__global__ void __launch_bounds__(256)
pack_a_kernel(const float* __restrict__ src, uint32_t* __restrict__ dst, int M, int K)
{
    const int K8 = K >> 3;
    const int total = (M >> 4) * K8 * 32;
    for (int q = blockIdx.x * 256 + threadIdx.x; q < total; q += gridDim.x * 256) {
        const int lane = q & 31;
        const int rs = q >> 5;
        const int S = rs % K8;
        const int R = rs / K8;
        const int g = lane >> 2, t = lane & 3;
        const float* p = src + (size_t)(R * 16 + g) * K + S * 8 + t;
        uint4 w;
        w.x = f2tf32(p[0]);
        w.y = f2tf32(p[(size_t)8 * K]);
        w.z = f2tf32(p[4]);
        w.w = f2tf32(p[(size_t)8 * K + 4]);
        ((uint4*)dst)[q] = w;
    }
}

__global__ void __launch_bounds__(256)
pack_b_kernel(const float* __restrict__ src, uint32_t* __restrict__ dst, int N, int K)
{
    const int K8 = K >> 3;
    const int total = (N >> 4) * K8 * 32;
    for (int q = blockIdx.x * 256 + threadIdx.x; q < total; q += gridDim.x * 256) {
        const int lane = q & 31;
        const int cs = q >> 5;
        const int S = cs % K8;
        const int C = cs / K8;
        const int g = lane >> 2, t = lane & 3;
        const float* p = src + (size_t)(C * 16 + g) * K + S * 8 + t;
        uint4 w;
        w.x = f2tf32(p[0]);
        w.y = f2tf32(p[4]);
        w.z = f2tf32(p[(size_t)8 * K]);
        w.w = f2tf32(p[(size_t)8 * K + 4]);
        ((uint4*)dst)[q] = w;
    }
}

// ===========================================================================
// tf32 GEMM on packed operands (unchanged from round 7)
// ===========================================================================
#define GP_SMEM_BYTES (4 * 16384)

__global__ void __launch_bounds__(256)
tf32_gemm_packed(const uint32_t* __restrict__ Ap, const uint32_t* __restrict__ Bp,
                 const float* __restrict__ bias, float* __restrict__ C,
                 int K, int ldc)
{
    extern __shared__ uint32_t ps[];
    uint32_t* sA = ps;
    uint32_t* sB = ps + 8192;
    const uint32_t sAaddr = smem_u32(sA);
    const uint32_t sBaddr = smem_u32(sB);

    const int tid  = threadIdx.x;
    const int wid  = tid >> 5;
    const int lane = tid & 31;
    const int g = lane >> 2, t = lane & 3;
    const int wm = wid & 3;
    const int wn = wid >> 2;
    const int bm = blockIdx.y * 128;
    const int bn = blockIdx.x * 128;
    const int K8 = K >> 3;
    const int Rb = bm >> 4;
    const int Cb = bn >> 4;

    float acc[2][8][4];
#pragma unroll
    for (int mi = 0; mi < 2; ++mi)
#pragma unroll
        for (int ni = 0; ni < 8; ++ni)
#pragma unroll
            for (int r = 0; r < 4; ++r) acc[mi][ni][r] = 0.f;

    auto issue = [&](int buf, int kt) {
        const int Sb = kt * 4;
#pragma unroll
        for (int i = 0; i < 4; ++i) {
            const int l  = tid + 256 * i;
            const int lR = l >> 7;
            const int lS = (l >> 5) & 3;
            const int ln = l & 31;
            cp_async16(sAaddr + buf * 16384 + l * 16,
                       Ap + (((size_t)(Rb + lR) * K8 + Sb + lS) * 32 + ln) * 4);
            cp_async16(sBaddr + buf * 16384 + l * 16,
                       Bp + (((size_t)(Cb + lR) * K8 + Sb + lS) * 32 + ln) * 4);
        }
    };

    const int nChunks = K >> 5;
    issue(0, 0);
    CP_COMMIT();

    for (int kt = 0; kt < nChunks; ++kt) {
        const int buf = kt & 1;
        if (kt + 1 < nChunks) {
            issue(buf ^ 1, kt + 1);
            CP_COMMIT();
            CP_WAIT(1);
        } else {
            CP_WAIT(0);
        }
        __syncthreads();

        const uint32_t* bufA = sA + buf * 4096;
        const uint32_t* bufB = sB + buf * 4096;
#pragma unroll
        for (int ks = 0; ks < 4; ++ks) {
            const uint4 fa0 = *(const uint4*)(bufA + ((((wm * 2 + 0) << 7) | (ks << 5) | lane) << 2));
            const uint4 fa1 = *(const uint4*)(bufA + ((((wm * 2 + 1) << 7) | (ks << 5) | lane) << 2));
            const uint32_t af0[4] = { fa0.x, fa0.y, fa0.z, fa0.w };
            const uint32_t af1[4] = { fa1.x, fa1.y, fa1.z, fa1.w };
#pragma unroll
            for (int c2 = 0; c2 < 4; ++c2) {
                const uint4 fb = *(const uint4*)(bufB + ((((wn * 4 + c2) << 7) | (ks << 5) | lane) << 2));
                mma_tf32(acc[0][2 * c2 + 0], af0, fb.x, fb.y);
                mma_tf32(acc[0][2 * c2 + 1], af0, fb.z, fb.w);
                mma_tf32(acc[1][2 * c2 + 0], af1, fb.x, fb.y);
                mma_tf32(acc[1][2 * c2 + 1], af1, fb.z, fb.w);
            }
        }
        __syncthreads();
    }

#pragma unroll
    for (int mi = 0; mi < 2; ++mi) {
        const int row = bm + wm * 32 + mi * 16 + g;
#pragma unroll
        for (int ni = 0; ni < 8; ++ni) {
            const int col = bn + wn * 64 + ni * 8 + 2 * t;
            const float b0 = bias[col];
            const float b1 = bias[col + 1];
            float2 lo, hi;
            lo.x = acc[mi][ni][0] + b0; lo.y = acc[mi][ni][1] + b1;
            hi.x = acc[mi][ni][2] + b0; hi.y = acc[mi][ni][3] + b1;
            *(float2*)(C + (size_t)row * ldc + col) = lo;
            *(float2*)(C + (size_t)(row + 8) * ldc + col) = hi;
        }
    }
}

// ===========================================================================
// K/V split + fragment-ready repack (unchanged)
// ===========================================================================
__global__ void __launch_bounds__(256)
convert_kv_kernel(const float* __restrict__ qkv)
{
    const int kt = blockIdx.x, h = blockIdx.y, b = blockIdx.z;
    const size_t tileBase = (((size_t)(b * Hh + h)) * 32 + kt) * 4096;
    const int tid = threadIdx.x;

#pragma unroll
    for (int i = 0; i < 4; ++i) {
        const int qi  = tid + 256 * i;
        const int t   = qi & 3;
        const int key = (qi >> 2) & 63;
        const int ks  = qi >> 8;
        const float* kp = qkv + (size_t)(b * Ts + kt * 64 + key) * QKV_N + Dd + h * HD + 16 * ks + 2 * t;
        const float2 v0 = *(const float2*)(kp);
        const float2 v1 = *(const float2*)(kp + 8);
        uint32_t h0, l0, h1, l1;
        split2(v0.x, v0.y, h0, l0);
        split2(v1.x, v1.y, h1, l1);
        uint4 w; w.x = h0; w.y = h1; w.z = l0; w.w = l1;
        *(uint4*)&g_K[tileBase + (size_t)qi * 4] = w;
    }
#pragma unroll
    for (int i = 0; i < 4; ++i) {
        const int qi  = tid + 256 * i;
        const int t   = qi & 3;
        const int d   = (qi >> 2) & 63;
        const int kp_ = qi >> 8;
        const float* vp = qkv + (size_t)(b * Ts + kt * 64 + 16 * kp_ + 2 * t) * QKV_N + 2 * Dd + h * HD + d;
        const float a0 = vp[0];
        const float a1 = vp[QKV_N];
        const float a2 = vp[8 * QKV_N];
        const float a3 = vp[9 * QKV_N];
        uint32_t h0, l0, h1, l1;
        split2(a0, a1, h0, l0);
        split2(a2, a3, h1, l1);
        uint4 w; w.x = h0; w.y = h1; w.z = l0; w.w = l1;
        *(uint4*)&g_V[tileBase + (size_t)qi * 4] = w;
    }
}

// ===========================================================================
// Tensor-core flash attention: no-max softmax (MUFU ex2, log2-domain bias),
// fused packed-tf32 A-layout epilogue straight into g_op.
// ===========================================================================
#define ATTN_SMEM_BYTES (2 * 16384 + 2 * 16384 + 2 * 256)
#define C1 0.18033688011112042f   // 0.125 * log2(e)

__global__ void __launch_bounds__(128, 3)
attn_bf16_kernel(const float* __restrict__ qkv, uint32_t* __restrict__ Opacked)
{
    extern __shared__ uint32_t asmem[];
    uint32_t* sK = asmem;
    uint32_t* sV = asmem + 8192;
    float*    sBias = (float*)(asmem + 16384);

    const uint32_t sKaddr = smem_u32(sK);
    const uint32_t sVaddr = smem_u32(sV);
    const uint32_t sBaddr = smem_u32(sBias);

    const int qt = blockIdx.x;
    const int h  = blockIdx.y;
    const int b  = blockIdx.z;
    const int tid  = threadIdx.x;
    const int warp = tid >> 5;
    const int lane = tid & 31;
    const int g = lane >> 2, t = lane & 3;

    const size_t kvBase = ((size_t)(b * Hh + h)) * 32 * 4096;

    uint32_t qh[4][4], ql[4][4];
    {
        const float* q0 = qkv + (size_t)(b * Ts + qt * 64 + warp * 16 + g) * QKV_N + h * HD;
        const float* q1 = q0 + (size_t)8 * QKV_N;
#pragma unroll
        for (int ks = 0; ks < 4; ++ks) {
#pragma unroll
            for (int hf = 0; hf < 2; ++hf) {
                const int col = 16 * ks + 2 * t + 8 * hf;
                const float2 v0 = *(const float2*)(q0 + col);
                const float2 v1 = *(const float2*)(q1 + col);
                split2(v0.x, v0.y, qh[ks][2 * hf + 0], ql[ks][2 * hf + 0]);
                split2(v1.x, v1.y, qh[ks][2 * hf + 1], ql[ks][2 * hf + 1]);
            }
        }
    }

    float o[8][4];
#pragma unroll
    for (int i = 0; i < 8; ++i)
#pragma unroll
        for (int j = 0; j < 4; ++j) o[i][j] = 0.f;
    float l0 = 0.f, l1 = 0.f;

    auto issue = [&](int buf, int kt) {
        const uint32_t* srcK = g_K + kvBase + (size_t)kt * 4096 + tid * 4;
        const uint32_t* srcV = g_V + kvBase + (size_t)kt * 4096 + tid * 4;
        const uint32_t dK = sKaddr + buf * 16384 + tid * 16;
        const uint32_t dV = sVaddr + buf * 16384 + tid * 16;
#pragma unroll
        for (int i = 0; i < 8; ++i) {
            cp_async16(dK + i * 2048, srcK + i * 512);
            cp_async16(dV + i * 2048, srcV + i * 512);
        }
        if (tid < 16) cp_async16(sBaddr + buf * 256 + tid * 16, g_bias + b * Ts + kt * 64 + tid * 4);
    };

    issue(0, 0);
    CP_COMMIT();

    for (int kt = 0; kt < Ts / 64; ++kt) {
        const int buf = kt & 1;
        if (kt + 1 < Ts / 64) {
            issue(buf ^ 1, kt + 1);
            CP_COMMIT();
            CP_WAIT(1);
        } else {
            CP_WAIT(0);
        }
        __syncthreads();

        const uint32_t* bK = sK + buf * 4096;
        const uint32_t* bV = sV + buf * 4096;
        const float* bB = sBias + buf * 64;

        // ---- S = Q K^T (bf16x3) ----
        float sacc[8][4];
#pragma unroll
        for (int nt = 0; nt < 8; ++nt)
#pragma unroll
            for (int j = 0; j < 4; ++j) sacc[nt][j] = 0.f;
#pragma unroll
        for (int ks = 0; ks < 4; ++ks) {
#pragma unroll
            for (int nt = 0; nt < 8; ++nt) {
                const uint4 f = *(const uint4*)(bK + ks * 1024 + (8 * nt + g) * 16 + t * 4);
                mma_bf16(sacc[nt], qh[ks], f.x, f.y);
                mma_bf16(sacc[nt], qh[ks], f.z, f.w);
                mma_bf16(sacc[nt], ql[ks], f.x, f.y);
            }
        }

        // ---- softmax weights, no max subtraction: P = exp2(S*C1 + log2bias) ----
        float rs0 = 0.f, rs1 = 0.f;
        uint32_t ph[8][2], pl[8][2];
#pragma unroll
        for (int nt = 0; nt < 8; ++nt) {
            const float b0 = bB[8 * nt + 2 * t];
            const float b1 = bB[8 * nt + 2 * t + 1];
            const float p0 = ex2f(fmaf(sacc[nt][0], C1, b0));
            const float p1 = ex2f(fmaf(sacc[nt][1], C1, b1));
            const float p2 = ex2f(fmaf(sacc[nt][2], C1, b0));
            const float p3 = ex2f(fmaf(sacc[nt][3], C1, b1));
            rs0 += p0 + p1;
            rs1 += p2 + p3;
            split2(p0, p1, ph[nt][0], pl[nt][0]);
            split2(p2, p3, ph[nt][1], pl[nt][1]);
        }
        l0 += rs0;
        l1 += rs1;

        // ---- O += P V (bf16x3) ----
#pragma unroll
        for (int kp = 0; kp < 4; ++kp) {
            const uint32_t ah[4]  = { ph[2 * kp][0], ph[2 * kp][1], ph[2 * kp + 1][0], ph[2 * kp + 1][1] };
            const uint32_t apl[4] = { pl[2 * kp][0], pl[2 * kp][1], pl[2 * kp + 1][0], pl[2 * kp + 1][1] };
#pragma unroll
            for (int ndt = 0; ndt < 8; ++ndt) {
                const uint4 f = *(const uint4*)(bV + kp * 1024 + (8 * ndt + g) * 16 + t * 4);
                mma_bf16(o[ndt], ah, f.x, f.y);
                mma_bf16(o[ndt], ah, f.z, f.w);
                mma_bf16(o[ndt], apl, f.x, f.y);
            }
        }
        __syncthreads();
    }

    // ---- row sums across the 4 t-lanes ----
    l0 += __shfl_xor_sync(0xffffffffu, l0, 1);
    l0 += __shfl_xor_sync(0xffffffffu, l0, 2);
    l1 += __shfl_xor_sync(0xffffffffu, l1, 1);
    l1 += __shfl_xor_sync(0xffffffffu, l1, 2);
    const float inv0 = 1.0f / l0;
    const float inv1 = 1.0f / l1;

    // ---- fused epilogue: normalize + repack to tf32 A-layout quads ----
    // Thread holds cols {2t, 2t+1} of block ndt; A-layout wants cols {t, t+4}.
    const int baseLane = lane & ~3;              // 4g
    const int R  = (b * Ts + qt * 64 + warp * 16) >> 4;
    const int K8 = Dd >> 3;                      // 128
#pragma unroll
    for (int ndt = 0; ndt < 8; ++ndt) {
        const float e00 = o[ndt][0] * inv0;   // row g,   col 2t
        const float e01 = o[ndt][1] * inv0;   // row g,   col 2t+1
        const float e10 = o[ndt][2] * inv1;   // row g+8, col 2t
        const float e11 = o[ndt][3] * inv1;   // row g+8, col 2t+1
        const int laneLo = baseLane + (t >> 1);
        const int laneHi = laneLo + 2;
        const float a0 = __shfl_sync(0xffffffffu, e00, laneLo);
        const float a1 = __shfl_sync(0xffffffffu, e01, laneLo);
        const float a2 = __shfl_sync(0xffffffffu, e10, laneLo);
        const float a3 = __shfl_sync(0xffffffffu, e11, laneLo);
        const float b0 = __shfl_sync(0xffffffffu, e00, laneHi);
        const float b1 = __shfl_sync(0xffffffffu, e01, laneHi);
        const float b2 = __shfl_sync(0xffffffffu, e10, laneHi);
        const float b3 = __shfl_sync(0xffffffffu, e11, laneHi);
        const bool odd = (t & 1);
        uint4 w;
        w.x = f2tf32(odd ? a1 : a0);   // row g,   col t
        w.y = f2tf32(odd ? a3 : a2);   // row g+8, col t
        w.z = f2tf32(odd ? b1 : b0);   // row g,   col t+4
        w.w = f2tf32(odd ? b3 : b2);   // row g+8, col t+4
        const int S = h * 8 + ndt;
        ((uint4*)Opacked)[((size_t)R * K8 + S) * 32 + lane] = w;
    }
}

// ===========================================================================
extern "C" void kernel_launch(void* const* d_in, const int* in_sizes, int n_in,
                              void* d_out, int out_size)
{
    const float* x     = (const float*)d_in[0];
    const float* eng   = (const float*)d_in[1];
    const void*  mask  = (const void*)d_in[2];
    const float* qkv_w = (const float*)d_in[3];
    const float* qkv_b = (const float*)d_in[4];
    const float* out_w = (const float*)d_in[5];
    const float* out_b = (const float*)d_in[6];
    float* out = (float*)d_out;

    float* qkv = nullptr;
    uint32_t *xp = nullptr, *op = nullptr, *wq = nullptr, *wo = nullptr;
    cudaGetSymbolAddress((void**)&qkv, g_qkv);
    cudaGetSymbolAddress((void**)&xp,  g_xp);
    cudaGetSymbolAddress((void**)&op,  g_op);
    cudaGetSymbolAddress((void**)&wq,  g_wq);
    cudaGetSymbolAddress((void**)&wo,  g_wo);

    cudaFuncSetAttribute(tf32_gemm_packed,
                         cudaFuncAttributeMaxDynamicSharedMemorySize, GP_SMEM_BYTES);
    cudaFuncSetAttribute(attn_bf16_kernel,
                         cudaFuncAttributeMaxDynamicSharedMemorySize, ATTN_SMEM_BYTES);

    // 0) mask dtype detection + per-key bias precompute (log2 domain)
    detect_mask_kernel<<<1, 256>>>((const unsigned char*)mask);
    bias_kernel<<<(Bb * Ts + 255) / 256, 256>>>(eng, mask);

    // 0b) pack x and weights into fragment-ready tf32 layouts
    pack_a_kernel<<<2048, 256>>>(x, xp, M_ROWS, Dd);
    pack_b_kernel<<<1024, 256>>>(qkv_w, wq, QKV_N, Dd);
    pack_b_kernel<<<512, 256>>>(out_w, wo, Dd, Dd);

    // 1) QKV projection (packed tf32 mma.sync)
    dim3 g1(QKV_N / 128, M_ROWS / 128);
    tf32_gemm_packed<<<g1, 256, GP_SMEM_BYTES>>>(xp, wq, qkv_b, qkv, Dd, QKV_N);

    // 1b) split + repack K/V into fragment-ready bf16 layout
    dim3 gc(32, Hh, Bb);
    convert_kv_kernel<<<gc, 256>>>(qkv);

    // 2) attention -> writes packed tf32 A-layout directly
    dim3 g2(Ts / 64, Hh, Bb);
    attn_bf16_kernel<<<g2, 128, ATTN_SMEM_BYTES>>>(qkv, op);

    // 3) output projection (packed tf32 mma.sync)
    dim3 g3(Dd / 128, M_ROWS / 128);
    tf32_gemm_packed<<<g3, 256, GP_SMEM_BYTES>>>(op, wo, out_b, out, Dd, Dd);
}

// round 9
// speedup vs baseline: 7.4901x; 1.4668x over previous
#include <cuda_runtime.h>
#include <cuda_bf16.h>
#include <cuda_fp16.h>
#include <math.h>
#include <stdint.h>

// Problem constants
#define Bb 4
#define Ts 2048
#define Dd 1024
#define Hh 16
#define HD 64
#define M_ROWS 8192
#define QKV_N 3072

// Scratch (device globals: allocation-free)
__device__ float g_qkv[(size_t)M_ROWS * QKV_N];   // [B*T, 3D]
__device__ float g_bias[Bb * Ts];                 // per-key log2-domain bias
__device__ int   g_maskMode;
// Fragment-ready split-bf16 K (S stage stays bf16x3)
__device__ uint32_t g_K[(size_t)Bb * Hh * 32 * 4096];
// Fragment-ready fp16 V (single precision PV)
__device__ uint4 g_Vq[(size_t)Bb * Hh * 32 * 512];
// Fragment-ready fp16 packs for GEMM operands
__device__ uint4 g_xp[(size_t)(M_ROWS / 16) * 64 * 32];   // x A-pack  (K16=64)
__device__ uint4 g_op[(size_t)(M_ROWS / 16) * 64 * 32];   // attn-out A-pack
__device__ uint4 g_wq[(size_t)(QKV_N / 8) * 32 * 32];     // qkv_w B-pack (K32=32)
__device__ uint4 g_wo[(size_t)(Dd / 8) * 32 * 32];        // out_w B-pack

// ===========================================================================
// helpers
// ===========================================================================
__device__ __forceinline__ uint32_t packf16(float lo, float hi) {
    uint32_t r;
    asm("cvt.rn.f16x2.f32 %0, %1, %2;" : "=r"(r) : "f"(hi), "f"(lo));
    return r;
}
__device__ __forceinline__ float ex2f(float x) {
    float r;
    asm("ex2.approx.ftz.f32 %0, %1;" : "=f"(r) : "f"(x));
    return r;
}

__device__ __forceinline__ void mma_f16(float* c, const uint32_t* a, uint32_t b0, uint32_t b1) {
    asm volatile(
        "mma.sync.aligned.m16n8k16.row.col.f32.f16.f16.f32 "
        "{%0,%1,%2,%3}, {%4,%5,%6,%7}, {%8,%9}, {%0,%1,%2,%3};\n"
        : "+f"(c[0]), "+f"(c[1]), "+f"(c[2]), "+f"(c[3])
        : "r"(a[0]), "r"(a[1]), "r"(a[2]), "r"(a[3]), "r"(b0), "r"(b1));
}
__device__ __forceinline__ void mma_f16q(float* c, const uint4& a, uint32_t b0, uint32_t b1) {
    asm volatile(
        "mma.sync.aligned.m16n8k16.row.col.f32.f16.f16.f32 "
        "{%0,%1,%2,%3}, {%4,%5,%6,%7}, {%8,%9}, {%0,%1,%2,%3};\n"
        : "+f"(c[0]), "+f"(c[1]), "+f"(c[2]), "+f"(c[3])
        : "r"(a.x), "r"(a.y), "r"(a.z), "r"(a.w), "r"(b0), "r"(b1));
}
__device__ __forceinline__ void mma_bf16(float* c, const uint32_t* a, uint32_t b0, uint32_t b1) {
    asm volatile(
        "mma.sync.aligned.m16n8k16.row.col.f32.bf16.bf16.f32 "
        "{%0,%1,%2,%3}, {%4,%5,%6,%7}, {%8,%9}, {%0,%1,%2,%3};\n"
        : "+f"(c[0]), "+f"(c[1]), "+f"(c[2]), "+f"(c[3])
        : "r"(a[0]), "r"(a[1]), "r"(a[2]), "r"(a[3]), "r"(b0), "r"(b1));
}

__device__ __forceinline__ void split2(float x, float y, uint32_t& hi, uint32_t& lo) {
    __nv_bfloat16 hx = __float2bfloat16_rn(x);
    __nv_bfloat16 hy = __float2bfloat16_rn(y);
    __nv_bfloat16 lx = __float2bfloat16_rn(x - __bfloat162float(hx));
    __nv_bfloat16 ly = __float2bfloat16_rn(y - __bfloat162float(hy));
    __nv_bfloat162 h2 = __halves2bfloat162(hx, hy);
    __nv_bfloat162 l2 = __halves2bfloat162(lx, ly);
    hi = *(uint32_t*)&h2;
    lo = *(uint32_t*)&l2;
}

__device__ __forceinline__ uint32_t smem_u32(const void* p) {
    uint32_t a;
    asm("{ .reg .u64 t; cvta.to.shared.u64 t, %1; cvt.u32.u64 %0, t; }" : "=r"(a) : "l"(p));
    return a;
}
__device__ __forceinline__ void cp_async16(uint32_t dst, const void* src) {
    asm volatile("cp.async.cg.shared.global [%0], [%1], 16;" :: "r"(dst), "l"(src));
}
#define CP_COMMIT() asm volatile("cp.async.commit_group;" ::: "memory")
#define CP_WAIT(n)  asm volatile("cp.async.wait_group %0;" :: "n"(n) : "memory")

// ===========================================================================
// Mask dtype detection + bias precompute (log2 domain)
// ===========================================================================
__global__ void detect_mask_kernel(const unsigned char* __restrict__ mask)
{
    __shared__ unsigned int orr[4][256];
    const int tid = threadIdx.x;
    unsigned int o0 = 0, o1 = 0, o2 = 0, o3 = 0;
    for (int i = tid * 4; i < Bb * Ts; i += 256 * 4) {
        o0 |= mask[i + 0]; o1 |= mask[i + 1]; o2 |= mask[i + 2]; o3 |= mask[i + 3];
    }
    orr[0][tid] = o0; orr[1][tid] = o1; orr[2][tid] = o2; orr[3][tid] = o3;
    __syncthreads();
    for (int s = 128; s; s >>= 1) {
        if (tid < s) {
            orr[0][tid] |= orr[0][tid + s];
            orr[1][tid] |= orr[1][tid + s];
            orr[2][tid] |= orr[2][tid + s];
            orr[3][tid] |= orr[3][tid + s];
        }
        __syncthreads();
    }
    if (tid == 0) {
        unsigned int l0 = orr[0][0], l1 = orr[1][0], l2 = orr[2][0], l3 = orr[3][0];
        int mode;
        if ((l1 | l2 | l3) == 0u) mode = 1;
        else if ((l0 | l1) == 0u && (l2 | l3) != 0u) mode = 2;
        else mode = 0;
        g_maskMode = mode;
    }
}

__global__ void bias_kernel(const float* __restrict__ eng, const void* __restrict__ mask)
{
    const int kk = blockIdx.x * 256 + threadIdx.x;
    if (kk >= Bb * Ts) return;
    const int mode = g_maskMode;
    bool m;
    if (mode == 1)      m = ((const int*)mask)[kk] != 0;
    else if (mode == 2) m = ((const float*)mask)[kk] != 0.f;
    else                m = ((const unsigned char*)mask)[kk] != 0;
    g_bias[kk] = m ? -1e9f : log2f(fmaxf(eng[kk], 1e-6f));
}

// ===========================================================================
// fp16 fragment packing.
// A-pack quad (R=row/16, S=k/16, lane=4g+t):
//   {A[16R+g][16S+2t..+1], A[16R+8+g][..], A[16R+g][16S+8+2t..], A[16R+8+g][..]}
// B-pack quad (C=col/8, S=k/32):
//   {W[8C+g][32S+2t..+1], W[..][32S+8+2t..], W[..][32S+16+2t..], W[..][32S+24+2t..]}
// ===========================================================================
__global__ void __launch_bounds__(256)
pack_a_f16(const float* __restrict__ src, uint4* __restrict__ dst, int M, int K)
{
    const int K16 = K >> 4;
    const int total = (M >> 4) * K16 * 32;
    for (int q = blockIdx.x * 256 + threadIdx.x; q < total; q += gridDim.x * 256) {
        const int lane = q & 31;
        const int rs = q >> 5;
        const int S = rs % K16;
        const int R = rs / K16;
        const int g = lane >> 2, t = lane & 3;
        const float* p = src + (size_t)(R * 16 + g) * K + S * 16 + 2 * t;
        const float* p2 = p + (size_t)8 * K;
        const float2 a0 = *(const float2*)(p);
        const float2 a1 = *(const float2*)(p2);
        const float2 a2 = *(const float2*)(p + 8);
        const float2 a3 = *(const float2*)(p2 + 8);
        uint4 w;
        w.x = packf16(a0.x, a0.y);
        w.y = packf16(a1.x, a1.y);
        w.z = packf16(a2.x, a2.y);
        w.w = packf16(a3.x, a3.y);
        dst[q] = w;
    }
}

__global__ void __launch_bounds__(256)
pack_b_f16(const float* __restrict__ src, uint4* __restrict__ dst, int N, int K)
{
    const int K32 = K >> 5;
    const int total = (N >> 3) * K32 * 32;
    for (int q = blockIdx.x * 256 + threadIdx.x; q < total; q += gridDim.x * 256) {
        const int lane = q & 31;
        const int cs = q >> 5;
        const int S = cs % K32;
        const int C = cs / K32;
        const int g = lane >> 2, t = lane & 3;
        const float* p = src + (size_t)(C * 8 + g) * K + S * 32 + 2 * t;
        const float2 b0 = *(const float2*)(p);
        const float2 b1 = *(const float2*)(p + 8);
        const float2 b2 = *(const float2*)(p + 16);
        const float2 b3 = *(const float2*)(p + 24);
        uint4 w;
        w.x = packf16(b0.x, b0.y);
        w.y = packf16(b1.x, b1.y);
        w.z = packf16(b2.x, b2.y);
        w.w = packf16(b3.x, b3.y);
        dst[q] = w;
    }
}

// ===========================================================================
// fp16 GEMM on packed operands: C[M,N] = A@W^T + bias
// 128x128 tile, BK=32, cp.async double-buffered, LDS.128 fragment loads.
// ===========================================================================
#define GP_SMEM_BYTES 32768

__global__ void __launch_bounds__(256)
f16_gemm_packed(const uint4* __restrict__ Ap, const uint4* __restrict__ Bp,
                const float* __restrict__ bias, float* __restrict__ C,
                int K, int ldc)
{
    extern __shared__ uint4 ps[];
    uint4* sA = ps;            // [2][512]
    uint4* sB = ps + 1024;     // [2][512]
    const uint32_t sAaddr = smem_u32(sA);
    const uint32_t sBaddr = smem_u32(sB);

    const int tid  = threadIdx.x;
    const int wid  = tid >> 5;
    const int lane = tid & 31;
    const int g = lane >> 2, t = lane & 3;
    const int wm = wid & 3;
    const int wn = wid >> 2;
    const int bm = blockIdx.y * 128;
    const int bn = blockIdx.x * 128;
    const int K16 = K >> 4;
    const int K32 = K >> 5;
    const int Rb = bm >> 4;
    const int Cb = bn >> 3;

    float acc[2][8][4];
#pragma unroll
    for (int mi = 0; mi < 2; ++mi)
#pragma unroll
        for (int ni = 0; ni < 8; ++ni)
#pragma unroll
            for (int r = 0; r < 4; ++r) acc[mi][ni][r] = 0.f;

    auto issue = [&](int buf, int kt) {
#pragma unroll
        for (int i = 0; i < 2; ++i) {
            const int l    = tid + 256 * i;
            const int tile = l >> 5;          // 0..15
            const int ln   = l & 31;
            // A: tile = r*2 + s  (r = M-16-tile 0..7, s = k16 sub 0..1)
            cp_async16(sAaddr + buf * 8192 + l * 16,
                       Ap + ((size_t)(Rb + (tile >> 1)) * K16 + 2 * kt + (tile & 1)) * 32 + ln);
            // B: tile = C-8-tile 0..15
            cp_async16(sBaddr + buf * 8192 + l * 16,
                       Bp + ((size_t)(Cb + tile) * K32 + kt) * 32 + ln);
        }
    };

    const int nChunks = K >> 5;
    issue(0, 0);
    CP_COMMIT();

    for (int kt = 0; kt < nChunks; ++kt) {
        const int buf = kt & 1;
        if (kt + 1 < nChunks) {
            issue(buf ^ 1, kt + 1);
            CP_COMMIT();
            CP_WAIT(1);
        } else {
            CP_WAIT(0);
        }
        __syncthreads();

        const uint4* bufA = sA + buf * 512;
        const uint4* bufB = sB + buf * 512;
        uint4 fa[2][2];
#pragma unroll
        for (int mi = 0; mi < 2; ++mi)
#pragma unroll
            for (int kc = 0; kc < 2; ++kc)
                fa[mi][kc] = bufA[(((wm * 2 + mi) << 1) | kc) * 32 + lane];
#pragma unroll
        for (int ni = 0; ni < 8; ++ni) {
            const uint4 f = bufB[(wn * 8 + ni) * 32 + lane];
            mma_f16q(acc[0][ni], fa[0][0], f.x, f.y);
            mma_f16q(acc[1][ni], fa[1][0], f.x, f.y);
            mma_f16q(acc[0][ni], fa[0][1], f.z, f.w);
            mma_f16q(acc[1][ni], fa[1][1], f.z, f.w);
        }
        __syncthreads();
    }

#pragma unroll
    for (int mi = 0; mi < 2; ++mi) {
        const int row = bm + wm * 32 + mi * 16 + g;
#pragma unroll
        for (int ni = 0; ni < 8; ++ni) {
            const int col = bn + wn * 64 + ni * 8 + 2 * t;
            const float b0 = bias[col];
            const float b1 = bias[col + 1];
            float2 lo, hi;
            lo.x = acc[mi][ni][0] + b0; lo.y = acc[mi][ni][1] + b1;
            hi.x = acc[mi][ni][2] + b0; hi.y = acc[mi][ni][3] + b1;
            *(float2*)(C + (size_t)row * ldc + col) = lo;
            *(float2*)(C + (size_t)(row + 8) * ldc + col) = hi;
        }
    }
}

// ===========================================================================
// K/V repack: K split-bf16 (unchanged layout), V single fp16 fragments.
// V quad (kp=key/16, nd2=d/16, lane): {V[16kp+2t..+1][d0], V[16kp+8+2t..][d0],
//                                      V[16kp+2t..+1][d1], V[16kp+8+2t..][d1]}
//   d0 = 16*nd2 + g, d1 = d0 + 8.
// ===========================================================================
__global__ void __launch_bounds__(256)
convert_kv_kernel(const float* __restrict__ qkv)
{
    const int kt = blockIdx.x, h = blockIdx.y, b = blockIdx.z;
    const size_t tileBaseK = (((size_t)(b * Hh + h)) * 32 + kt) * 4096;
    const size_t tileBaseV = (((size_t)(b * Hh + h)) * 32 + kt) * 512;
    const int tid = threadIdx.x;

    // K: split-bf16 fragment quads (4096 u32 per tile)
#pragma unroll
    for (int i = 0; i < 4; ++i) {
        const int qi  = tid + 256 * i;
        const int t   = qi & 3;
        const int key = (qi >> 2) & 63;
        const int ks  = qi >> 8;
        const float* kp = qkv + (size_t)(b * Ts + kt * 64 + key) * QKV_N + Dd + h * HD + 16 * ks + 2 * t;
        const float2 v0 = *(const float2*)(kp);
        const float2 v1 = *(const float2*)(kp + 8);
        uint32_t h0, l0, h1, l1;
        split2(v0.x, v0.y, h0, l0);
        split2(v1.x, v1.y, h1, l1);
        uint4 w; w.x = h0; w.y = h1; w.z = l0; w.w = l1;
        *(uint4*)&g_K[tileBaseK + (size_t)qi * 4] = w;
    }
    // V: fp16 quads (512 uint4 per tile)
#pragma unroll
    for (int i = 0; i < 2; ++i) {
        const int qi   = tid + 256 * i;
        const int lane = qi & 31;
        const int g    = lane >> 2, t = lane & 3;
        const int nd2  = (qi >> 5) & 3;
        const int kp_  = qi >> 7;
        const int d0 = nd2 * 16 + g;
        const float* vb = qkv + (size_t)(b * Ts + kt * 64 + kp_ * 16 + 2 * t) * QKV_N + 2 * Dd + h * HD;
        uint4 w;
        w.x = packf16(vb[d0],                   vb[QKV_N + d0]);
        w.y = packf16(vb[8 * QKV_N + d0],       vb[9 * QKV_N + d0]);
        w.z = packf16(vb[d0 + 8],               vb[QKV_N + d0 + 8]);
        w.w = packf16(vb[8 * QKV_N + d0 + 8],   vb[9 * QKV_N + d0 + 8]);
        g_Vq[tileBaseV + qi] = w;
    }
}

// ===========================================================================
// Flash attention: S = bf16x3 MMA, softmax = no-max ex2 (log2 bias),
// PV = single-fp16 MMA, epilogue writes fp16 A-pack quads for out-proj.
// ===========================================================================
#define ATTN_SMEM_BYTES (2 * 16384 + 2 * 8192 + 2 * 256)
#define C1 0.18033688011112042f   // 0.125 * log2(e)

__global__ void __launch_bounds__(128, 3)
attn_kernel(const float* __restrict__ qkv, uint4* __restrict__ Opacked)
{
    extern __shared__ uint32_t asmem[];
    uint32_t* sK = asmem;                        // [2][4096] u32
    uint4*    sV = (uint4*)(asmem + 8192);       // [2][512] uint4
    float*    sBias = (float*)(asmem + 8192 + 4096);  // [2][64]

    const uint32_t sKaddr = smem_u32(sK);
    const uint32_t sVaddr = smem_u32(sV);
    const uint32_t sBaddr = smem_u32(sBias);

    const int qt = blockIdx.x;
    const int h  = blockIdx.y;
    const int b  = blockIdx.z;
    const int tid  = threadIdx.x;
    const int warp = tid >> 5;
    const int lane = tid & 31;
    const int g = lane >> 2, t = lane & 3;

    const size_t kvBaseK = ((size_t)(b * Hh + h)) * 32 * 4096;
    const size_t kvBaseV = ((size_t)(b * Hh + h)) * 32 * 512;

    // Q fragments (split bf16)
    uint32_t qh[4][4], ql[4][4];
    {
        const float* q0 = qkv + (size_t)(b * Ts + qt * 64 + warp * 16 + g) * QKV_N + h * HD;
        const float* q1 = q0 + (size_t)8 * QKV_N;
#pragma unroll
        for (int ks = 0; ks < 4; ++ks) {
#pragma unroll
            for (int hf = 0; hf < 2; ++hf) {
                const int col = 16 * ks + 2 * t + 8 * hf;
                const float2 v0 = *(const float2*)(q0 + col);
                const float2 v1 = *(const float2*)(q1 + col);
                split2(v0.x, v0.y, qh[ks][2 * hf + 0], ql[ks][2 * hf + 0]);
                split2(v1.x, v1.y, qh[ks][2 * hf + 1], ql[ks][2 * hf + 1]);
            }
        }
    }

    float o[8][4];
#pragma unroll
    for (int i = 0; i < 8; ++i)
#pragma unroll
        for (int j = 0; j < 4; ++j) o[i][j] = 0.f;
    float l0 = 0.f, l1 = 0.f;

    auto issue = [&](int buf, int kt) {
        const uint32_t* srcK = g_K + kvBaseK + (size_t)kt * 4096 + tid * 4;
        const uint4*    srcV = g_Vq + kvBaseV + (size_t)kt * 512 + tid;
        const uint32_t dK = sKaddr + buf * 16384 + tid * 16;
        const uint32_t dV = sVaddr + buf * 8192 + tid * 16;
#pragma unroll
        for (int i = 0; i < 8; ++i) cp_async16(dK + i * 2048, srcK + i * 512);
#pragma unroll
        for (int i = 0; i < 4; ++i) cp_async16(dV + i * 2048, srcV + i * 128);
        if (tid < 16) cp_async16(sBaddr + buf * 256 + tid * 16, g_bias + b * Ts + kt * 64 + tid * 4);
    };

    issue(0, 0);
    CP_COMMIT();

    for (int kt = 0; kt < Ts / 64; ++kt) {
        const int buf = kt & 1;
        if (kt + 1 < Ts / 64) {
            issue(buf ^ 1, kt + 1);
            CP_COMMIT();
            CP_WAIT(1);
        } else {
            CP_WAIT(0);
        }
        __syncthreads();

        const uint32_t* bK = sK + buf * 4096;
        const uint4*    bV = sV + buf * 512;
        const float* bB = sBias + buf * 64;

        // ---- S = Q K^T (bf16x3) ----
        float sacc[8][4];
#pragma unroll
        for (int nt = 0; nt < 8; ++nt)
#pragma unroll
            for (int j = 0; j < 4; ++j) sacc[nt][j] = 0.f;
#pragma unroll
        for (int ks = 0; ks < 4; ++ks) {
#pragma unroll
            for (int nt = 0; nt < 8; ++nt) {
                const uint4 f = *(const uint4*)(bK + ks * 1024 + (8 * nt + g) * 16 + t * 4);
                mma_bf16(sacc[nt], qh[ks], f.x, f.y);
                mma_bf16(sacc[nt], qh[ks], f.z, f.w);
                mma_bf16(sacc[nt], ql[ks], f.x, f.y);
            }
        }

        // ---- softmax weights (no max): P = exp2(S*C1 + log2bias), pack fp16 ----
        float rs0 = 0.f, rs1 = 0.f;
        uint32_t ph[8][2];
#pragma unroll
        for (int nt = 0; nt < 8; ++nt) {
            const float b0 = bB[8 * nt + 2 * t];
            const float b1 = bB[8 * nt + 2 * t + 1];
            const float p0 = ex2f(fmaf(sacc[nt][0], C1, b0));
            const float p1 = ex2f(fmaf(sacc[nt][1], C1, b1));
            const float p2 = ex2f(fmaf(sacc[nt][2], C1, b0));
            const float p3 = ex2f(fmaf(sacc[nt][3], C1, b1));
            rs0 += p0 + p1;
            rs1 += p2 + p3;
            ph[nt][0] = packf16(p0, p1);
            ph[nt][1] = packf16(p2, p3);
        }
        l0 += rs0;
        l1 += rs1;

        // ---- O += P V (single fp16) ----
#pragma unroll
        for (int kp = 0; kp < 4; ++kp) {
            const uint32_t a[4] = { ph[2 * kp][0], ph[2 * kp][1],
                                    ph[2 * kp + 1][0], ph[2 * kp + 1][1] };
#pragma unroll
            for (int nd2 = 0; nd2 < 4; ++nd2) {
                const uint4 f = bV[(kp * 4 + nd2) * 32 + lane];
                mma_f16(o[2 * nd2], a, f.x, f.y);
                mma_f16(o[2 * nd2 + 1], a, f.z, f.w);
            }
        }
        __syncthreads();
    }

    // row sums across 4 t-lanes
    l0 += __shfl_xor_sync(0xffffffffu, l0, 1);
    l0 += __shfl_xor_sync(0xffffffffu, l0, 2);
    l1 += __shfl_xor_sync(0xffffffffu, l1, 1);
    l1 += __shfl_xor_sync(0xffffffffu, l1, 2);
    const float inv0 = 1.0f / l0;
    const float inv1 = 1.0f / l1;

    // fused epilogue: normalize + write fp16 A-pack quads (no shuffles needed)
    const int R = (b * Ts + qt * 64 + warp * 16) >> 4;
#pragma unroll
    for (int sd = 0; sd < 4; ++sd) {
        uint4 w;
        w.x = packf16(o[2 * sd][0] * inv0,     o[2 * sd][1] * inv0);
        w.y = packf16(o[2 * sd][2] * inv1,     o[2 * sd][3] * inv1);
        w.z = packf16(o[2 * sd + 1][0] * inv0, o[2 * sd + 1][1] * inv0);
        w.w = packf16(o[2 * sd + 1][2] * inv1, o[2 * sd + 1][3] * inv1);
        Opacked[((size_t)R * 64 + h * 4 + sd) * 32 + lane] = w;
    }
}

// ===========================================================================
extern "C" void kernel_launch(void* const* d_in, const int* in_sizes, int n_in,
                              void* d_out, int out_size)
{
    const float* x     = (const float*)d_in[0];
    const float* eng   = (const float*)d_in[1];
    const void*  mask  = (const void*)d_in[2];
    const float* qkv_w = (const float*)d_in[3];
    const float* qkv_b = (const float*)d_in[4];
    const float* out_w = (const float*)d_in[5];
    const float* out_b = (const float*)d_in[6];
    float* out = (float*)d_out;

    float* qkv = nullptr;
    uint4 *xp = nullptr, *op = nullptr, *wq = nullptr, *wo = nullptr;
    cudaGetSymbolAddress((void**)&qkv, g_qkv);
    cudaGetSymbolAddress((void**)&xp,  g_xp);
    cudaGetSymbolAddress((void**)&op,  g_op);
    cudaGetSymbolAddress((void**)&wq,  g_wq);
    cudaGetSymbolAddress((void**)&wo,  g_wo);

    cudaFuncSetAttribute(f16_gemm_packed,
                         cudaFuncAttributeMaxDynamicSharedMemorySize, GP_SMEM_BYTES);
    cudaFuncSetAttribute(attn_kernel,
                         cudaFuncAttributeMaxDynamicSharedMemorySize, ATTN_SMEM_BYTES);

    // 0) mask dtype detection + per-key bias precompute (log2 domain)
    detect_mask_kernel<<<1, 256>>>((const unsigned char*)mask);
    bias_kernel<<<(Bb * Ts + 255) / 256, 256>>>(eng, mask);

    // 0b) pack x and weights into fp16 fragment layouts
    pack_a_f16<<<2048, 256>>>(x, xp, M_ROWS, Dd);
    pack_b_f16<<<1536, 256>>>(qkv_w, wq, QKV_N, Dd);
    pack_b_f16<<<512, 256>>>(out_w, wo, Dd, Dd);

    // 1) QKV projection (packed fp16 mma.sync)
    dim3 g1(QKV_N / 128, M_ROWS / 128);
    f16_gemm_packed<<<g1, 256, GP_SMEM_BYTES>>>(xp, wq, qkv_b, qkv, Dd, QKV_N);

    // 1b) repack K (split-bf16) + V (fp16) fragments
    dim3 gc(32, Hh, Bb);
    convert_kv_kernel<<<gc, 256>>>(qkv);

    // 2) attention -> writes fp16 A-pack directly
    dim3 g2(Ts / 64, Hh, Bb);
    attn_kernel<<<g2, 128, ATTN_SMEM_BYTES>>>(qkv, op);

    // 3) output projection (packed fp16 mma.sync)
    dim3 g3(Dd / 128, M_ROWS / 128);
    f16_gemm_packed<<<g3, 256, GP_SMEM_BYTES>>>(op, wo, out_b, out, Dd, Dd);
}

// round 10
// speedup vs baseline: 9.6465x; 1.2879x over previous
#include <cuda_runtime.h>
#include <cuda_bf16.h>
#include <cuda_fp16.h>
#include <math.h>
#include <stdint.h>

// Problem constants
#define Bb 4
#define Ts 2048
#define Dd 1024
#define Hh 16
#define HD 64
#define M_ROWS 8192
#define QKV_N 3072

// Scratch (device globals: allocation-free)
__device__ float g_qkv[(size_t)M_ROWS * QKV_N];   // [B*T, 3D]
__device__ float g_bias[Bb * Ts];                 // per-key log2-domain bias
__device__ int   g_maskMode;
// Fragment-ready fp16 K (B-pack layout) and V
__device__ uint4 g_Kq[(size_t)Bb * Hh * 32 * 512];
__device__ uint4 g_Vq[(size_t)Bb * Hh * 32 * 512];
// Fragment-ready fp16 packs for GEMM operands
__device__ uint4 g_xp[(size_t)(M_ROWS / 16) * 64 * 32];   // x A-pack
__device__ uint4 g_op[(size_t)(M_ROWS / 16) * 64 * 32];   // attn-out A-pack
__device__ uint4 g_wq[(size_t)(QKV_N / 8) * 32 * 32];     // qkv_w B-pack
__device__ uint4 g_wo[(size_t)(Dd / 8) * 32 * 32];        // out_w B-pack

// ===========================================================================
// helpers
// ===========================================================================
__device__ __forceinline__ uint32_t packf16(float lo, float hi) {
    uint32_t r;
    asm("cvt.rn.f16x2.f32 %0, %1, %2;" : "=r"(r) : "f"(hi), "f"(lo));
    return r;
}
__device__ __forceinline__ float ex2f(float x) {
    float r;
    asm("ex2.approx.ftz.f32 %0, %1;" : "=f"(r) : "f"(x));
    return r;
}

__device__ __forceinline__ void mma_f16(float* c, const uint32_t* a, uint32_t b0, uint32_t b1) {
    asm volatile(
        "mma.sync.aligned.m16n8k16.row.col.f32.f16.f16.f32 "
        "{%0,%1,%2,%3}, {%4,%5,%6,%7}, {%8,%9}, {%0,%1,%2,%3};\n"
        : "+f"(c[0]), "+f"(c[1]), "+f"(c[2]), "+f"(c[3])
        : "r"(a[0]), "r"(a[1]), "r"(a[2]), "r"(a[3]), "r"(b0), "r"(b1));
}
__device__ __forceinline__ void mma_f16q(float* c, const uint4& a, uint32_t b0, uint32_t b1) {
    asm volatile(
        "mma.sync.aligned.m16n8k16.row.col.f32.f16.f16.f32 "
        "{%0,%1,%2,%3}, {%4,%5,%6,%7}, {%8,%9}, {%0,%1,%2,%3};\n"
        : "+f"(c[0]), "+f"(c[1]), "+f"(c[2]), "+f"(c[3])
        : "r"(a.x), "r"(a.y), "r"(a.z), "r"(a.w), "r"(b0), "r"(b1));
}

__device__ __forceinline__ uint32_t smem_u32(const void* p) {
    uint32_t a;
    asm("{ .reg .u64 t; cvta.to.shared.u64 t, %1; cvt.u32.u64 %0, t; }" : "=r"(a) : "l"(p));
    return a;
}
__device__ __forceinline__ void cp_async16(uint32_t dst, const void* src) {
    asm volatile("cp.async.cg.shared.global [%0], [%1], 16;" :: "r"(dst), "l"(src));
}
#define CP_COMMIT() asm volatile("cp.async.commit_group;" ::: "memory")
#define CP_WAIT(n)  asm volatile("cp.async.wait_group %0;" :: "n"(n) : "memory")

// ===========================================================================
// Mask dtype detection + bias precompute (log2 domain)
// ===========================================================================
__global__ void detect_mask_kernel(const unsigned char* __restrict__ mask)
{
    __shared__ unsigned int orr[4][256];
    const int tid = threadIdx.x;
    unsigned int o0 = 0, o1 = 0, o2 = 0, o3 = 0;
    for (int i = tid * 4; i < Bb * Ts; i += 256 * 4) {
        o0 |= mask[i + 0]; o1 |= mask[i + 1]; o2 |= mask[i + 2]; o3 |= mask[i + 3];
    }
    orr[0][tid] = o0; orr[1][tid] = o1; orr[2][tid] = o2; orr[3][tid] = o3;
    __syncthreads();
    for (int s = 128; s; s >>= 1) {
        if (tid < s) {
            orr[0][tid] |= orr[0][tid + s];
            orr[1][tid] |= orr[1][tid + s];
            orr[2][tid] |= orr[2][tid + s];
            orr[3][tid] |= orr[3][tid + s];
        }
        __syncthreads();
    }
    if (tid == 0) {
        unsigned int l0 = orr[0][0], l1 = orr[1][0], l2 = orr[2][0], l3 = orr[3][0];
        int mode;
        if ((l1 | l2 | l3) == 0u) mode = 1;
        else if ((l0 | l1) == 0u && (l2 | l3) != 0u) mode = 2;
        else mode = 0;
        g_maskMode = mode;
    }
}

__global__ void bias_kernel(const float* __restrict__ eng, const void* __restrict__ mask)
{
    const int kk = blockIdx.x * 256 + threadIdx.x;
    if (kk >= Bb * Ts) return;
    const int mode = g_maskMode;
    bool m;
    if (mode == 1)      m = ((const int*)mask)[kk] != 0;
    else if (mode == 2) m = ((const float*)mask)[kk] != 0.f;
    else                m = ((const unsigned char*)mask)[kk] != 0;
    g_bias[kk] = m ? -1e9f : log2f(fmaxf(eng[kk], 1e-6f));
}

// ===========================================================================
// fp16 fragment packing (A- and B-layouts), unchanged from round 9
// ===========================================================================
__global__ void __launch_bounds__(256)
pack_a_f16(const float* __restrict__ src, uint4* __restrict__ dst, int M, int K)
{
    const int K16 = K >> 4;
    const int total = (M >> 4) * K16 * 32;
    for (int q = blockIdx.x * 256 + threadIdx.x; q < total; q += gridDim.x * 256) {
        const int lane = q & 31;
        const int rs = q >> 5;
        const int S = rs % K16;
        const int R = rs / K16;
        const int g = lane >> 2, t = lane & 3;
        const float* p = src + (size_t)(R * 16 + g) * K + S * 16 + 2 * t;
        const float* p2 = p + (size_t)8 * K;
        const float2 a0 = *(const float2*)(p);
        const float2 a1 = *(const float2*)(p2);
        const float2 a2 = *(const float2*)(p + 8);
        const float2 a3 = *(const float2*)(p2 + 8);
        uint4 w;
        w.x = packf16(a0.x, a0.y);
        w.y = packf16(a1.x, a1.y);
        w.z = packf16(a2.x, a2.y);
        w.w = packf16(a3.x, a3.y);
        dst[q] = w;
    }
}

__global__ void __launch_bounds__(256)
pack_b_f16(const float* __restrict__ src, uint4* __restrict__ dst, int N, int K)
{
    const int K32 = K >> 5;
    const int total = (N >> 3) * K32 * 32;
    for (int q = blockIdx.x * 256 + threadIdx.x; q < total; q += gridDim.x * 256) {
        const int lane = q & 31;
        const int cs = q >> 5;
        const int S = cs % K32;
        const int C = cs / K32;
        const int g = lane >> 2, t = lane & 3;
        const float* p = src + (size_t)(C * 8 + g) * K + S * 32 + 2 * t;
        const float2 b0 = *(const float2*)(p);
        const float2 b1 = *(const float2*)(p + 8);
        const float2 b2 = *(const float2*)(p + 16);
        const float2 b3 = *(const float2*)(p + 24);
        uint4 w;
        w.x = packf16(b0.x, b0.y);
        w.y = packf16(b1.x, b1.y);
        w.z = packf16(b2.x, b2.y);
        w.w = packf16(b3.x, b3.y);
        dst[q] = w;
    }
}

// ===========================================================================
// fp16 GEMM on packed operands (unchanged from round 9)
// ===========================================================================
#define GP_SMEM_BYTES 32768

__global__ void __launch_bounds__(256)
f16_gemm_packed(const uint4* __restrict__ Ap, const uint4* __restrict__ Bp,
                const float* __restrict__ bias, float* __restrict__ C,
                int K, int ldc)
{
    extern __shared__ uint4 ps[];
    uint4* sA = ps;
    uint4* sB = ps + 1024;
    const uint32_t sAaddr = smem_u32(sA);
    const uint32_t sBaddr = smem_u32(sB);

    const int tid  = threadIdx.x;
    const int wid  = tid >> 5;
    const int lane = tid & 31;
    const int g = lane >> 2, t = lane & 3;
    const int wm = wid & 3;
    const int wn = wid >> 2;
    const int bm = blockIdx.y * 128;
    const int bn = blockIdx.x * 128;
    const int K16 = K >> 4;
    const int K32 = K >> 5;
    const int Rb = bm >> 4;
    const int Cb = bn >> 3;

    float acc[2][8][4];
#pragma unroll
    for (int mi = 0; mi < 2; ++mi)
#pragma unroll
        for (int ni = 0; ni < 8; ++ni)
#pragma unroll
            for (int r = 0; r < 4; ++r) acc[mi][ni][r] = 0.f;

    auto issue = [&](int buf, int kt) {
#pragma unroll
        for (int i = 0; i < 2; ++i) {
            const int l    = tid + 256 * i;
            const int tile = l >> 5;
            const int ln   = l & 31;
            cp_async16(sAaddr + buf * 8192 + l * 16,
                       Ap + ((size_t)(Rb + (tile >> 1)) * K16 + 2 * kt + (tile & 1)) * 32 + ln);
            cp_async16(sBaddr + buf * 8192 + l * 16,
                       Bp + ((size_t)(Cb + tile) * K32 + kt) * 32 + ln);
        }
    };

    const int nChunks = K >> 5;
    issue(0, 0);
    CP_COMMIT();

    for (int kt = 0; kt < nChunks; ++kt) {
        const int buf = kt & 1;
        if (kt + 1 < nChunks) {
            issue(buf ^ 1, kt + 1);
            CP_COMMIT();
            CP_WAIT(1);
        } else {
            CP_WAIT(0);
        }
        __syncthreads();

        const uint4* bufA = sA + buf * 512;
        const uint4* bufB = sB + buf * 512;
        uint4 fa[2][2];
#pragma unroll
        for (int mi = 0; mi < 2; ++mi)
#pragma unroll
            for (int kc = 0; kc < 2; ++kc)
                fa[mi][kc] = bufA[(((wm * 2 + mi) << 1) | kc) * 32 + lane];
#pragma unroll
        for (int ni = 0; ni < 8; ++ni) {
            const uint4 f = bufB[(wn * 8 + ni) * 32 + lane];
            mma_f16q(acc[0][ni], fa[0][0], f.x, f.y);
            mma_f16q(acc[1][ni], fa[1][0], f.x, f.y);
            mma_f16q(acc[0][ni], fa[0][1], f.z, f.w);
            mma_f16q(acc[1][ni], fa[1][1], f.z, f.w);
        }
        __syncthreads();
    }

#pragma unroll
    for (int mi = 0; mi < 2; ++mi) {
        const int row = bm + wm * 32 + mi * 16 + g;
#pragma unroll
        for (int ni = 0; ni < 8; ++ni) {
            const int col = bn + wn * 64 + ni * 8 + 2 * t;
            const float b0 = bias[col];
            const float b1 = bias[col + 1];
            float2 lo, hi;
            lo.x = acc[mi][ni][0] + b0; lo.y = acc[mi][ni][1] + b1;
            hi.x = acc[mi][ni][2] + b0; hi.y = acc[mi][ni][3] + b1;
            *(float2*)(C + (size_t)row * ldc + col) = lo;
            *(float2*)(C + (size_t)(row + 8) * ldc + col) = hi;
        }
    }
}

// ===========================================================================
// K/V repack, both single fp16.
// K quad (nt=key/8, ksp=dim/32, lane): B-pack layout
//   {K[8nt+g][32ksp+2t..], [..+8..], [..+16..], [..+24..]}
// V quad (kp=key/16, nd2=d/16, lane): as round 9.
// ===========================================================================
__global__ void __launch_bounds__(256)
convert_kv_kernel(const float* __restrict__ qkv)
{
    const int kt = blockIdx.x, h = blockIdx.y, b = blockIdx.z;
    const size_t tileBase = (((size_t)(b * Hh + h)) * 32 + kt) * 512;
    const int tid = threadIdx.x;

    // K: fp16 B-pack quads (512 uint4 per tile)
#pragma unroll
    for (int i = 0; i < 2; ++i) {
        const int qi   = tid + 256 * i;
        const int lane = qi & 31;
        const int g    = lane >> 2, t = lane & 3;
        const int ksp  = (qi >> 5) & 1;
        const int nt   = qi >> 6;
        const int key  = kt * 64 + nt * 8 + g;
        const float* p = qkv + (size_t)(b * Ts + key) * QKV_N + Dd + h * HD + 32 * ksp + 2 * t;
        const float2 b0 = *(const float2*)(p);
        const float2 b1 = *(const float2*)(p + 8);
        const float2 b2 = *(const float2*)(p + 16);
        const float2 b3 = *(const float2*)(p + 24);
        uint4 w;
        w.x = packf16(b0.x, b0.y);
        w.y = packf16(b1.x, b1.y);
        w.z = packf16(b2.x, b2.y);
        w.w = packf16(b3.x, b3.y);
        g_Kq[tileBase + qi] = w;
    }
    // V: fp16 quads (512 uint4 per tile)
#pragma unroll
    for (int i = 0; i < 2; ++i) {
        const int qi   = tid + 256 * i;
        const int lane = qi & 31;
        const int g    = lane >> 2, t = lane & 3;
        const int nd2  = (qi >> 5) & 3;
        const int kp_  = qi >> 7;
        const int d0 = nd2 * 16 + g;
        const float* vb = qkv + (size_t)(b * Ts + kt * 64 + kp_ * 16 + 2 * t) * QKV_N + 2 * Dd + h * HD;
        uint4 w;
        w.x = packf16(vb[d0],                   vb[QKV_N + d0]);
        w.y = packf16(vb[8 * QKV_N + d0],       vb[9 * QKV_N + d0]);
        w.z = packf16(vb[d0 + 8],               vb[QKV_N + d0 + 8]);
        w.w = packf16(vb[8 * QKV_N + d0 + 8],   vb[9 * QKV_N + d0 + 8]);
        g_Vq[tileBase + qi] = w;
    }
}

// ===========================================================================
// Flash attention: all-fp16 MMA (S and PV single precision),
// no-max ex2 softmax, fused fp16 A-pack epilogue.
// ===========================================================================
#define ATTN_SMEM_BYTES (2 * 8192 + 2 * 8192 + 2 * 256)
#define C1 0.18033688011112042f   // 0.125 * log2(e)

__global__ void __launch_bounds__(128, 3)
attn_kernel(const float* __restrict__ qkv, uint4* __restrict__ Opacked)
{
    extern __shared__ uint4 asm4[];
    uint4* sK = asm4;                    // [2][512]
    uint4* sV = asm4 + 1024;             // [2][512]
    float* sBias = (float*)(asm4 + 2048);  // [2][64]

    const uint32_t sKaddr = smem_u32(sK);
    const uint32_t sVaddr = smem_u32(sV);
    const uint32_t sBaddr = smem_u32(sBias);

    const int qt = blockIdx.x;
    const int h  = blockIdx.y;
    const int b  = blockIdx.z;
    const int tid  = threadIdx.x;
    const int warp = tid >> 5;
    const int lane = tid & 31;
    const int g = lane >> 2, t = lane & 3;

    const size_t kvBase = ((size_t)(b * Hh + h)) * 32 * 512;

    // Q fragments: 4 fp16 A-quads (k16 steps)
    uint4 qf[4];
    {
        const float* q0 = qkv + (size_t)(b * Ts + qt * 64 + warp * 16 + g) * QKV_N + h * HD;
        const float* q1 = q0 + (size_t)8 * QKV_N;
#pragma unroll
        for (int ks = 0; ks < 4; ++ks) {
            const int col = 16 * ks + 2 * t;
            const float2 a0 = *(const float2*)(q0 + col);
            const float2 a1 = *(const float2*)(q1 + col);
            const float2 a2 = *(const float2*)(q0 + col + 8);
            const float2 a3 = *(const float2*)(q1 + col + 8);
            qf[ks].x = packf16(a0.x, a0.y);
            qf[ks].y = packf16(a1.x, a1.y);
            qf[ks].z = packf16(a2.x, a2.y);
            qf[ks].w = packf16(a3.x, a3.y);
        }
    }

    float o[8][4];
#pragma unroll
    for (int i = 0; i < 8; ++i)
#pragma unroll
        for (int j = 0; j < 4; ++j) o[i][j] = 0.f;
    float l0 = 0.f, l1 = 0.f;

    auto issue = [&](int buf, int kt) {
        const uint4* srcK = g_Kq + kvBase + (size_t)kt * 512 + tid;
        const uint4* srcV = g_Vq + kvBase + (size_t)kt * 512 + tid;
        const uint32_t dK = sKaddr + buf * 8192 + tid * 16;
        const uint32_t dV = sVaddr + buf * 8192 + tid * 16;
#pragma unroll
        for (int i = 0; i < 4; ++i) {
            cp_async16(dK + i * 2048, srcK + i * 128);
            cp_async16(dV + i * 2048, srcV + i * 128);
        }
        if (tid < 16) cp_async16(sBaddr + buf * 256 + tid * 16, g_bias + b * Ts + kt * 64 + tid * 4);
    };

    issue(0, 0);
    CP_COMMIT();

    for (int kt = 0; kt < Ts / 64; ++kt) {
        const int buf = kt & 1;
        if (kt + 1 < Ts / 64) {
            issue(buf ^ 1, kt + 1);
            CP_COMMIT();
            CP_WAIT(1);
        } else {
            CP_WAIT(0);
        }
        __syncthreads();

        const uint4* bK = sK + buf * 512;
        const uint4* bV = sV + buf * 512;
        const float* bB = sBias + buf * 64;

        // ---- S = Q K^T (single fp16, 32 MMAs) ----
        float sacc[8][4];
#pragma unroll
        for (int nt = 0; nt < 8; ++nt)
#pragma unroll
            for (int j = 0; j < 4; ++j) sacc[nt][j] = 0.f;
#pragma unroll
        for (int ksp = 0; ksp < 2; ++ksp) {
#pragma unroll
            for (int nt = 0; nt < 8; ++nt) {
                const uint4 f = bK[(nt * 2 + ksp) * 32 + lane];
                mma_f16q(sacc[nt], qf[2 * ksp], f.x, f.y);
                mma_f16q(sacc[nt], qf[2 * ksp + 1], f.z, f.w);
            }
        }

        // ---- softmax weights (no max): P = exp2(S*C1 + log2bias) ----
        float rs0 = 0.f, rs1 = 0.f;
        uint32_t ph[8][2];
#pragma unroll
        for (int nt = 0; nt < 8; ++nt) {
            const float b0 = bB[8 * nt + 2 * t];
            const float b1 = bB[8 * nt + 2 * t + 1];
            const float p0 = ex2f(fmaf(sacc[nt][0], C1, b0));
            const float p1 = ex2f(fmaf(sacc[nt][1], C1, b1));
            const float p2 = ex2f(fmaf(sacc[nt][2], C1, b0));
            const float p3 = ex2f(fmaf(sacc[nt][3], C1, b1));
            rs0 += p0 + p1;
            rs1 += p2 + p3;
            ph[nt][0] = packf16(p0, p1);
            ph[nt][1] = packf16(p2, p3);
        }
        l0 += rs0;
        l1 += rs1;

        // ---- O += P V (single fp16, 32 MMAs) ----
#pragma unroll
        for (int kp = 0; kp < 4; ++kp) {
            const uint32_t a[4] = { ph[2 * kp][0], ph[2 * kp][1],
                                    ph[2 * kp + 1][0], ph[2 * kp + 1][1] };
#pragma unroll
            for (int nd2 = 0; nd2 < 4; ++nd2) {
                const uint4 f = bV[(kp * 4 + nd2) * 32 + lane];
                mma_f16(o[2 * nd2], a, f.x, f.y);
                mma_f16(o[2 * nd2 + 1], a, f.z, f.w);
            }
        }
        __syncthreads();
    }

    // row sums across 4 t-lanes
    l0 += __shfl_xor_sync(0xffffffffu, l0, 1);
    l0 += __shfl_xor_sync(0xffffffffu, l0, 2);
    l1 += __shfl_xor_sync(0xffffffffu, l1, 1);
    l1 += __shfl_xor_sync(0xffffffffu, l1, 2);
    const float inv0 = 1.0f / l0;
    const float inv1 = 1.0f / l1;

    // fused epilogue: normalize + write fp16 A-pack quads
    const int R = (b * Ts + qt * 64 + warp * 16) >> 4;
#pragma unroll
    for (int sd = 0; sd < 4; ++sd) {
        uint4 w;
        w.x = packf16(o[2 * sd][0] * inv0,     o[2 * sd][1] * inv0);
        w.y = packf16(o[2 * sd][2] * inv1,     o[2 * sd][3] * inv1);
        w.z = packf16(o[2 * sd + 1][0] * inv0, o[2 * sd + 1][1] * inv0);
        w.w = packf16(o[2 * sd + 1][2] * inv1, o[2 * sd + 1][3] * inv1);
        Opacked[((size_t)R * 64 + h * 4 + sd) * 32 + lane] = w;
    }
}

// ===========================================================================
extern "C" void kernel_launch(void* const* d_in, const int* in_sizes, int n_in,
                              void* d_out, int out_size)
{
    const float* x     = (const float*)d_in[0];
    const float* eng   = (const float*)d_in[1];
    const void*  mask  = (const void*)d_in[2];
    const float* qkv_w = (const float*)d_in[3];
    const float* qkv_b = (const float*)d_in[4];
    const float* out_w = (const float*)d_in[5];
    const float* out_b = (const float*)d_in[6];
    float* out = (float*)d_out;

    float* qkv = nullptr;
    uint4 *xp = nullptr, *op = nullptr, *wq = nullptr, *wo = nullptr;
    cudaGetSymbolAddress((void**)&qkv, g_qkv);
    cudaGetSymbolAddress((void**)&xp,  g_xp);
    cudaGetSymbolAddress((void**)&op,  g_op);
    cudaGetSymbolAddress((void**)&wq,  g_wq);
    cudaGetSymbolAddress((void**)&wo,  g_wo);

    cudaFuncSetAttribute(f16_gemm_packed,
                         cudaFuncAttributeMaxDynamicSharedMemorySize, GP_SMEM_BYTES);
    cudaFuncSetAttribute(attn_kernel,
                         cudaFuncAttributeMaxDynamicSharedMemorySize, ATTN_SMEM_BYTES);

    // 0) mask dtype detection + per-key bias precompute (log2 domain)
    detect_mask_kernel<<<1, 256>>>((const unsigned char*)mask);
    bias_kernel<<<(Bb * Ts + 255) / 256, 256>>>(eng, mask);

    // 0b) pack x and weights into fp16 fragment layouts
    pack_a_f16<<<2048, 256>>>(x, xp, M_ROWS, Dd);
    pack_b_f16<<<1536, 256>>>(qkv_w, wq, QKV_N, Dd);
    pack_b_f16<<<512, 256>>>(out_w, wo, Dd, Dd);

    // 1) QKV projection (packed fp16 mma.sync)
    dim3 g1(QKV_N / 128, M_ROWS / 128);
    f16_gemm_packed<<<g1, 256, GP_SMEM_BYTES>>>(xp, wq, qkv_b, qkv, Dd, QKV_N);

    // 1b) repack K + V to fp16 fragment quads
    dim3 gc(32, Hh, Bb);
    convert_kv_kernel<<<gc, 256>>>(qkv);

    // 2) attention (all-fp16 MMA) -> writes fp16 A-pack directly
    dim3 g2(Ts / 64, Hh, Bb);
    attn_kernel<<<g2, 128, ATTN_SMEM_BYTES>>>(qkv, op);

    // 3) output projection (packed fp16 mma.sync)
    dim3 g3(Dd / 128, M_ROWS / 128);
    f16_gemm_packed<<<g3, 256, GP_SMEM_BYTES>>>(op, wo, out_b, out, Dd, Dd);
}

// round 11
// speedup vs baseline: 10.9036x; 1.1303x over previous
#include <cuda_runtime.h>
#include <cuda_bf16.h>
#include <cuda_fp16.h>
#include <math.h>
#include <stdint.h>

// Problem constants
#define Bb 4
#define Ts 2048
#define Dd 1024
#define Hh 16
#define HD 64
#define M_ROWS 8192
#define QKV_N 3072

// Scratch (device globals: allocation-free)
__device__ float g_bias[Bb * Ts];                 // per-key log2-domain bias
__device__ int   g_maskMode;
// Fragment-ready fp16 buffers
__device__ uint4 g_qp[(size_t)(M_ROWS / 16) * 64 * 32];   // Q A-pack
__device__ uint4 g_Kq[(size_t)Bb * Hh * 32 * 512];        // K B-pack tiles
__device__ uint4 g_Vq[(size_t)Bb * Hh * 32 * 512];        // V frag tiles
__device__ uint4 g_xp[(size_t)(M_ROWS / 16) * 64 * 32];   // x A-pack
__device__ uint4 g_op[(size_t)(M_ROWS / 16) * 64 * 32];   // attn-out A-pack
__device__ uint4 g_wq[(size_t)(QKV_N / 8) * 32 * 32];     // qkv_w B-pack
__device__ uint4 g_wo[(size_t)(Dd / 8) * 32 * 32];        // out_w B-pack

// ===========================================================================
// helpers
// ===========================================================================
__device__ __forceinline__ uint32_t packf16(float lo, float hi) {
    uint32_t r;
    asm("cvt.rn.f16x2.f32 %0, %1, %2;" : "=r"(r) : "f"(hi), "f"(lo));
    return r;
}
__device__ __forceinline__ float ex2f(float x) {
    float r;
    asm("ex2.approx.ftz.f32 %0, %1;" : "=f"(r) : "f"(x));
    return r;
}

__device__ __forceinline__ void mma_f16(float* c, const uint32_t* a, uint32_t b0, uint32_t b1) {
    asm volatile(
        "mma.sync.aligned.m16n8k16.row.col.f32.f16.f16.f32 "
        "{%0,%1,%2,%3}, {%4,%5,%6,%7}, {%8,%9}, {%0,%1,%2,%3};\n"
        : "+f"(c[0]), "+f"(c[1]), "+f"(c[2]), "+f"(c[3])
        : "r"(a[0]), "r"(a[1]), "r"(a[2]), "r"(a[3]), "r"(b0), "r"(b1));
}
__device__ __forceinline__ void mma_f16q(float* c, const uint4& a, uint32_t b0, uint32_t b1) {
    asm volatile(
        "mma.sync.aligned.m16n8k16.row.col.f32.f16.f16.f32 "
        "{%0,%1,%2,%3}, {%4,%5,%6,%7}, {%8,%9}, {%0,%1,%2,%3};\n"
        : "+f"(c[0]), "+f"(c[1]), "+f"(c[2]), "+f"(c[3])
        : "r"(a.x), "r"(a.y), "r"(a.z), "r"(a.w), "r"(b0), "r"(b1));
}

__device__ __forceinline__ uint32_t smem_u32(const void* p) {
    uint32_t a;
    asm("{ .reg .u64 t; cvta.to.shared.u64 t, %1; cvt.u32.u64 %0, t; }" : "=r"(a) : "l"(p));
    return a;
}
__device__ __forceinline__ void cp_async16(uint32_t dst, const void* src) {
    asm volatile("cp.async.cg.shared.global [%0], [%1], 16;" :: "r"(dst), "l"(src));
}
#define CP_COMMIT() asm volatile("cp.async.commit_group;" ::: "memory")
#define CP_WAIT(n)  asm volatile("cp.async.wait_group %0;" :: "n"(n) : "memory")

// ===========================================================================
// Mask dtype detection + bias precompute (log2 domain)
// ===========================================================================
__global__ void detect_mask_kernel(const unsigned char* __restrict__ mask)
{
    __shared__ unsigned int orr[4][256];
    const int tid = threadIdx.x;
    unsigned int o0 = 0, o1 = 0, o2 = 0, o3 = 0;
    for (int i = tid * 4; i < Bb * Ts; i += 256 * 4) {
        o0 |= mask[i + 0]; o1 |= mask[i + 1]; o2 |= mask[i + 2]; o3 |= mask[i + 3];
    }
    orr[0][tid] = o0; orr[1][tid] = o1; orr[2][tid] = o2; orr[3][tid] = o3;
    __syncthreads();
    for (int s = 128; s; s >>= 1) {
        if (tid < s) {
            orr[0][tid] |= orr[0][tid + s];
            orr[1][tid] |= orr[1][tid + s];
            orr[2][tid] |= orr[2][tid + s];
            orr[3][tid] |= orr[3][tid + s];
        }
        __syncthreads();
    }
    if (tid == 0) {
        unsigned int l0 = orr[0][0], l1 = orr[1][0], l2 = orr[2][0], l3 = orr[3][0];
        int mode;
        if ((l1 | l2 | l3) == 0u) mode = 1;
        else if ((l0 | l1) == 0u && (l2 | l3) != 0u) mode = 2;
        else mode = 0;
        g_maskMode = mode;
    }
}

__global__ void bias_kernel(const float* __restrict__ eng, const void* __restrict__ mask)
{
    const int kk = blockIdx.x * 256 + threadIdx.x;
    if (kk >= Bb * Ts) return;
    const int mode = g_maskMode;
    bool m;
    if (mode == 1)      m = ((const int*)mask)[kk] != 0;
    else if (mode == 2) m = ((const float*)mask)[kk] != 0.f;
    else                m = ((const unsigned char*)mask)[kk] != 0;
    g_bias[kk] = m ? -1e9f : log2f(fmaxf(eng[kk], 1e-6f));
}

// ===========================================================================
// fp16 fragment packing (A- and B-layouts)
// ===========================================================================
__global__ void __launch_bounds__(256)
pack_a_f16(const float* __restrict__ src, uint4* __restrict__ dst, int M, int K)
{
    const int K16 = K >> 4;
    const int total = (M >> 4) * K16 * 32;
    for (int q = blockIdx.x * 256 + threadIdx.x; q < total; q += gridDim.x * 256) {
        const int lane = q & 31;
        const int rs = q >> 5;
        const int S = rs % K16;
        const int R = rs / K16;
        const int g = lane >> 2, t = lane & 3;
        const float* p = src + (size_t)(R * 16 + g) * K + S * 16 + 2 * t;
        const float* p2 = p + (size_t)8 * K;
        const float2 a0 = *(const float2*)(p);
        const float2 a1 = *(const float2*)(p2);
        const float2 a2 = *(const float2*)(p + 8);
        const float2 a3 = *(const float2*)(p2 + 8);
        uint4 w;
        w.x = packf16(a0.x, a0.y);
        w.y = packf16(a1.x, a1.y);
        w.z = packf16(a2.x, a2.y);
        w.w = packf16(a3.x, a3.y);
        dst[q] = w;
    }
}

__global__ void __launch_bounds__(256)
pack_b_f16(const float* __restrict__ src, uint4* __restrict__ dst, int N, int K)
{
    const int K32 = K >> 5;
    const int total = (N >> 3) * K32 * 32;
    for (int q = blockIdx.x * 256 + threadIdx.x; q < total; q += gridDim.x * 256) {
        const int lane = q & 31;
        const int cs = q >> 5;
        const int S = cs % K32;
        const int C = cs / K32;
        const int g = lane >> 2, t = lane & 3;
        const float* p = src + (size_t)(C * 8 + g) * K + S * 32 + 2 * t;
        const float2 b0 = *(const float2*)(p);
        const float2 b1 = *(const float2*)(p + 8);
        const float2 b2 = *(const float2*)(p + 16);
        const float2 b3 = *(const float2*)(p + 24);
        uint4 w;
        w.x = packf16(b0.x, b0.y);
        w.y = packf16(b1.x, b1.y);
        w.z = packf16(b2.x, b2.y);
        w.w = packf16(b3.x, b3.y);
        dst[q] = w;
    }
}

// ===========================================================================
// Shared GEMM mainloop macro bits: 128x128 tile, BK=32, 4-stage cp.async.
// ===========================================================================
#define GP_SMEM_BYTES 65536   // 4 stages x (8KB A + 8KB B)

// generic fp16 GEMM -> fp32 C + bias (used for out-projection)
__global__ void __launch_bounds__(256)
f16_gemm_packed(const uint4* __restrict__ Ap, const uint4* __restrict__ Bp,
                const float* __restrict__ bias, float* __restrict__ C,
                int K, int ldc)
{
    extern __shared__ uint4 ps[];
    uint4* sA = ps;            // [4][512]
    uint4* sB = ps + 2048;     // [4][512]
    const uint32_t sAaddr = smem_u32(sA);
    const uint32_t sBaddr = smem_u32(sB);

    const int tid  = threadIdx.x;
    const int wid  = tid >> 5;
    const int lane = tid & 31;
    const int g = lane >> 2, t = lane & 3;
    const int wm = wid & 3;
    const int wn = wid >> 2;
    const int bm = blockIdx.y * 128;
    const int bn = blockIdx.x * 128;
    const int K16 = K >> 4;
    const int K32 = K >> 5;
    const int Rb = bm >> 4;
    const int Cb = bn >> 3;

    float acc[2][8][4];
#pragma unroll
    for (int mi = 0; mi < 2; ++mi)
#pragma unroll
        for (int ni = 0; ni < 8; ++ni)
#pragma unroll
            for (int r = 0; r < 4; ++r) acc[mi][ni][r] = 0.f;

    auto issue = [&](int buf, int kt) {
#pragma unroll
        for (int i = 0; i < 2; ++i) {
            const int l    = tid + 256 * i;
            const int tile = l >> 5;
            const int ln   = l & 31;
            cp_async16(sAaddr + buf * 8192 + l * 16,
                       Ap + ((size_t)(Rb + (tile >> 1)) * K16 + 2 * kt + (tile & 1)) * 32 + ln);
            cp_async16(sBaddr + buf * 8192 + l * 16,
                       Bp + ((size_t)(Cb + tile) * K32 + kt) * 32 + ln);
        }
    };

    const int nChunks = K >> 5;
#pragma unroll
    for (int p = 0; p < 3; ++p) {
        if (p < nChunks) { issue(p, p); CP_COMMIT(); }
    }

    for (int kt = 0; kt < nChunks; ++kt) {
        if (kt + 3 < nChunks) {
            issue((kt + 3) & 3, kt + 3);
            CP_COMMIT();
            CP_WAIT(3);
        } else if (kt + 2 < nChunks) { CP_WAIT(2); }
        else if (kt + 1 < nChunks)   { CP_WAIT(1); }
        else                         { CP_WAIT(0); }
        __syncthreads();

        const uint4* bufA = sA + (kt & 3) * 512;
        const uint4* bufB = sB + (kt & 3) * 512;
        uint4 fa[2][2];
#pragma unroll
        for (int mi = 0; mi < 2; ++mi)
#pragma unroll
            for (int kc = 0; kc < 2; ++kc)
                fa[mi][kc] = bufA[(((wm * 2 + mi) << 1) | kc) * 32 + lane];
#pragma unroll
        for (int ni = 0; ni < 8; ++ni) {
            const uint4 f = bufB[(wn * 8 + ni) * 32 + lane];
            mma_f16q(acc[0][ni], fa[0][0], f.x, f.y);
            mma_f16q(acc[1][ni], fa[1][0], f.x, f.y);
            mma_f16q(acc[0][ni], fa[0][1], f.z, f.w);
            mma_f16q(acc[1][ni], fa[1][1], f.z, f.w);
        }
        __syncthreads();
    }

#pragma unroll
    for (int mi = 0; mi < 2; ++mi) {
        const int row = bm + wm * 32 + mi * 16 + g;
#pragma unroll
        for (int ni = 0; ni < 8; ++ni) {
            const int col = bn + wn * 64 + ni * 8 + 2 * t;
            const float b0 = bias[col];
            const float b1 = bias[col + 1];
            float2 lo, hi;
            lo.x = acc[mi][ni][0] + b0; lo.y = acc[mi][ni][1] + b1;
            hi.x = acc[mi][ni][2] + b0; hi.y = acc[mi][ni][3] + b1;
            *(float2*)(C + (size_t)row * ldc + col) = lo;
            *(float2*)(C + (size_t)(row + 8) * ldc + col) = hi;
        }
    }
}

// ===========================================================================
// Fused QKV GEMM: same mainloop; epilogue writes Q A-pack, K B-pack, and
// V fragment quads (via conflict-free smem transpose) directly.
// grid.x = 24 col-blocks: 0-7 Q, 8-15 K, 16-23 V.
// ===========================================================================
__global__ void __launch_bounds__(256)
qkv_gemm_fused(const uint4* __restrict__ Ap, const uint4* __restrict__ Bp,
               const float* __restrict__ bias,
               uint4* __restrict__ Qp, uint4* __restrict__ Kq, uint4* __restrict__ Vq)
{
    extern __shared__ uint4 ps[];
    uint4* sA = ps;
    uint4* sB = ps + 2048;
    const uint32_t sAaddr = smem_u32(sA);
    const uint32_t sBaddr = smem_u32(sB);

    const int tid  = threadIdx.x;
    const int wid  = tid >> 5;
    const int lane = tid & 31;
    const int g = lane >> 2, t = lane & 3;
    const int wm = wid & 3;
    const int wn = wid >> 2;
    const int bm = blockIdx.y * 128;
    const int bn = blockIdx.x * 128;
    const int K16 = Dd >> 4;   // 64
    const int K32 = Dd >> 5;   // 32
    const int Rb = bm >> 4;
    const int Cb = bn >> 3;

    float acc[2][8][4];
#pragma unroll
    for (int mi = 0; mi < 2; ++mi)
#pragma unroll
        for (int ni = 0; ni < 8; ++ni)
#pragma unroll
            for (int r = 0; r < 4; ++r) acc[mi][ni][r] = 0.f;

    auto issue = [&](int buf, int kt) {
#pragma unroll
        for (int i = 0; i < 2; ++i) {
            const int l    = tid + 256 * i;
            const int tile = l >> 5;
            const int ln   = l & 31;
            cp_async16(sAaddr + buf * 8192 + l * 16,
                       Ap + ((size_t)(Rb + (tile >> 1)) * K16 + 2 * kt + (tile & 1)) * 32 + ln);
            cp_async16(sBaddr + buf * 8192 + l * 16,
                       Bp + ((size_t)(Cb + tile) * K32 + kt) * 32 + ln);
        }
    };

    const int nChunks = Dd >> 5;  // 32
#pragma unroll
    for (int p = 0; p < 3; ++p) { issue(p, p); CP_COMMIT(); }

    for (int kt = 0; kt < nChunks; ++kt) {
        if (kt + 3 < nChunks) {
            issue((kt + 3) & 3, kt + 3);
            CP_COMMIT();
            CP_WAIT(3);
        } else if (kt + 2 < nChunks) { CP_WAIT(2); }
        else if (kt + 1 < nChunks)   { CP_WAIT(1); }
        else                         { CP_WAIT(0); }
        __syncthreads();

        const uint4* bufA = sA + (kt & 3) * 512;
        const uint4* bufB = sB + (kt & 3) * 512;
        uint4 fa[2][2];
#pragma unroll
        for (int mi = 0; mi < 2; ++mi)
#pragma unroll
            for (int kc = 0; kc < 2; ++kc)
                fa[mi][kc] = bufA[(((wm * 2 + mi) << 1) | kc) * 32 + lane];
#pragma unroll
        for (int ni = 0; ni < 8; ++ni) {
            const uint4 f = bufB[(wn * 8 + ni) * 32 + lane];
            mma_f16q(acc[0][ni], fa[0][0], f.x, f.y);
            mma_f16q(acc[1][ni], fa[1][0], f.x, f.y);
            mma_f16q(acc[0][ni], fa[0][1], f.z, f.w);
            mma_f16q(acc[1][ni], fa[1][1], f.z, f.w);
        }
        __syncthreads();
    }

    const int region = blockIdx.x >> 3;

    if (region == 0) {
        // ---- Q: emit A-pack quads directly ----
#pragma unroll
        for (int mi = 0; mi < 2; ++mi) {
            const int R = Rb + wm * 2 + mi;
#pragma unroll
            for (int s = 0; s < 4; ++s) {
                const int colb = bn + wn * 64 + s * 16;
                const float b0 = bias[colb + 2 * t];
                const float b1 = bias[colb + 2 * t + 1];
                const float b2 = bias[colb + 8 + 2 * t];
                const float b3 = bias[colb + 8 + 2 * t + 1];
                uint4 w;
                w.x = packf16(acc[mi][2 * s][0] + b0,     acc[mi][2 * s][1] + b1);
                w.y = packf16(acc[mi][2 * s][2] + b0,     acc[mi][2 * s][3] + b1);
                w.z = packf16(acc[mi][2 * s + 1][0] + b2, acc[mi][2 * s + 1][1] + b3);
                w.w = packf16(acc[mi][2 * s + 1][2] + b2, acc[mi][2 * s + 1][3] + b3);
                const int Scol = blockIdx.x * 8 + wn * 4 + s;
                Qp[((size_t)R * 64 + Scol) * 32 + lane] = w;
            }
        }
    } else if (region == 1) {
        // ---- K: emit B-pack quads directly ----
        const int h = (blockIdx.x - 8) * 2 + wn;
#pragma unroll
        for (int mi = 0; mi < 2; ++mi) {
            const int rowbase = bm + wm * 32 + mi * 16;
            const int bb  = rowbase >> 11;
            const int tok = rowbase & 2047;
            const int kt  = tok >> 6;
            const int nt0 = (tok >> 3) & 7;
            const size_t base = ((size_t)(bb * Hh + h) * 32 + kt) * 512;
#pragma unroll
            for (int ksp = 0; ksp < 2; ++ksp) {
                const int colb = bn + wn * 64 + 32 * ksp;
                float bb0[4], bb1[4];
#pragma unroll
                for (int j = 0; j < 4; ++j) {
                    bb0[j] = bias[colb + 8 * j + 2 * t];
                    bb1[j] = bias[colb + 8 * j + 2 * t + 1];
                }
                uint4 w0, w1;
                w0.x = packf16(acc[mi][4 * ksp + 0][0] + bb0[0], acc[mi][4 * ksp + 0][1] + bb1[0]);
                w0.y = packf16(acc[mi][4 * ksp + 1][0] + bb0[1], acc[mi][4 * ksp + 1][1] + bb1[1]);
                w0.z = packf16(acc[mi][4 * ksp + 2][0] + bb0[2], acc[mi][4 * ksp + 2][1] + bb1[2]);
                w0.w = packf16(acc[mi][4 * ksp + 3][0] + bb0[3], acc[mi][4 * ksp + 3][1] + bb1[3]);
                w1.x = packf16(acc[mi][4 * ksp + 0][2] + bb0[0], acc[mi][4 * ksp + 0][3] + bb1[0]);
                w1.y = packf16(acc[mi][4 * ksp + 1][2] + bb0[1], acc[mi][4 * ksp + 1][3] + bb1[1]);
                w1.z = packf16(acc[mi][4 * ksp + 2][2] + bb0[2], acc[mi][4 * ksp + 2][3] + bb1[2]);
                w1.w = packf16(acc[mi][4 * ksp + 3][2] + bb0[3], acc[mi][4 * ksp + 3][3] + bb1[3]);
                Kq[base + ((size_t)(nt0 * 2 + ksp)) * 32 + lane] = w0;
                Kq[base + ((size_t)((nt0 + 1) * 2 + ksp)) * 32 + lane] = w1;
            }
        }
    } else {
        // ---- V: smem transpose (stride 136 halves, conflict-free), emit quads ----
        unsigned short* sT = (unsigned short*)ps;   // 128 x 136 halves = 34.8KB < 64KB
#pragma unroll
        for (int mi = 0; mi < 2; ++mi) {
            const int r0 = wm * 32 + mi * 16 + g;
#pragma unroll
            for (int ni = 0; ni < 8; ++ni) {
                const int c = wn * 64 + ni * 8 + 2 * t;
                const float b0 = bias[bn + c];
                const float b1 = bias[bn + c + 1];
                *(uint32_t*)&sT[r0 * 136 + c]       = packf16(acc[mi][ni][0] + b0, acc[mi][ni][1] + b1);
                *(uint32_t*)&sT[(r0 + 8) * 136 + c] = packf16(acc[mi][ni][2] + b0, acc[mi][ni][3] + b1);
            }
        }
        __syncthreads();

        const int bb   = bm >> 11;
        const int tokb = bm & 2047;
#pragma unroll
        for (int i = 0; i < 8; ++i) {
            const int q6   = i * 8 + (tid >> 5);
            const int head = q6 >> 5;
            const int kt2  = (q6 >> 4) & 1;
            const int kp   = (q6 >> 2) & 3;
            const int nd2  = q6 & 3;
            const int r0 = kt2 * 64 + kp * 16 + 2 * t;
            const int c0 = head * 64 + nd2 * 16 + g;
            uint4 w;
            w.x = (uint32_t)sT[r0 * 136 + c0]           | ((uint32_t)sT[(r0 + 1) * 136 + c0] << 16);
            w.y = (uint32_t)sT[(r0 + 8) * 136 + c0]     | ((uint32_t)sT[(r0 + 9) * 136 + c0] << 16);
            w.z = (uint32_t)sT[r0 * 136 + c0 + 8]       | ((uint32_t)sT[(r0 + 1) * 136 + c0 + 8] << 16);
            w.w = (uint32_t)sT[(r0 + 8) * 136 + c0 + 8] | ((uint32_t)sT[(r0 + 9) * 136 + c0 + 8] << 16);
            const int hg  = (blockIdx.x - 16) * 2 + head;
            const int ktg = (tokb >> 6) + kt2;
            Vq[((size_t)(bb * Hh + hg) * 32 + ktg) * 512 + (kp * 4 + nd2) * 32 + lane] = w;
        }
    }
}

// ===========================================================================
// Flash attention: all-fp16 MMA, no-max ex2 softmax, Q from A-pack,
// fused fp16 A-pack epilogue.
// ===========================================================================
#define ATTN_SMEM_BYTES (2 * 8192 + 2 * 8192 + 2 * 256)
#define C1 0.18033688011112042f   // 0.125 * log2(e)

__global__ void __launch_bounds__(128, 3)
attn_kernel(const uint4* __restrict__ Qp, uint4* __restrict__ Opacked)
{
    extern __shared__ uint4 asm4[];
    uint4* sK = asm4;                    // [2][512]
    uint4* sV = asm4 + 1024;             // [2][512]
    float* sBias = (float*)(asm4 + 2048);  // [2][64]

    const uint32_t sKaddr = smem_u32(sK);
    const uint32_t sVaddr = smem_u32(sV);
    const uint32_t sBaddr = smem_u32(sBias);

    const int qt = blockIdx.x;
    const int h  = blockIdx.y;
    const int b  = blockIdx.z;
    const int tid  = threadIdx.x;
    const int warp = tid >> 5;
    const int lane = tid & 31;
    const int t = lane & 3;

    const size_t kvBase = ((size_t)(b * Hh + h)) * 32 * 512;
    const int R = (b * Ts + qt * 64 + warp * 16) >> 4;

    // Q fragments straight from the A-pack
    uint4 qf[4];
#pragma unroll
    for (int ks = 0; ks < 4; ++ks)
        qf[ks] = Qp[((size_t)R * 64 + h * 4 + ks) * 32 + lane];

    float o[8][4];
#pragma unroll
    for (int i = 0; i < 8; ++i)
#pragma unroll
        for (int j = 0; j < 4; ++j) o[i][j] = 0.f;
    float l0 = 0.f, l1 = 0.f;

    auto issue = [&](int buf, int kt) {
        const uint4* srcK = g_Kq + kvBase + (size_t)kt * 512 + tid;
        const uint4* srcV = g_Vq + kvBase + (size_t)kt * 512 + tid;
        const uint32_t dK = sKaddr + buf * 8192 + tid * 16;
        const uint32_t dV = sVaddr + buf * 8192 + tid * 16;
#pragma unroll
        for (int i = 0; i < 4; ++i) {
            cp_async16(dK + i * 2048, srcK + i * 128);
            cp_async16(dV + i * 2048, srcV + i * 128);
        }
        if (tid < 16) cp_async16(sBaddr + buf * 256 + tid * 16, g_bias + b * Ts + kt * 64 + tid * 4);
    };

    issue(0, 0);
    CP_COMMIT();

    for (int kt = 0; kt < Ts / 64; ++kt) {
        const int buf = kt & 1;
        if (kt + 1 < Ts / 64) {
            issue(buf ^ 1, kt + 1);
            CP_COMMIT();
            CP_WAIT(1);
        } else {
            CP_WAIT(0);
        }
        __syncthreads();

        const uint4* bK = sK + buf * 512;
        const uint4* bV = sV + buf * 512;
        const float* bB = sBias + buf * 64;

        // ---- S = Q K^T (fp16) ----
        float sacc[8][4];
#pragma unroll
        for (int nt = 0; nt < 8; ++nt)
#pragma unroll
            for (int j = 0; j < 4; ++j) sacc[nt][j] = 0.f;
#pragma unroll
        for (int ksp = 0; ksp < 2; ++ksp) {
#pragma unroll
            for (int nt = 0; nt < 8; ++nt) {
                const uint4 f = bK[(nt * 2 + ksp) * 32 + lane];
                mma_f16q(sacc[nt], qf[2 * ksp], f.x, f.y);
                mma_f16q(sacc[nt], qf[2 * ksp + 1], f.z, f.w);
            }
        }

        // ---- softmax weights (no max): P = exp2(S*C1 + log2bias) ----
        float rs0 = 0.f, rs1 = 0.f;
        uint32_t ph[8][2];
#pragma unroll
        for (int nt = 0; nt < 8; ++nt) {
            const float b0 = bB[8 * nt + 2 * t];
            const float b1 = bB[8 * nt + 2 * t + 1];
            const float p0 = ex2f(fmaf(sacc[nt][0], C1, b0));
            const float p1 = ex2f(fmaf(sacc[nt][1], C1, b1));
            const float p2 = ex2f(fmaf(sacc[nt][2], C1, b0));
            const float p3 = ex2f(fmaf(sacc[nt][3], C1, b1));
            rs0 += p0 + p1;
            rs1 += p2 + p3;
            ph[nt][0] = packf16(p0, p1);
            ph[nt][1] = packf16(p2, p3);
        }
        l0 += rs0;
        l1 += rs1;

        // ---- O += P V (fp16) ----
#pragma unroll
        for (int kp = 0; kp < 4; ++kp) {
            const uint32_t a[4] = { ph[2 * kp][0], ph[2 * kp][1],
                                    ph[2 * kp + 1][0], ph[2 * kp + 1][1] };
#pragma unroll
            for (int nd2 = 0; nd2 < 4; ++nd2) {
                const uint4 f = bV[(kp * 4 + nd2) * 32 + lane];
                mma_f16(o[2 * nd2], a, f.x, f.y);
                mma_f16(o[2 * nd2 + 1], a, f.z, f.w);
            }
        }
        __syncthreads();
    }

    // row sums across 4 t-lanes
    l0 += __shfl_xor_sync(0xffffffffu, l0, 1);
    l0 += __shfl_xor_sync(0xffffffffu, l0, 2);
    l1 += __shfl_xor_sync(0xffffffffu, l1, 1);
    l1 += __shfl_xor_sync(0xffffffffu, l1, 2);
    const float inv0 = 1.0f / l0;
    const float inv1 = 1.0f / l1;

    // fused epilogue: normalize + write fp16 A-pack quads
#pragma unroll
    for (int sd = 0; sd < 4; ++sd) {
        uint4 w;
        w.x = packf16(o[2 * sd][0] * inv0,     o[2 * sd][1] * inv0);
        w.y = packf16(o[2 * sd][2] * inv1,     o[2 * sd][3] * inv1);
        w.z = packf16(o[2 * sd + 1][0] * inv0, o[2 * sd + 1][1] * inv0);
        w.w = packf16(o[2 * sd + 1][2] * inv1, o[2 * sd + 1][3] * inv1);
        Opacked[((size_t)R * 64 + h * 4 + sd) * 32 + lane] = w;
    }
}

// ===========================================================================
extern "C" void kernel_launch(void* const* d_in, const int* in_sizes, int n_in,
                              void* d_out, int out_size)
{
    const float* x     = (const float*)d_in[0];
    const float* eng   = (const float*)d_in[1];
    const void*  mask  = (const void*)d_in[2];
    const float* qkv_w = (const float*)d_in[3];
    const float* qkv_b = (const float*)d_in[4];
    const float* out_w = (const float*)d_in[5];
    const float* out_b = (const float*)d_in[6];
    float* out = (float*)d_out;

    uint4 *qp = nullptr, *kq = nullptr, *vq = nullptr;
    uint4 *xp = nullptr, *op = nullptr, *wq = nullptr, *wo = nullptr;
    cudaGetSymbolAddress((void**)&qp, g_qp);
    cudaGetSymbolAddress((void**)&kq, g_Kq);
    cudaGetSymbolAddress((void**)&vq, g_Vq);
    cudaGetSymbolAddress((void**)&xp, g_xp);
    cudaGetSymbolAddress((void**)&op, g_op);
    cudaGetSymbolAddress((void**)&wq, g_wq);
    cudaGetSymbolAddress((void**)&wo, g_wo);

    cudaFuncSetAttribute(f16_gemm_packed,
                         cudaFuncAttributeMaxDynamicSharedMemorySize, GP_SMEM_BYTES);
    cudaFuncSetAttribute(qkv_gemm_fused,
                         cudaFuncAttributeMaxDynamicSharedMemorySize, GP_SMEM_BYTES);
    cudaFuncSetAttribute(attn_kernel,
                         cudaFuncAttributeMaxDynamicSharedMemorySize, ATTN_SMEM_BYTES);

    // 0) mask dtype detection + per-key bias precompute (log2 domain)
    detect_mask_kernel<<<1, 256>>>((const unsigned char*)mask);
    bias_kernel<<<(Bb * Ts + 255) / 256, 256>>>(eng, mask);

    // 0b) pack x and weights into fp16 fragment layouts
    pack_a_f16<<<2048, 256>>>(x, xp, M_ROWS, Dd);
    pack_b_f16<<<1536, 256>>>(qkv_w, wq, QKV_N, Dd);
    pack_b_f16<<<512, 256>>>(out_w, wo, Dd, Dd);

    // 1) fused QKV projection -> Q A-pack, K B-pack, V frag tiles
    dim3 g1(QKV_N / 128, M_ROWS / 128);
    qkv_gemm_fused<<<g1, 256, GP_SMEM_BYTES>>>(xp, wq, qkv_b, qp, kq, vq);

    // 2) attention (all-fp16 MMA) -> writes fp16 A-pack directly
    dim3 g2(Ts / 64, Hh, Bb);
    attn_kernel<<<g2, 128, ATTN_SMEM_BYTES>>>(qp, op);

    // 3) output projection (packed fp16 mma.sync, 4-stage pipeline)
    dim3 g3(Dd / 128, M_ROWS / 128);
    f16_gemm_packed<<<g3, 256, GP_SMEM_BYTES>>>(op, wo, out_b, out, Dd, Dd);
}